// round 7
// baseline (speedup 1.0000x reference)
#include <cuda_runtime.h>
#include <cuda_bf16.h>
#include <math.h>
#include <stdint.h>

#define Bn   4
#define Sn   2048
#define HIDn 1024
#define NHn  16
#define Dn   64
#define BHn  64
#define Mn   8192

// ---------------- scratch (static device globals; no runtime alloc) --------
__device__ __nv_bfloat16 g_xh[(size_t)Mn * HIDn];
__device__ __nv_bfloat16 g_xl[(size_t)Mn * HIDn];
__device__ __nv_bfloat16 g_wh[(size_t)3 * HIDn * HIDn];
__device__ __nv_bfloat16 g_wl[(size_t)3 * HIDn * HIDn];
__device__ __nv_bfloat16 g_qh[(size_t)BHn * Sn * Dn];
__device__ __nv_bfloat16 g_ql[(size_t)BHn * Sn * Dn];
__device__ __nv_bfloat16 g_kh[(size_t)BHn * Sn * Dn];
__device__ __nv_bfloat16 g_kl[(size_t)BHn * Sn * Dn];
__device__ __nv_bfloat16 g_vh[(size_t)BHn * Sn * Dn];
__device__ __nv_bfloat16 g_vl[(size_t)BHn * Sn * Dn];
__device__ float g_m[(size_t)BHn * Sn];
__device__ float g_l[(size_t)BHn * Sn];

// ---------------- PTX helpers (baseline-feature PTX only) -------------------
__device__ __forceinline__ uint32_t smem_u32(const void* p) {
    uint32_t a;
    asm("{ .reg .u64 t; cvta.to.shared.u64 t, %1; cvt.u32.u64 %0, t; }" : "=r"(a) : "l"(p));
    return a;
}
#define CP_ASYNC(dst, src) \
    asm volatile("cp.async.cg.shared.global [%0], [%1], 16;" :: "r"(dst), "l"(src))
#define CP_COMMIT() asm volatile("cp.async.commit_group;")
#define CP_WAIT0()  asm volatile("cp.async.wait_group 0;")
#define CP_WAIT1()  asm volatile("cp.async.wait_group 1;")

__device__ __forceinline__ void ldsm4(uint32_t r[4], uint32_t addr) {
    asm volatile("ldmatrix.sync.aligned.m8n8.x4.shared.b16 {%0,%1,%2,%3}, [%4];"
        : "=r"(r[0]), "=r"(r[1]), "=r"(r[2]), "=r"(r[3]) : "r"(addr));
}
__device__ __forceinline__ void ldsm4_t(uint32_t r[4], uint32_t addr) {
    asm volatile("ldmatrix.sync.aligned.m8n8.x4.trans.shared.b16 {%0,%1,%2,%3}, [%4];"
        : "=r"(r[0]), "=r"(r[1]), "=r"(r[2]), "=r"(r[3]) : "r"(addr));
}
__device__ __forceinline__ void mma16816(float c[4], const uint32_t a[4],
                                         uint32_t b0, uint32_t b1) {
    asm volatile("mma.sync.aligned.m16n8k16.row.col.f32.bf16.bf16.f32 "
        "{%0,%1,%2,%3}, {%4,%5,%6,%7}, {%8,%9}, {%0,%1,%2,%3};"
        : "+f"(c[0]), "+f"(c[1]), "+f"(c[2]), "+f"(c[3])
        : "r"(a[0]), "r"(a[1]), "r"(a[2]), "r"(a[3]), "r"(b0), "r"(b1));
}

// ---------------- fp32 -> (bf16 hi, bf16 lo) split --------------------------
__device__ __forceinline__ void split1(float v, uint16_t& h, uint16_t& l) {
    __nv_bfloat16 hb = __float2bfloat16(v);
    float r = v - __bfloat162float(hb);
    h = __bfloat16_as_ushort(hb);
    l = __bfloat16_as_ushort(__float2bfloat16(r));
}

__global__ __launch_bounds__(256) void split_x_kernel(const float4* __restrict__ src) {
    size_t i = (size_t)blockIdx.x * 256 + threadIdx.x;
    float4 v = src[i];
    uint16_t h0,h1,h2,h3,l0,l1,l2,l3;
    split1(v.x,h0,l0); split1(v.y,h1,l1); split1(v.z,h2,l2); split1(v.w,h3,l3);
    uint2 uh, ul;
    uh.x = ((uint32_t)h1<<16)|h0; uh.y = ((uint32_t)h3<<16)|h2;
    ul.x = ((uint32_t)l1<<16)|l0; ul.y = ((uint32_t)l3<<16)|l2;
    ((uint2*)g_xh)[i] = uh; ((uint2*)g_xl)[i] = ul;
}

__global__ __launch_bounds__(256) void split_w_kernel(const float4* __restrict__ Wq,
                                                      const float4* __restrict__ Wk,
                                                      const float4* __restrict__ Wv) {
    const int which = blockIdx.y;
    const float4* W = (which == 0) ? Wq : ((which == 1) ? Wk : Wv);
    size_t i = (size_t)blockIdx.x * 256 + threadIdx.x;
    float4 v = W[i];
    uint16_t h0,h1,h2,h3,l0,l1,l2,l3;
    split1(v.x,h0,l0); split1(v.y,h1,l1); split1(v.z,h2,l2); split1(v.w,h3,l3);
    uint2 uh, ul;
    uh.x = ((uint32_t)h1<<16)|h0; uh.y = ((uint32_t)h3<<16)|h2;
    ul.x = ((uint32_t)l1<<16)|l0; ul.y = ((uint32_t)l3<<16)|l2;
    size_t o = (size_t)which * (HIDn * HIDn / 4) + i;
    ((uint2*)g_wh)[o] = uh; ((uint2*)g_wl)[o] = ul;
}

// Tile: 128 rows x 64 bf16 (128B data + 16B pad = 144B row stride).
#define ROWB 144
#define T1   (128 * ROWB)     // 18432 B per tile

// ---------------------------------------------------------------------------
// K1: QKV projection, y = x @ W^T + b.  CTA = 128x128 tile, K=1024 in 16
// chunks of 64.  3x bf16-split mma.sync, cp.async double-buffered.
// Q, K, V all written as bf16 hi/lo in [bh][s][d] layout.
// ---------------------------------------------------------------------------
#define K1_SMEM (8 * T1)      // 147456 B

__global__ __launch_bounds__(256) void qkv_mma(
    const float* __restrict__ bq, const float* __restrict__ bk, const float* __restrict__ bv)
{
    extern __shared__ char smem[];
    const uint32_t sb = smem_u32(smem);
    const int tid = threadIdx.x;
    const int lane = tid & 31;
    const int wid = tid >> 5;
    const int warp_m = wid & 1;
    const int warp_n = wid >> 1;
    const int which = blockIdx.z;
    const int m0 = blockIdx.x * 128;
    const int n0 = blockIdx.y * 128;
    const float* bias = (which == 0) ? bq : ((which == 1) ? bk : bv);
    const __nv_bfloat16* wh = g_wh + (size_t)which * HIDn * HIDn;
    const __nv_bfloat16* wl = g_wl + (size_t)which * HIDn * HIDn;

    float C[4][4][4];
#pragma unroll
    for (int a = 0; a < 4; a++)
#pragma unroll
        for (int n = 0; n < 4; n++)
#pragma unroll
            for (int j = 0; j < 4; j++) C[a][n][j] = 0.0f;

    auto load_chunk = [&](int chunk, int buf) {
        const int kc = chunk * 64;
        const uint32_t bufb = sb + buf * 4 * T1;
#pragma unroll
        for (int t = 0; t < 4; t++) {
            const __nv_bfloat16* src = (t == 0) ? g_xh : (t == 1) ? g_xl : (t == 2) ? wh : wl;
            const int rbase = (t < 2) ? m0 : n0;
#pragma unroll
            for (int i = 0; i < 4; i++) {
                const int idx = tid + 256 * i;
                const int row = idx >> 3, c = idx & 7;
                CP_ASYNC(bufb + t * T1 + row * ROWB + c * 16,
                         src + (size_t)(rbase + row) * HIDn + kc + c * 8);
            }
        }
        CP_COMMIT();
    };

    auto compute = [&](int buf) {
        const uint32_t base = sb + buf * 4 * T1;
#pragma unroll
        for (int ks = 0; ks < 4; ks++) {
            uint32_t ah[4][4], al[4][4];
#pragma unroll
            for (int a = 0; a < 4; a++) {
                const int row = warp_m * 64 + a * 16 + ((lane >> 3) & 1) * 8 + (lane & 7);
                const int colb = ks * 32 + (lane >> 4) * 16;
                ldsm4(ah[a], base + row * ROWB + colb);
                ldsm4(al[a], base + T1 + row * ROWB + colb);
            }
            uint32_t bh[2][4], bl[2][4];
#pragma unroll
            for (int p = 0; p < 2; p++) {
                const int row = warp_n * 32 + p * 16 + ((lane >> 4) & 1) * 8 + (lane & 7);
                const int colb = ks * 32 + ((lane >> 3) & 1) * 16;
                ldsm4(bh[p], base + 2 * T1 + row * ROWB + colb);
                ldsm4(bl[p], base + 3 * T1 + row * ROWB + colb);
            }
#pragma unroll
            for (int a = 0; a < 4; a++)
#pragma unroll
                for (int n = 0; n < 4; n++) {
                    const int p = n >> 1, q = (n & 1) * 2;
                    mma16816(C[a][n], ah[a], bh[p][q], bh[p][q + 1]);
                    mma16816(C[a][n], ah[a], bl[p][q], bl[p][q + 1]);
                    mma16816(C[a][n], al[a], bh[p][q], bh[p][q + 1]);
                }
        }
    };

    load_chunk(0, 0);
    load_chunk(1, 1);
    for (int kt = 0; kt < 16; kt++) {
        if (kt == 15) { CP_WAIT0(); } else { CP_WAIT1(); }
        __syncthreads();
        compute(kt & 1);
        __syncthreads();
        if (kt + 2 < 16) load_chunk(kt + 2, kt & 1);
    }

    // epilogue: bias + split + scatter to [bh][s][d] (hi/lo for all of q,k,v)
    __nv_bfloat16* oh = (which == 0) ? g_qh : ((which == 1) ? g_kh : g_vh);
    __nv_bfloat16* ol = (which == 0) ? g_ql : ((which == 1) ? g_kl : g_vl);
#pragma unroll
    for (int a = 0; a < 4; a++)
#pragma unroll
        for (int n = 0; n < 4; n++) {
            const int row0 = m0 + warp_m * 64 + a * 16 + (lane >> 2);
            const int col  = n0 + warp_n * 32 + n * 8 + (lane & 3) * 2;
            const float bb0 = bias[col], bb1 = bias[col + 1];
            const int hd = col >> 6, d = col & 63;
#pragma unroll
            for (int h = 0; h < 2; h++) {
                const int row = row0 + h * 8;
                const float v0 = C[a][n][h * 2 + 0] + bb0;
                const float v1 = C[a][n][h * 2 + 1] + bb1;
                const int bidx = row >> 11, s = row & (Sn - 1);
                const size_t oi = ((size_t)(bidx * NHn + hd) * Sn + s) * Dn + d;
                uint16_t h0, h1, l0, l1;
                split1(v0, h0, l0); split1(v1, h1, l1);
                *(uint32_t*)&oh[oi] = ((uint32_t)h1 << 16) | h0;
                *(uint32_t*)&ol[oi] = ((uint32_t)l1 << 16) | l0;
            }
        }
}

// ---------------------------------------------------------------------------
// K2: scores = QK^T/8 + mask -> raw into probs, online per-row (m,l).
// ---------------------------------------------------------------------------
#define K2_MASKOFF (6 * T1)
#define K2_REDM    (K2_MASKOFF + Sn * 4)
#define K2_REDL    (K2_REDM + 4 * 128 * 4)
#define K2_SMEM    (K2_REDL + 4 * 128 * 4)

__global__ __launch_bounds__(256) void scores_mma(
    const float* __restrict__ mask, float* __restrict__ probs)
{
    extern __shared__ char smem[];
    const uint32_t sb = smem_u32(smem);
    float* maskS = (float*)(smem + K2_MASKOFF);
    float* redM  = (float*)(smem + K2_REDM);
    float* redL  = (float*)(smem + K2_REDL);
    const int tid = threadIdx.x;
    const int lane = tid & 31;
    const int wid = tid >> 5;
    const int warp_m = wid & 1;
    const int warp_n = wid >> 1;
    const int qt = blockIdx.x;
    const int bh = blockIdx.y;
    const int bidx = bh >> 4;
    const int grow = qt * 128;

    const size_t qgb = ((size_t)bh * Sn + grow) * Dn;
#pragma unroll
    for (int i = 0; i < 4; i++) {
        const int idx = tid + 256 * i;
        const int row = idx >> 3, c = idx & 7;
        CP_ASYNC(sb + row * ROWB + c * 16,      g_qh + qgb + row * Dn + c * 8);
        CP_ASYNC(sb + T1 + row * ROWB + c * 16, g_ql + qgb + row * Dn + c * 8);
    }
#pragma unroll
    for (int i = 0; i < 2; i++)
        ((float4*)maskS)[tid + 256 * i] = ((const float4*)(mask + (size_t)bidx * Sn))[tid + 256 * i];

    auto load_k = [&](int kt, int buf) {
        const size_t kgb = ((size_t)bh * Sn + kt * 128) * Dn;
        const uint32_t bufb = sb + (2 + buf * 2) * T1;
#pragma unroll
        for (int i = 0; i < 4; i++) {
            const int idx = tid + 256 * i;
            const int row = idx >> 3, c = idx & 7;
            CP_ASYNC(bufb + row * ROWB + c * 16,      g_kh + kgb + row * Dn + c * 8);
            CP_ASYNC(bufb + T1 + row * ROWB + c * 16, g_kl + kgb + row * Dn + c * 8);
        }
        CP_COMMIT();
    };

    load_k(0, 0);
    load_k(1, 1);

    float sm_[8], sl_[8];
#pragma unroll
    for (int i = 0; i < 8; i++) { sm_[i] = -1e30f; sl_[i] = 0.0f; }

    for (int kt = 0; kt < 16; kt++) {
        if (kt == 15) { CP_WAIT0(); } else { CP_WAIT1(); }
        __syncthreads();

        const uint32_t kbase = sb + (2 + (kt & 1) * 2) * T1;
        float C[4][4][4];
#pragma unroll
        for (int a = 0; a < 4; a++)
#pragma unroll
            for (int n = 0; n < 4; n++)
#pragma unroll
                for (int j = 0; j < 4; j++) C[a][n][j] = 0.0f;

#pragma unroll
        for (int ks = 0; ks < 4; ks++) {
            uint32_t ah[4][4], al[4][4];
#pragma unroll
            for (int a = 0; a < 4; a++) {
                const int row = warp_m * 64 + a * 16 + ((lane >> 3) & 1) * 8 + (lane & 7);
                const int colb = ks * 32 + (lane >> 4) * 16;
                ldsm4(ah[a], sb + row * ROWB + colb);
                ldsm4(al[a], sb + T1 + row * ROWB + colb);
            }
            uint32_t bhf[2][4], blf[2][4];
#pragma unroll
            for (int p = 0; p < 2; p++) {
                const int row = warp_n * 32 + p * 16 + ((lane >> 4) & 1) * 8 + (lane & 7);
                const int colb = ks * 32 + ((lane >> 3) & 1) * 16;
                ldsm4(bhf[p], kbase + row * ROWB + colb);
                ldsm4(blf[p], kbase + T1 + row * ROWB + colb);
            }
#pragma unroll
            for (int a = 0; a < 4; a++)
#pragma unroll
                for (int n = 0; n < 4; n++) {
                    const int p = n >> 1, q = (n & 1) * 2;
                    mma16816(C[a][n], ah[a], bhf[p][q], bhf[p][q + 1]);
                    mma16816(C[a][n], ah[a], blf[p][q], blf[p][q + 1]);
                    mma16816(C[a][n], al[a], bhf[p][q], bhf[p][q + 1]);
                }
        }

#pragma unroll
        for (int a = 0; a < 4; a++) {
            float s[4][4];
#pragma unroll
            for (int n = 0; n < 4; n++) {
                const int colt = warp_n * 32 + n * 8 + (lane & 3) * 2;
                const float mk0 = maskS[kt * 128 + colt];
                const float mk1 = maskS[kt * 128 + colt + 1];
                s[n][0] = C[a][n][0] * 0.125f + mk0;
                s[n][1] = C[a][n][1] * 0.125f + mk1;
                s[n][2] = C[a][n][2] * 0.125f + mk0;
                s[n][3] = C[a][n][3] * 0.125f + mk1;
                const int rt0 = warp_m * 64 + a * 16 + (lane >> 2);
                const size_t r0 = ((size_t)bh * Sn + grow + rt0) * Sn + kt * 128 + colt;
                const size_t r1 = ((size_t)bh * Sn + grow + rt0 + 8) * Sn + kt * 128 + colt;
                *(float2*)&probs[r0] = make_float2(s[n][0], s[n][1]);
                *(float2*)&probs[r1] = make_float2(s[n][2], s[n][3]);
            }
#pragma unroll
            for (int hh = 0; hh < 2; hh++) {
                float cm = s[0][hh * 2];
#pragma unroll
                for (int n = 0; n < 4; n++) {
                    cm = fmaxf(cm, s[n][hh * 2]);
                    cm = fmaxf(cm, s[n][hh * 2 + 1]);
                }
                const int si = a * 2 + hh;
                const float mn = fmaxf(sm_[si], cm);
                float ps = 0.0f;
#pragma unroll
                for (int n = 0; n < 4; n++)
                    ps += __expf(s[n][hh * 2] - mn) + __expf(s[n][hh * 2 + 1] - mn);
                sl_[si] = sl_[si] * __expf(sm_[si] - mn) + ps;
                sm_[si] = mn;
            }
        }

        __syncthreads();
        if (kt + 2 < 16) load_k(kt + 2, kt & 1);
    }

#pragma unroll
    for (int i = 0; i < 8; i++) {
        float m = sm_[i], l = sl_[i];
#pragma unroll
        for (int off = 1; off <= 2; off <<= 1) {
            const float om = __shfl_xor_sync(0xffffffffu, m, off);
            const float ol = __shfl_xor_sync(0xffffffffu, l, off);
            const float mn = fmaxf(m, om);
            l = l * __expf(m - mn) + ol * __expf(om - mn);
            m = mn;
        }
        if ((lane & 3) == 0) {
            const int row = warp_m * 64 + (i >> 1) * 16 + (i & 1) * 8 + (lane >> 2);
            redM[warp_n * 128 + row] = m;
            redL[warp_n * 128 + row] = l;
        }
    }
    __syncthreads();
    if (tid < 128) {
        float m = redM[tid], l = redL[tid];
#pragma unroll
        for (int w = 1; w < 4; w++) {
            const float om = redM[w * 128 + tid];
            const float ol = redL[w * 128 + tid];
            const float mn = fmaxf(m, om);
            l = l * __expf(m - mn) + ol * __expf(om - mn);
            m = mn;
        }
        g_m[(size_t)bh * Sn + grow + tid] = m;
        g_l[(size_t)bh * Sn + grow + tid] = l;
    }
}

// ---------------------------------------------------------------------------
// K3: read raw scores, p = exp(s-m)/l -> final probs (written back), and
// ctx = P @ V on mma.sync (3x bf16 split, V via ldmatrix.trans).
// CTA = 128 q-rows, full d=64; loop k in tiles of 128. 8 warps x 16 rows.
// ---------------------------------------------------------------------------
#define PROWB 272                          // 128 bf16 + 8 pad
#define PT    (128 * PROWB)                // 34816
#define K3_VOFF (2 * PT)                   // 69632
#define K3_VT   T1                         // 18432 (128 rows x 144B)
#define K3_MS   (K3_VOFF + 4 * K3_VT)      // 143360
#define K3_LV   (K3_MS + 512)              // 143872
#define K3_SMEM (K3_LV + 512)              // 144384

__global__ __launch_bounds__(256) void ctx_mma(
    float* __restrict__ probs, float* __restrict__ ctx)
{
    extern __shared__ char smem[];
    const uint32_t sb = smem_u32(smem);
    float* ms = (float*)(smem + K3_MS);
    float* lv = (float*)(smem + K3_LV);
    const int tid = threadIdx.x;
    const int lane = tid & 31;
    const int wid = tid >> 5;
    const int qt = blockIdx.x;
    const int bh = blockIdx.y;
    const int bidx = bh >> 4;
    const int h    = bh & 15;
    const int q0 = qt * 128;

    if (tid < 128) {
        const size_t ro = (size_t)bh * Sn + q0 + tid;
        ms[tid] = g_m[ro];
        lv[tid] = 1.0f / g_l[ro];
    }

    auto load_v = [&](int kt, int buf) {
        const size_t vgb = ((size_t)bh * Sn + kt * 128) * Dn;
        const uint32_t vbase = sb + K3_VOFF + buf * 2 * K3_VT;
#pragma unroll
        for (int i = 0; i < 8; i++) {
            const int idx = tid + 256 * i;            // 0..2047
            const int mat = idx >> 10;                // 0=hi 1=lo
            const int rem = idx & 1023;
            const int row = rem >> 3, c = rem & 7;
            const __nv_bfloat16* src = mat ? g_vl : g_vh;
            CP_ASYNC(vbase + mat * K3_VT + row * ROWB + c * 16,
                     src + vgb + (size_t)row * Dn + c * 8);
        }
        CP_COMMIT();
    };

    load_v(0, 0);
    load_v(1, 1);
    __syncthreads();   // ms/lv visible

    float C[8][4];
#pragma unroll
    for (int n = 0; n < 8; n++)
#pragma unroll
        for (int j = 0; j < 4; j++) C[n][j] = 0.0f;

    for (int kt = 0; kt < 16; kt++) {
        // ---- P stage: normalize raw scores -> final probs + split into smem
#pragma unroll
        for (int i = 0; i < 16; i++) {
            const int idx = tid + 256 * i;            // 0..4095 float4
            const int row = idx >> 5;
            const int c4 = (idx & 31) * 4;
            const size_t gi = ((size_t)bh * Sn + q0 + row) * Sn + kt * 128 + c4;
            float4 s4 = *(const float4*)&probs[gi];
            const float mm = ms[row], ll = lv[row];
            s4.x = __expf(s4.x - mm) * ll;
            s4.y = __expf(s4.y - mm) * ll;
            s4.z = __expf(s4.z - mm) * ll;
            s4.w = __expf(s4.w - mm) * ll;
            *(float4*)&probs[gi] = s4;
            uint16_t h0,h1,h2,h3,l0,l1,l2,l3;
            split1(s4.x,h0,l0); split1(s4.y,h1,l1); split1(s4.z,h2,l2); split1(s4.w,h3,l3);
            uint2 uh, ul;
            uh.x = ((uint32_t)h1<<16)|h0; uh.y = ((uint32_t)h3<<16)|h2;
            ul.x = ((uint32_t)l1<<16)|l0; ul.y = ((uint32_t)l3<<16)|l2;
            *(uint2*)(smem + row * PROWB + c4 * 2)      = uh;
            *(uint2*)(smem + PT + row * PROWB + c4 * 2) = ul;
        }
        if (kt == 15) { CP_WAIT0(); } else { CP_WAIT1(); }
        __syncthreads();

        // ---- PV mma: warp wid owns rows 16*wid..16*wid+15
        const uint32_t vb = sb + K3_VOFF + (kt & 1) * 2 * K3_VT;
        const int r0 = wid * 16;
#pragma unroll
        for (int ks = 0; ks < 8; ks++) {
            uint32_t ph4[4], pl4[4];
            const uint32_t pa = sb + (r0 + (lane & 15)) * PROWB + ks * 32 + (lane >> 4) * 16;
            ldsm4(ph4, pa);
            ldsm4(pl4, pa + PT);
            const uint32_t brow = ks * 16 + (lane & 7) + ((lane >> 3) & 1) * 8;
#pragma unroll
            for (int nb = 0; nb < 4; nb++) {
                uint32_t vh4[4], vl4[4];
                const uint32_t ba = vb + brow * ROWB + nb * 32 + (lane >> 4) * 16;
                ldsm4_t(vh4, ba);
                ldsm4_t(vl4, ba + K3_VT);
                mma16816(C[nb*2],   ph4, vh4[0], vh4[1]);
                mma16816(C[nb*2],   ph4, vl4[0], vl4[1]);
                mma16816(C[nb*2],   pl4, vh4[0], vh4[1]);
                mma16816(C[nb*2+1], ph4, vh4[2], vh4[3]);
                mma16816(C[nb*2+1], ph4, vl4[2], vl4[3]);
                mma16816(C[nb*2+1], pl4, vh4[2], vh4[3]);
            }
        }
        __syncthreads();
        if (kt + 2 < 16) load_v(kt + 2, kt & 1);
    }

    // epilogue: ctx[b][s][h*64+d]
#pragma unroll
    for (int nb = 0; nb < 8; nb++) {
        const int col = nb * 8 + (lane & 3) * 2;
        const int row = q0 + wid * 16 + (lane >> 2);
        *(float2*)&ctx[((size_t)(bidx * Sn + row)) * HIDn + h * 64 + col] =
            make_float2(C[nb][0], C[nb][1]);
        *(float2*)&ctx[((size_t)(bidx * Sn + row + 8)) * HIDn + h * 64 + col] =
            make_float2(C[nb][2], C[nb][3]);
    }
}

// ---------------------------------------------------------------------------
extern "C" void kernel_launch(void* const* d_in, const int* in_sizes, int n_in,
                              void* d_out, int out_size)
{
    const float* x    = (const float*)d_in[0];
    const float* mask = (const float*)d_in[1];
    const float* Wq   = (const float*)d_in[2];
    const float* bq   = (const float*)d_in[3];
    const float* Wk   = (const float*)d_in[4];
    const float* bk   = (const float*)d_in[5];
    const float* Wv   = (const float*)d_in[6];
    const float* bv   = (const float*)d_in[7];

    float* ctx = (float*)d_out;
    const size_t PROBS_ELEMS = (size_t)BHn * Sn * Sn;
    size_t probs_off = 0;
    if ((size_t)out_size > PROBS_ELEMS) probs_off = (size_t)out_size - PROBS_ELEMS;
    float* probs = (float*)d_out + probs_off;

    cudaFuncSetAttribute(qkv_mma,    cudaFuncAttributeMaxDynamicSharedMemorySize, K1_SMEM);
    cudaFuncSetAttribute(scores_mma, cudaFuncAttributeMaxDynamicSharedMemorySize, K2_SMEM);
    cudaFuncSetAttribute(ctx_mma,    cudaFuncAttributeMaxDynamicSharedMemorySize, K3_SMEM);

    split_x_kernel<<<Mn * HIDn / 4 / 256, 256>>>((const float4*)x);
    split_w_kernel<<<dim3(HIDn * HIDn / 4 / 256, 3), 256>>>(
        (const float4*)Wq, (const float4*)Wk, (const float4*)Wv);
    qkv_mma<<<dim3(Mn/128, HIDn/128, 3), 256, K1_SMEM>>>(bq, bk, bv);
    scores_mma<<<dim3(Sn/128, BHn), 256, K2_SMEM>>>(mask, probs);
    ctx_mma<<<dim3(Sn/128, BHn), 256, K3_SMEM>>>(probs, ctx);
}

// round 8
// speedup vs baseline: 1.4779x; 1.4779x over previous
#include <cuda_runtime.h>
#include <cuda_bf16.h>
#include <math.h>
#include <stdint.h>

#define Bn   4
#define Sn   2048
#define HIDn 1024
#define NHn  16
#define Dn   64
#define BHn  64
#define Mn   8192

// ---------------- scratch (static device globals; no runtime alloc) --------
__device__ __nv_bfloat16 g_xh[(size_t)Mn * HIDn];
__device__ __nv_bfloat16 g_xl[(size_t)Mn * HIDn];
__device__ __nv_bfloat16 g_wh[(size_t)3 * HIDn * HIDn];
__device__ __nv_bfloat16 g_wl[(size_t)3 * HIDn * HIDn];
__device__ __nv_bfloat16 g_qh[(size_t)BHn * Sn * Dn];
__device__ __nv_bfloat16 g_ql[(size_t)BHn * Sn * Dn];
__device__ __nv_bfloat16 g_kh[(size_t)BHn * Sn * Dn];
__device__ __nv_bfloat16 g_kl[(size_t)BHn * Sn * Dn];
__device__ __nv_bfloat16 g_vh[(size_t)BHn * Sn * Dn];
__device__ __nv_bfloat16 g_vl[(size_t)BHn * Sn * Dn];
__device__ float g_m[(size_t)BHn * Sn];
__device__ float g_l[(size_t)BHn * Sn];

// ---------------- PTX helpers (baseline-feature PTX only) -------------------
__device__ __forceinline__ uint32_t smem_u32(const void* p) {
    uint32_t a;
    asm("{ .reg .u64 t; cvta.to.shared.u64 t, %1; cvt.u32.u64 %0, t; }" : "=r"(a) : "l"(p));
    return a;
}
#define CP_ASYNC(dst, src) \
    asm volatile("cp.async.cg.shared.global [%0], [%1], 16;" :: "r"(dst), "l"(src))
#define CP_COMMIT() asm volatile("cp.async.commit_group;")
#define CP_WAIT0()  asm volatile("cp.async.wait_group 0;")
#define CP_WAIT1()  asm volatile("cp.async.wait_group 1;")

__device__ __forceinline__ void ldsm4(uint32_t r[4], uint32_t addr) {
    asm volatile("ldmatrix.sync.aligned.m8n8.x4.shared.b16 {%0,%1,%2,%3}, [%4];"
        : "=r"(r[0]), "=r"(r[1]), "=r"(r[2]), "=r"(r[3]) : "r"(addr));
}
__device__ __forceinline__ void ldsm4_t(uint32_t r[4], uint32_t addr) {
    asm volatile("ldmatrix.sync.aligned.m8n8.x4.trans.shared.b16 {%0,%1,%2,%3}, [%4];"
        : "=r"(r[0]), "=r"(r[1]), "=r"(r[2]), "=r"(r[3]) : "r"(addr));
}
__device__ __forceinline__ void mma16816(float c[4], const uint32_t a[4],
                                         uint32_t b0, uint32_t b1) {
    asm volatile("mma.sync.aligned.m16n8k16.row.col.f32.bf16.bf16.f32 "
        "{%0,%1,%2,%3}, {%4,%5,%6,%7}, {%8,%9}, {%0,%1,%2,%3};"
        : "+f"(c[0]), "+f"(c[1]), "+f"(c[2]), "+f"(c[3])
        : "r"(a[0]), "r"(a[1]), "r"(a[2]), "r"(a[3]), "r"(b0), "r"(b1));
}

// ---------------- fp32 -> (bf16 hi, bf16 lo) split --------------------------
__device__ __forceinline__ void split1(float v, uint16_t& h, uint16_t& l) {
    __nv_bfloat16 hb = __float2bfloat16(v);
    float r = v - __bfloat162float(hb);
    h = __bfloat16_as_ushort(hb);
    l = __bfloat16_as_ushort(__float2bfloat16(r));
}
// pack two fp32 into one bf16x2 reg (lo = first element), plus residual reg
__device__ __forceinline__ void split_pack(float v0, float v1, uint32_t& ph, uint32_t& pl) {
    uint16_t h0, h1, l0, l1;
    split1(v0, h0, l0); split1(v1, h1, l1);
    ph = ((uint32_t)h1 << 16) | h0;
    pl = ((uint32_t)l1 << 16) | l0;
}

__global__ __launch_bounds__(256) void split_x_kernel(const float4* __restrict__ src) {
    size_t i = (size_t)blockIdx.x * 256 + threadIdx.x;
    float4 v = src[i];
    uint32_t h01, l01, h23, l23;
    split_pack(v.x, v.y, h01, l01);
    split_pack(v.z, v.w, h23, l23);
    ((uint2*)g_xh)[i] = make_uint2(h01, h23);
    ((uint2*)g_xl)[i] = make_uint2(l01, l23);
}

__global__ __launch_bounds__(256) void split_w_kernel(const float4* __restrict__ Wq,
                                                      const float4* __restrict__ Wk,
                                                      const float4* __restrict__ Wv) {
    const int which = blockIdx.y;
    const float4* W = (which == 0) ? Wq : ((which == 1) ? Wk : Wv);
    size_t i = (size_t)blockIdx.x * 256 + threadIdx.x;
    float4 v = W[i];
    uint32_t h01, l01, h23, l23;
    split_pack(v.x, v.y, h01, l01);
    split_pack(v.z, v.w, h23, l23);
    size_t o = (size_t)which * (HIDn * HIDn / 4) + i;
    ((uint2*)g_wh)[o] = make_uint2(h01, h23);
    ((uint2*)g_wl)[o] = make_uint2(l01, l23);
}

// Tile: 128 rows x 64 bf16 (128B data + 16B pad = 144B row stride).
#define ROWB 144
#define T1   (128 * ROWB)     // 18432 B per tile

// ---------------------------------------------------------------------------
// K1: QKV projection, y = x @ W^T + b.  CTA = 128x128 tile, K=1024 in 16
// chunks of 64.  3x bf16-split mma.sync, cp.async double-buffered.
// Q, K, V all written as bf16 hi/lo in [bh][s][d] layout.
// ---------------------------------------------------------------------------
#define K1_SMEM (8 * T1)      // 147456 B

__global__ __launch_bounds__(256) void qkv_mma(
    const float* __restrict__ bq, const float* __restrict__ bk, const float* __restrict__ bv)
{
    extern __shared__ char smem[];
    const uint32_t sb = smem_u32(smem);
    const int tid = threadIdx.x;
    const int lane = tid & 31;
    const int wid = tid >> 5;
    const int warp_m = wid & 1;
    const int warp_n = wid >> 1;
    const int which = blockIdx.z;
    const int m0 = blockIdx.x * 128;
    const int n0 = blockIdx.y * 128;
    const float* bias = (which == 0) ? bq : ((which == 1) ? bk : bv);
    const __nv_bfloat16* wh = g_wh + (size_t)which * HIDn * HIDn;
    const __nv_bfloat16* wl = g_wl + (size_t)which * HIDn * HIDn;

    float C[4][4][4];
#pragma unroll
    for (int a = 0; a < 4; a++)
#pragma unroll
        for (int n = 0; n < 4; n++)
#pragma unroll
            for (int j = 0; j < 4; j++) C[a][n][j] = 0.0f;

    auto load_chunk = [&](int chunk, int buf) {
        const int kc = chunk * 64;
        const uint32_t bufb = sb + buf * 4 * T1;
#pragma unroll
        for (int t = 0; t < 4; t++) {
            const __nv_bfloat16* src = (t == 0) ? g_xh : (t == 1) ? g_xl : (t == 2) ? wh : wl;
            const int rbase = (t < 2) ? m0 : n0;
#pragma unroll
            for (int i = 0; i < 4; i++) {
                const int idx = tid + 256 * i;
                const int row = idx >> 3, c = idx & 7;
                CP_ASYNC(bufb + t * T1 + row * ROWB + c * 16,
                         src + (size_t)(rbase + row) * HIDn + kc + c * 8);
            }
        }
        CP_COMMIT();
    };

    auto compute = [&](int buf) {
        const uint32_t base = sb + buf * 4 * T1;
#pragma unroll
        for (int ks = 0; ks < 4; ks++) {
            uint32_t ah[4][4], al[4][4];
#pragma unroll
            for (int a = 0; a < 4; a++) {
                const int row = warp_m * 64 + a * 16 + ((lane >> 3) & 1) * 8 + (lane & 7);
                const int colb = ks * 32 + (lane >> 4) * 16;
                ldsm4(ah[a], base + row * ROWB + colb);
                ldsm4(al[a], base + T1 + row * ROWB + colb);
            }
            uint32_t bh[2][4], bl[2][4];
#pragma unroll
            for (int p = 0; p < 2; p++) {
                const int row = warp_n * 32 + p * 16 + ((lane >> 4) & 1) * 8 + (lane & 7);
                const int colb = ks * 32 + ((lane >> 3) & 1) * 16;
                ldsm4(bh[p], base + 2 * T1 + row * ROWB + colb);
                ldsm4(bl[p], base + 3 * T1 + row * ROWB + colb);
            }
#pragma unroll
            for (int a = 0; a < 4; a++)
#pragma unroll
                for (int n = 0; n < 4; n++) {
                    const int p = n >> 1, q = (n & 1) * 2;
                    mma16816(C[a][n], ah[a], bh[p][q], bh[p][q + 1]);
                    mma16816(C[a][n], ah[a], bl[p][q], bl[p][q + 1]);
                    mma16816(C[a][n], al[a], bh[p][q], bh[p][q + 1]);
                }
        }
    };

    load_chunk(0, 0);
    load_chunk(1, 1);
    for (int kt = 0; kt < 16; kt++) {
        if (kt == 15) { CP_WAIT0(); } else { CP_WAIT1(); }
        __syncthreads();
        compute(kt & 1);
        __syncthreads();
        if (kt + 2 < 16) load_chunk(kt + 2, kt & 1);
    }

    // epilogue: bias + split + scatter to [bh][s][d] (hi/lo for q,k,v)
    __nv_bfloat16* oh = (which == 0) ? g_qh : ((which == 1) ? g_kh : g_vh);
    __nv_bfloat16* ol = (which == 0) ? g_ql : ((which == 1) ? g_kl : g_vl);
#pragma unroll
    for (int a = 0; a < 4; a++)
#pragma unroll
        for (int n = 0; n < 4; n++) {
            const int row0 = m0 + warp_m * 64 + a * 16 + (lane >> 2);
            const int col  = n0 + warp_n * 32 + n * 8 + (lane & 3) * 2;
            const float bb0 = bias[col], bb1 = bias[col + 1];
            const int hd = col >> 6, d = col & 63;
#pragma unroll
            for (int h = 0; h < 2; h++) {
                const int row = row0 + h * 8;
                const float v0 = C[a][n][h * 2 + 0] + bb0;
                const float v1 = C[a][n][h * 2 + 1] + bb1;
                const int bidx = row >> 11, s = row & (Sn - 1);
                const size_t oi = ((size_t)(bidx * NHn + hd) * Sn + s) * Dn + d;
                uint32_t ph, pl;
                split_pack(v0, v1, ph, pl);
                *(uint32_t*)&oh[oi] = ph;
                *(uint32_t*)&ol[oi] = pl;
            }
        }
}

// ---------------------------------------------------------------------------
// K2a: softmax stats only.  scores = QK^T/8 + mask; track per-row (m, l).
// Identical structure to the validated scores kernel, probs stores deleted.
// ---------------------------------------------------------------------------
#define K2_MASKOFF (6 * T1)
#define K2_REDM    (K2_MASKOFF + Sn * 4)
#define K2_REDL    (K2_REDM + 4 * 128 * 4)
#define K2_SMEM    (K2_REDL + 4 * 128 * 4)

__global__ __launch_bounds__(256) void stats_mma(const float* __restrict__ mask)
{
    extern __shared__ char smem[];
    const uint32_t sb = smem_u32(smem);
    float* maskS = (float*)(smem + K2_MASKOFF);
    float* redM  = (float*)(smem + K2_REDM);
    float* redL  = (float*)(smem + K2_REDL);
    const int tid = threadIdx.x;
    const int lane = tid & 31;
    const int wid = tid >> 5;
    const int warp_m = wid & 1;
    const int warp_n = wid >> 1;
    const int qt = blockIdx.x;
    const int bh = blockIdx.y;
    const int bidx = bh >> 4;
    const int grow = qt * 128;

    const size_t qgb = ((size_t)bh * Sn + grow) * Dn;
#pragma unroll
    for (int i = 0; i < 4; i++) {
        const int idx = tid + 256 * i;
        const int row = idx >> 3, c = idx & 7;
        CP_ASYNC(sb + row * ROWB + c * 16,      g_qh + qgb + row * Dn + c * 8);
        CP_ASYNC(sb + T1 + row * ROWB + c * 16, g_ql + qgb + row * Dn + c * 8);
    }
#pragma unroll
    for (int i = 0; i < 2; i++)
        ((float4*)maskS)[tid + 256 * i] = ((const float4*)(mask + (size_t)bidx * Sn))[tid + 256 * i];

    auto load_k = [&](int kt, int buf) {
        const size_t kgb = ((size_t)bh * Sn + kt * 128) * Dn;
        const uint32_t bufb = sb + (2 + buf * 2) * T1;
#pragma unroll
        for (int i = 0; i < 4; i++) {
            const int idx = tid + 256 * i;
            const int row = idx >> 3, c = idx & 7;
            CP_ASYNC(bufb + row * ROWB + c * 16,      g_kh + kgb + row * Dn + c * 8);
            CP_ASYNC(bufb + T1 + row * ROWB + c * 16, g_kl + kgb + row * Dn + c * 8);
        }
        CP_COMMIT();
    };

    load_k(0, 0);
    load_k(1, 1);

    float sm_[8], sl_[8];
#pragma unroll
    for (int i = 0; i < 8; i++) { sm_[i] = -1e30f; sl_[i] = 0.0f; }

    for (int kt = 0; kt < 16; kt++) {
        if (kt == 15) { CP_WAIT0(); } else { CP_WAIT1(); }
        __syncthreads();

        const uint32_t kbase = sb + (2 + (kt & 1) * 2) * T1;
        float C[4][4][4];
#pragma unroll
        for (int a = 0; a < 4; a++)
#pragma unroll
            for (int n = 0; n < 4; n++)
#pragma unroll
                for (int j = 0; j < 4; j++) C[a][n][j] = 0.0f;

#pragma unroll
        for (int ks = 0; ks < 4; ks++) {
            uint32_t ah[4][4], al[4][4];
#pragma unroll
            for (int a = 0; a < 4; a++) {
                const int row = warp_m * 64 + a * 16 + ((lane >> 3) & 1) * 8 + (lane & 7);
                const int colb = ks * 32 + (lane >> 4) * 16;
                ldsm4(ah[a], sb + row * ROWB + colb);
                ldsm4(al[a], sb + T1 + row * ROWB + colb);
            }
            uint32_t bhf[2][4], blf[2][4];
#pragma unroll
            for (int p = 0; p < 2; p++) {
                const int row = warp_n * 32 + p * 16 + ((lane >> 4) & 1) * 8 + (lane & 7);
                const int colb = ks * 32 + ((lane >> 3) & 1) * 16;
                ldsm4(bhf[p], kbase + row * ROWB + colb);
                ldsm4(blf[p], kbase + T1 + row * ROWB + colb);
            }
#pragma unroll
            for (int a = 0; a < 4; a++)
#pragma unroll
                for (int n = 0; n < 4; n++) {
                    const int p = n >> 1, q = (n & 1) * 2;
                    mma16816(C[a][n], ah[a], bhf[p][q], bhf[p][q + 1]);
                    mma16816(C[a][n], ah[a], blf[p][q], blf[p][q + 1]);
                    mma16816(C[a][n], al[a], bhf[p][q], bhf[p][q + 1]);
                }
        }

#pragma unroll
        for (int a = 0; a < 4; a++) {
            float s[4][4];
#pragma unroll
            for (int n = 0; n < 4; n++) {
                const int colt = warp_n * 32 + n * 8 + (lane & 3) * 2;
                const float mk0 = maskS[kt * 128 + colt];
                const float mk1 = maskS[kt * 128 + colt + 1];
                s[n][0] = C[a][n][0] * 0.125f + mk0;
                s[n][1] = C[a][n][1] * 0.125f + mk1;
                s[n][2] = C[a][n][2] * 0.125f + mk0;
                s[n][3] = C[a][n][3] * 0.125f + mk1;
            }
#pragma unroll
            for (int hh = 0; hh < 2; hh++) {
                float cm = s[0][hh * 2];
#pragma unroll
                for (int n = 0; n < 4; n++) {
                    cm = fmaxf(cm, s[n][hh * 2]);
                    cm = fmaxf(cm, s[n][hh * 2 + 1]);
                }
                const int si = a * 2 + hh;
                const float mn = fmaxf(sm_[si], cm);
                float ps = 0.0f;
#pragma unroll
                for (int n = 0; n < 4; n++)
                    ps += __expf(s[n][hh * 2] - mn) + __expf(s[n][hh * 2 + 1] - mn);
                sl_[si] = sl_[si] * __expf(sm_[si] - mn) + ps;
                sm_[si] = mn;
            }
        }

        __syncthreads();
        if (kt + 2 < 16) load_k(kt + 2, kt & 1);
    }

#pragma unroll
    for (int i = 0; i < 8; i++) {
        float m = sm_[i], l = sl_[i];
#pragma unroll
        for (int off = 1; off <= 2; off <<= 1) {
            const float om = __shfl_xor_sync(0xffffffffu, m, off);
            const float ol = __shfl_xor_sync(0xffffffffu, l, off);
            const float mn = fmaxf(m, om);
            l = l * __expf(m - mn) + ol * __expf(om - mn);
            m = mn;
        }
        if ((lane & 3) == 0) {
            const int row = warp_m * 64 + (i >> 1) * 16 + (i & 1) * 8 + (lane >> 2);
            redM[warp_n * 128 + row] = m;
            redL[warp_n * 128 + row] = l;
        }
    }
    __syncthreads();
    if (tid < 128) {
        float m = redM[tid], l = redL[tid];
#pragma unroll
        for (int w = 1; w < 4; w++) {
            const float om = redM[w * 128 + tid];
            const float ol = redL[w * 128 + tid];
            const float mn = fmaxf(m, om);
            l = l * __expf(m - mn) + ol * __expf(om - mn);
            m = mn;
        }
        g_m[(size_t)bh * Sn + grow + tid] = m;
        g_l[(size_t)bh * Sn + grow + tid] = l;
    }
}

// ---------------------------------------------------------------------------
// K2b: fused.  Recompute scores (8 warps x 16 q-rows, full 128 k-cols),
// p = exp(s-m)*invl, write FINAL probs (only probs traffic), and P@V via
// register-reused A-fragments (C frag of QK == A frag of PV, packed bf16x2
// hi/lo).  V via validated ldmatrix.trans path.
// smem: Qh|Ql | Kh0 Kl0 Kh1 Kl1 | Vh0 Vl0 Vh1 Vl1 | mask | m | invl
// ---------------------------------------------------------------------------
#define F_KOFF  (2 * T1)
#define F_VOFF  (6 * T1)
#define F_MASK  (10 * T1)                 // 184320
#define F_MROW  (F_MASK + Sn * 4)         // 192512
#define F_LROW  (F_MROW + 512)            // 193024
#define F_SMEM  (F_LROW + 512)            // 193536

__global__ __launch_bounds__(256) void fused_pv(
    const float* __restrict__ mask, float* __restrict__ probs, float* __restrict__ ctx)
{
    extern __shared__ char smem[];
    const uint32_t sb = smem_u32(smem);
    float* maskS = (float*)(smem + F_MASK);
    float* mrow  = (float*)(smem + F_MROW);
    float* lrow  = (float*)(smem + F_LROW);
    const int tid = threadIdx.x;
    const int lane = tid & 31;
    const int wid = tid >> 5;
    const int qt = blockIdx.x;
    const int bh = blockIdx.y;
    const int bidx = bh >> 4;
    const int h    = bh & 15;
    const int q0 = qt * 128;

    // Q (with group 0)
    const size_t qgb = ((size_t)bh * Sn + q0) * Dn;
#pragma unroll
    for (int i = 0; i < 4; i++) {
        const int idx = tid + 256 * i;
        const int row = idx >> 3, c = idx & 7;
        CP_ASYNC(sb + row * ROWB + c * 16,      g_qh + qgb + row * Dn + c * 8);
        CP_ASYNC(sb + T1 + row * ROWB + c * 16, g_ql + qgb + row * Dn + c * 8);
    }

    auto load_kv = [&](int kt, int buf) {
        const size_t gb = ((size_t)bh * Sn + kt * 128) * Dn;
        const uint32_t kb = sb + F_KOFF + buf * 2 * T1;
        const uint32_t vb = sb + F_VOFF + buf * 2 * T1;
#pragma unroll
        for (int i = 0; i < 4; i++) {
            const int idx = tid + 256 * i;
            const int row = idx >> 3, c = idx & 7;
            const size_t g = gb + (size_t)row * Dn + c * 8;
            CP_ASYNC(kb + row * ROWB + c * 16,      g_kh + g);
            CP_ASYNC(kb + T1 + row * ROWB + c * 16, g_kl + g);
            CP_ASYNC(vb + row * ROWB + c * 16,      g_vh + g);
            CP_ASYNC(vb + T1 + row * ROWB + c * 16, g_vl + g);
        }
        CP_COMMIT();
    };

    load_kv(0, 0);     // group 0 (includes Q)
    load_kv(1, 1);     // group 1

    // mask + stats (plain loads; visible after first __syncthreads)
#pragma unroll
    for (int i = 0; i < 2; i++)
        ((float4*)maskS)[tid + 256 * i] = ((const float4*)(mask + (size_t)bidx * Sn))[tid + 256 * i];
    if (tid < 128) {
        const size_t ro = (size_t)bh * Sn + q0 + tid;
        mrow[tid] = g_m[ro];
        lrow[tid] = 1.0f / g_l[ro];
    }

    float O[8][4];
#pragma unroll
    for (int n = 0; n < 8; n++)
#pragma unroll
        for (int j = 0; j < 4; j++) O[n][j] = 0.0f;

    const int rloc0 = wid * 16 + (lane >> 2);          // local q-row (first half)
    // per-lane stats for its two rows
    float mm0, ll0, mm1, ll1;

    for (int kt = 0; kt < 16; kt++) {
        if (kt == 15) { CP_WAIT0(); } else { CP_WAIT1(); }
        __syncthreads();
        if (kt == 0) { mm0 = mrow[rloc0]; ll0 = lrow[rloc0];
                       mm1 = mrow[rloc0 + 8]; ll1 = lrow[rloc0 + 8]; }

        const uint32_t kbase = sb + F_KOFF + (kt & 1) * 2 * T1;
        const uint32_t vbase = sb + F_VOFF + (kt & 1) * 2 * T1;

        // ---- QK^T: C[16 n-blocks][4]
        float C[16][4];
#pragma unroll
        for (int n = 0; n < 16; n++)
#pragma unroll
            for (int j = 0; j < 4; j++) C[n][j] = 0.0f;

#pragma unroll
        for (int ks = 0; ks < 4; ks++) {
            uint32_t qh4[4], ql4[4];
            {
                const int row = wid * 16 + ((lane >> 3) & 1) * 8 + (lane & 7);
                const int colb = ks * 32 + (lane >> 4) * 16;
                ldsm4(qh4, sb + row * ROWB + colb);
                ldsm4(ql4, sb + T1 + row * ROWB + colb);
            }
#pragma unroll
            for (int g = 0; g < 8; g++) {
                uint32_t kh4[4], kl4[4];
                const int row = g * 16 + ((lane >> 4) & 1) * 8 + (lane & 7);
                const int colb = ks * 32 + ((lane >> 3) & 1) * 16;
                ldsm4(kh4, kbase + row * ROWB + colb);
                ldsm4(kl4, kbase + T1 + row * ROWB + colb);
                mma16816(C[2*g],   qh4, kh4[0], kh4[1]);
                mma16816(C[2*g],   qh4, kl4[0], kl4[1]);
                mma16816(C[2*g],   ql4, kh4[0], kh4[1]);
                mma16816(C[2*g+1], qh4, kh4[2], kh4[3]);
                mma16816(C[2*g+1], qh4, kl4[2], kl4[3]);
                mma16816(C[2*g+1], ql4, kh4[2], kh4[3]);
            }
        }

        // ---- scale+mask+exp normalize, write final probs, keep p in C
        const size_t prow0 = ((size_t)bh * Sn + q0 + rloc0) * Sn + kt * 128;
        const size_t prow1 = prow0 + (size_t)8 * Sn;
#pragma unroll
        for (int n = 0; n < 16; n++) {
            const int colt = n * 8 + (lane & 3) * 2;
            const float mk0 = maskS[kt * 128 + colt];
            const float mk1 = maskS[kt * 128 + colt + 1];
            const float p00 = __expf(C[n][0] * 0.125f + mk0 - mm0) * ll0;
            const float p01 = __expf(C[n][1] * 0.125f + mk1 - mm0) * ll0;
            const float p10 = __expf(C[n][2] * 0.125f + mk0 - mm1) * ll1;
            const float p11 = __expf(C[n][3] * 0.125f + mk1 - mm1) * ll1;
            C[n][0] = p00; C[n][1] = p01; C[n][2] = p10; C[n][3] = p11;
            *(float2*)&probs[prow0 + colt] = make_float2(p00, p01);
            *(float2*)&probs[prow1 + colt] = make_float2(p10, p11);
        }

        // ---- P@V: A-frags from C registers (hi/lo split), V via ldsm trans
#pragma unroll
        for (int kg = 0; kg < 8; kg++) {
            uint32_t aph[4], apl[4];
            split_pack(C[2*kg][0],   C[2*kg][1],   aph[0], apl[0]);
            split_pack(C[2*kg][2],   C[2*kg][3],   aph[1], apl[1]);
            split_pack(C[2*kg+1][0], C[2*kg+1][1], aph[2], apl[2]);
            split_pack(C[2*kg+1][2], C[2*kg+1][3], aph[3], apl[3]);
            const uint32_t brow = kg * 16 + (lane & 7) + ((lane >> 3) & 1) * 8;
#pragma unroll
            for (int nb = 0; nb < 4; nb++) {
                uint32_t vh4[4], vl4[4];
                const uint32_t ba = vbase + brow * ROWB + nb * 32 + (lane >> 4) * 16;
                ldsm4_t(vh4, ba);
                ldsm4_t(vl4, ba + T1);
                mma16816(O[nb*2],   aph, vh4[0], vh4[1]);
                mma16816(O[nb*2],   aph, vl4[0], vl4[1]);
                mma16816(O[nb*2],   apl, vh4[0], vh4[1]);
                mma16816(O[nb*2+1], aph, vh4[2], vh4[3]);
                mma16816(O[nb*2+1], aph, vl4[2], vl4[3]);
                mma16816(O[nb*2+1], apl, vh4[2], vh4[3]);
            }
        }

        __syncthreads();
        if (kt + 2 < 16) load_kv(kt + 2, kt & 1);
    }

    // epilogue: ctx[b][s][h*64+d]
#pragma unroll
    for (int nb = 0; nb < 8; nb++) {
        const int col = nb * 8 + (lane & 3) * 2;
        const int row = q0 + wid * 16 + (lane >> 2);
        *(float2*)&ctx[((size_t)(bidx * Sn + row)) * HIDn + h * 64 + col] =
            make_float2(O[nb][0], O[nb][1]);
        *(float2*)&ctx[((size_t)(bidx * Sn + row + 8)) * HIDn + h * 64 + col] =
            make_float2(O[nb][2], O[nb][3]);
    }
}

// ---------------------------------------------------------------------------
extern "C" void kernel_launch(void* const* d_in, const int* in_sizes, int n_in,
                              void* d_out, int out_size)
{
    const float* x    = (const float*)d_in[0];
    const float* mask = (const float*)d_in[1];
    const float* Wq   = (const float*)d_in[2];
    const float* bq   = (const float*)d_in[3];
    const float* Wk   = (const float*)d_in[4];
    const float* bk   = (const float*)d_in[5];
    const float* Wv   = (const float*)d_in[6];
    const float* bv   = (const float*)d_in[7];

    float* ctx = (float*)d_out;
    const size_t PROBS_ELEMS = (size_t)BHn * Sn * Sn;
    size_t probs_off = 0;
    if ((size_t)out_size > PROBS_ELEMS) probs_off = (size_t)out_size - PROBS_ELEMS;
    float* probs = (float*)d_out + probs_off;

    cudaFuncSetAttribute(qkv_mma,   cudaFuncAttributeMaxDynamicSharedMemorySize, K1_SMEM);
    cudaFuncSetAttribute(stats_mma, cudaFuncAttributeMaxDynamicSharedMemorySize, K2_SMEM);
    cudaFuncSetAttribute(fused_pv,  cudaFuncAttributeMaxDynamicSharedMemorySize, F_SMEM);

    split_x_kernel<<<Mn * HIDn / 4 / 256, 256>>>((const float4*)x);
    split_w_kernel<<<dim3(HIDn * HIDn / 4 / 256, 3), 256>>>(
        (const float4*)Wq, (const float4*)Wk, (const float4*)Wv);
    qkv_mma<<<dim3(Mn/128, HIDn/128, 3), 256, K1_SMEM>>>(bq, bk, bv);
    stats_mma<<<dim3(Sn/128, BHn), 256, K2_SMEM>>>(mask);
    fused_pv<<<dim3(Sn/128, BHn), 256, F_SMEM>>>(mask, probs, ctx);
}

// round 9
// speedup vs baseline: 1.6855x; 1.1405x over previous
#include <cuda_runtime.h>
#include <cuda_bf16.h>
#include <cuda_fp16.h>
#include <math.h>
#include <stdint.h>

#define Bn   4
#define Sn   2048
#define HIDn 1024
#define NHn  16
#define Dn   64
#define BHn  64
#define Mn   8192

// ---------------- scratch (static device globals; no runtime alloc) --------
__device__ __nv_bfloat16 g_xh[(size_t)Mn * HIDn];
__device__ __nv_bfloat16 g_xl[(size_t)Mn * HIDn];
__device__ __nv_bfloat16 g_wh[(size_t)3 * HIDn * HIDn];
__device__ __nv_bfloat16 g_wl[(size_t)3 * HIDn * HIDn];
__device__ __half g_qfh[(size_t)BHn * Sn * Dn];
__device__ __half g_qfl[(size_t)BHn * Sn * Dn];
__device__ __half g_kfh[(size_t)BHn * Sn * Dn];
__device__ __half g_kfl[(size_t)BHn * Sn * Dn];
__device__ __half g_vf [(size_t)BHn * Sn * Dn];
__device__ float g_m[(size_t)BHn * Sn];
__device__ float g_l[(size_t)BHn * Sn];

// ---------------- PTX helpers (baseline-feature PTX only) -------------------
__device__ __forceinline__ uint32_t smem_u32(const void* p) {
    uint32_t a;
    asm("{ .reg .u64 t; cvta.to.shared.u64 t, %1; cvt.u32.u64 %0, t; }" : "=r"(a) : "l"(p));
    return a;
}
#define CP_ASYNC(dst, src) \
    asm volatile("cp.async.cg.shared.global [%0], [%1], 16;" :: "r"(dst), "l"(src))
#define CP_COMMIT() asm volatile("cp.async.commit_group;")
#define CP_WAIT0()  asm volatile("cp.async.wait_group 0;")
#define CP_WAIT1()  asm volatile("cp.async.wait_group 1;")

__device__ __forceinline__ void ldsm4(uint32_t r[4], uint32_t addr) {
    asm volatile("ldmatrix.sync.aligned.m8n8.x4.shared.b16 {%0,%1,%2,%3}, [%4];"
        : "=r"(r[0]), "=r"(r[1]), "=r"(r[2]), "=r"(r[3]) : "r"(addr));
}
__device__ __forceinline__ void ldsm4_t(uint32_t r[4], uint32_t addr) {
    asm volatile("ldmatrix.sync.aligned.m8n8.x4.trans.shared.b16 {%0,%1,%2,%3}, [%4];"
        : "=r"(r[0]), "=r"(r[1]), "=r"(r[2]), "=r"(r[3]) : "r"(addr));
}
// bf16 mma (used by qkv projection)
__device__ __forceinline__ void mma16816(float c[4], const uint32_t a[4],
                                         uint32_t b0, uint32_t b1) {
    asm volatile("mma.sync.aligned.m16n8k16.row.col.f32.bf16.bf16.f32 "
        "{%0,%1,%2,%3}, {%4,%5,%6,%7}, {%8,%9}, {%0,%1,%2,%3};"
        : "+f"(c[0]), "+f"(c[1]), "+f"(c[2]), "+f"(c[3])
        : "r"(a[0]), "r"(a[1]), "r"(a[2]), "r"(a[3]), "r"(b0), "r"(b1));
}
// fp16 mma (used by stats + fused)
__device__ __forceinline__ void mma16816h(float c[4], const uint32_t a[4],
                                          uint32_t b0, uint32_t b1) {
    asm volatile("mma.sync.aligned.m16n8k16.row.col.f32.f16.f16.f32 "
        "{%0,%1,%2,%3}, {%4,%5,%6,%7}, {%8,%9}, {%0,%1,%2,%3};"
        : "+f"(c[0]), "+f"(c[1]), "+f"(c[2]), "+f"(c[3])
        : "r"(a[0]), "r"(a[1]), "r"(a[2]), "r"(a[3]), "r"(b0), "r"(b1));
}

// ---------------- splits ----------------------------------------------------
__device__ __forceinline__ void split1(float v, uint16_t& h, uint16_t& l) {     // bf16
    __nv_bfloat16 hb = __float2bfloat16(v);
    float r = v - __bfloat162float(hb);
    h = __bfloat16_as_ushort(hb);
    l = __bfloat16_as_ushort(__float2bfloat16(r));
}
__device__ __forceinline__ void split_pack(float v0, float v1, uint32_t& ph, uint32_t& pl) {
    uint16_t h0, h1, l0, l1;
    split1(v0, h0, l0); split1(v1, h1, l1);
    ph = ((uint32_t)h1 << 16) | h0;
    pl = ((uint32_t)l1 << 16) | l0;
}
__device__ __forceinline__ void split1h(float v, uint16_t& h, uint16_t& l) {    // fp16
    __half hb = __float2half_rn(v);
    float r = v - __half2float(hb);
    h = __half_as_ushort(hb);
    l = __half_as_ushort(__float2half_rn(r));
}
__device__ __forceinline__ void split_packh(float v0, float v1, uint32_t& ph, uint32_t& pl) {
    uint16_t h0, h1, l0, l1;
    split1h(v0, h0, l0); split1h(v1, h1, l1);
    ph = ((uint32_t)h1 << 16) | h0;
    pl = ((uint32_t)l1 << 16) | l0;
}
__device__ __forceinline__ uint32_t packh1(float v0, float v1) {
    return ((uint32_t)__half_as_ushort(__float2half_rn(v1)) << 16) |
           (uint32_t)__half_as_ushort(__float2half_rn(v0));
}

__global__ __launch_bounds__(256) void split_x_kernel(const float4* __restrict__ src) {
    size_t i = (size_t)blockIdx.x * 256 + threadIdx.x;
    float4 v = src[i];
    uint32_t h01, l01, h23, l23;
    split_pack(v.x, v.y, h01, l01);
    split_pack(v.z, v.w, h23, l23);
    ((uint2*)g_xh)[i] = make_uint2(h01, h23);
    ((uint2*)g_xl)[i] = make_uint2(l01, l23);
}

__global__ __launch_bounds__(256) void split_w_kernel(const float4* __restrict__ Wq,
                                                      const float4* __restrict__ Wk,
                                                      const float4* __restrict__ Wv) {
    const int which = blockIdx.y;
    const float4* W = (which == 0) ? Wq : ((which == 1) ? Wk : Wv);
    size_t i = (size_t)blockIdx.x * 256 + threadIdx.x;
    float4 v = W[i];
    uint32_t h01, l01, h23, l23;
    split_pack(v.x, v.y, h01, l01);
    split_pack(v.z, v.w, h23, l23);
    size_t o = (size_t)which * (HIDn * HIDn / 4) + i;
    ((uint2*)g_wh)[o] = make_uint2(h01, h23);
    ((uint2*)g_wl)[o] = make_uint2(l01, l23);
}

// Tile: 128 rows x 64 elems x 2B (128B data + 16B pad = 144B row stride).
#define ROWB 144
#define T1   (128 * ROWB)     // 18432 B per tile

// ---------------------------------------------------------------------------
// K1: QKV projection (bf16 3-term, unchanged math).  Epilogue writes fp16:
// Q -> g_qfh/g_qfl, K -> g_kfh/g_kfl, V -> g_vf (single).
// ---------------------------------------------------------------------------
#define K1_SMEM (8 * T1)      // 147456 B

__global__ __launch_bounds__(256) void qkv_mma(
    const float* __restrict__ bq, const float* __restrict__ bk, const float* __restrict__ bv)
{
    extern __shared__ char smem[];
    const uint32_t sb = smem_u32(smem);
    const int tid = threadIdx.x;
    const int lane = tid & 31;
    const int wid = tid >> 5;
    const int warp_m = wid & 1;
    const int warp_n = wid >> 1;
    const int which = blockIdx.z;
    const int m0 = blockIdx.x * 128;
    const int n0 = blockIdx.y * 128;
    const float* bias = (which == 0) ? bq : ((which == 1) ? bk : bv);
    const __nv_bfloat16* wh = g_wh + (size_t)which * HIDn * HIDn;
    const __nv_bfloat16* wl = g_wl + (size_t)which * HIDn * HIDn;

    float C[4][4][4];
#pragma unroll
    for (int a = 0; a < 4; a++)
#pragma unroll
        for (int n = 0; n < 4; n++)
#pragma unroll
            for (int j = 0; j < 4; j++) C[a][n][j] = 0.0f;

    auto load_chunk = [&](int chunk, int buf) {
        const int kc = chunk * 64;
        const uint32_t bufb = sb + buf * 4 * T1;
#pragma unroll
        for (int t = 0; t < 4; t++) {
            const __nv_bfloat16* src = (t == 0) ? g_xh : (t == 1) ? g_xl : (t == 2) ? wh : wl;
            const int rbase = (t < 2) ? m0 : n0;
#pragma unroll
            for (int i = 0; i < 4; i++) {
                const int idx = tid + 256 * i;
                const int row = idx >> 3, c = idx & 7;
                CP_ASYNC(bufb + t * T1 + row * ROWB + c * 16,
                         src + (size_t)(rbase + row) * HIDn + kc + c * 8);
            }
        }
        CP_COMMIT();
    };

    auto compute = [&](int buf) {
        const uint32_t base = sb + buf * 4 * T1;
#pragma unroll
        for (int ks = 0; ks < 4; ks++) {
            uint32_t ah[4][4], al[4][4];
#pragma unroll
            for (int a = 0; a < 4; a++) {
                const int row = warp_m * 64 + a * 16 + ((lane >> 3) & 1) * 8 + (lane & 7);
                const int colb = ks * 32 + (lane >> 4) * 16;
                ldsm4(ah[a], base + row * ROWB + colb);
                ldsm4(al[a], base + T1 + row * ROWB + colb);
            }
            uint32_t bh[2][4], bl[2][4];
#pragma unroll
            for (int p = 0; p < 2; p++) {
                const int row = warp_n * 32 + p * 16 + ((lane >> 4) & 1) * 8 + (lane & 7);
                const int colb = ks * 32 + ((lane >> 3) & 1) * 16;
                ldsm4(bh[p], base + 2 * T1 + row * ROWB + colb);
                ldsm4(bl[p], base + 3 * T1 + row * ROWB + colb);
            }
#pragma unroll
            for (int a = 0; a < 4; a++)
#pragma unroll
                for (int n = 0; n < 4; n++) {
                    const int p = n >> 1, q = (n & 1) * 2;
                    mma16816(C[a][n], ah[a], bh[p][q], bh[p][q + 1]);
                    mma16816(C[a][n], ah[a], bl[p][q], bl[p][q + 1]);
                    mma16816(C[a][n], al[a], bh[p][q], bh[p][q + 1]);
                }
        }
    };

    load_chunk(0, 0);
    load_chunk(1, 1);
    for (int kt = 0; kt < 16; kt++) {
        if (kt == 15) { CP_WAIT0(); } else { CP_WAIT1(); }
        __syncthreads();
        compute(kt & 1);
        __syncthreads();
        if (kt + 2 < 16) load_chunk(kt + 2, kt & 1);
    }

    // epilogue: bias + fp16 split + scatter to [bh][s][d]
#pragma unroll
    for (int a = 0; a < 4; a++)
#pragma unroll
        for (int n = 0; n < 4; n++) {
            const int row0 = m0 + warp_m * 64 + a * 16 + (lane >> 2);
            const int col  = n0 + warp_n * 32 + n * 8 + (lane & 3) * 2;
            const float bb0 = bias[col], bb1 = bias[col + 1];
            const int hd = col >> 6, d = col & 63;
#pragma unroll
            for (int h = 0; h < 2; h++) {
                const int row = row0 + h * 8;
                const float v0 = C[a][n][h * 2 + 0] + bb0;
                const float v1 = C[a][n][h * 2 + 1] + bb1;
                const int bidx = row >> 11, s = row & (Sn - 1);
                const size_t oi = ((size_t)(bidx * NHn + hd) * Sn + s) * Dn + d;
                if (which == 2) {
                    *(uint32_t*)&g_vf[oi] = packh1(v0, v1);
                } else {
                    uint32_t ph, pl;
                    split_packh(v0, v1, ph, pl);
                    __half* oh = (which == 0) ? g_qfh : g_kfh;
                    __half* ol = (which == 0) ? g_qfl : g_kfl;
                    *(uint32_t*)&oh[oi] = ph;
                    *(uint32_t*)&ol[oi] = pl;
                }
            }
        }
}

// ---------------------------------------------------------------------------
// K2a: softmax stats only.  fp16 2-term: (Qh + Ql) x Kh.  K-lo never loaded.
// smem: Qh | Ql | Khbuf0 | Khbuf1 | mask | red  = 86016 B
// ---------------------------------------------------------------------------
#define K2_MASKOFF (4 * T1)                    // 73728
#define K2_REDM    (K2_MASKOFF + Sn * 4)       // 81920
#define K2_REDL    (K2_REDM + 4 * 128 * 4)     // 83968
#define K2_SMEM    (K2_REDL + 4 * 128 * 4)     // 86016

__global__ __launch_bounds__(256) void stats_mma(const float* __restrict__ mask)
{
    extern __shared__ char smem[];
    const uint32_t sb = smem_u32(smem);
    float* maskS = (float*)(smem + K2_MASKOFF);
    float* redM  = (float*)(smem + K2_REDM);
    float* redL  = (float*)(smem + K2_REDL);
    const int tid = threadIdx.x;
    const int lane = tid & 31;
    const int wid = tid >> 5;
    const int warp_m = wid & 1;
    const int warp_n = wid >> 1;
    const int qt = blockIdx.x;
    const int bh = blockIdx.y;
    const int bidx = bh >> 4;
    const int grow = qt * 128;

    const size_t qgb = ((size_t)bh * Sn + grow) * Dn;
#pragma unroll
    for (int i = 0; i < 4; i++) {
        const int idx = tid + 256 * i;
        const int row = idx >> 3, c = idx & 7;
        CP_ASYNC(sb + row * ROWB + c * 16,      g_qfh + qgb + row * Dn + c * 8);
        CP_ASYNC(sb + T1 + row * ROWB + c * 16, g_qfl + qgb + row * Dn + c * 8);
    }
#pragma unroll
    for (int i = 0; i < 2; i++)
        ((float4*)maskS)[tid + 256 * i] = ((const float4*)(mask + (size_t)bidx * Sn))[tid + 256 * i];

    auto load_k = [&](int kt, int buf) {
        const size_t kgb = ((size_t)bh * Sn + kt * 128) * Dn;
        const uint32_t bufb = sb + 2 * T1 + buf * T1;
#pragma unroll
        for (int i = 0; i < 4; i++) {
            const int idx = tid + 256 * i;
            const int row = idx >> 3, c = idx & 7;
            CP_ASYNC(bufb + row * ROWB + c * 16, g_kfh + kgb + row * Dn + c * 8);
        }
        CP_COMMIT();
    };

    load_k(0, 0);
    load_k(1, 1);

    float sm_[8], sl_[8];
#pragma unroll
    for (int i = 0; i < 8; i++) { sm_[i] = -1e30f; sl_[i] = 0.0f; }

    for (int kt = 0; kt < 16; kt++) {
        if (kt == 15) { CP_WAIT0(); } else { CP_WAIT1(); }
        __syncthreads();

        const uint32_t kbase = sb + 2 * T1 + (kt & 1) * T1;
        float C[4][4][4];
#pragma unroll
        for (int a = 0; a < 4; a++)
#pragma unroll
            for (int n = 0; n < 4; n++)
#pragma unroll
                for (int j = 0; j < 4; j++) C[a][n][j] = 0.0f;

#pragma unroll
        for (int ks = 0; ks < 4; ks++) {
            uint32_t ah[4][4], al[4][4];
#pragma unroll
            for (int a = 0; a < 4; a++) {
                const int row = warp_m * 64 + a * 16 + ((lane >> 3) & 1) * 8 + (lane & 7);
                const int colb = ks * 32 + (lane >> 4) * 16;
                ldsm4(ah[a], sb + row * ROWB + colb);
                ldsm4(al[a], sb + T1 + row * ROWB + colb);
            }
            uint32_t bhf[2][4];
#pragma unroll
            for (int p = 0; p < 2; p++) {
                const int row = warp_n * 32 + p * 16 + ((lane >> 4) & 1) * 8 + (lane & 7);
                const int colb = ks * 32 + ((lane >> 3) & 1) * 16;
                ldsm4(bhf[p], kbase + row * ROWB + colb);
            }
#pragma unroll
            for (int a = 0; a < 4; a++)
#pragma unroll
                for (int n = 0; n < 4; n++) {
                    const int p = n >> 1, q = (n & 1) * 2;
                    mma16816h(C[a][n], ah[a], bhf[p][q], bhf[p][q + 1]);
                    mma16816h(C[a][n], al[a], bhf[p][q], bhf[p][q + 1]);
                }
        }

#pragma unroll
        for (int a = 0; a < 4; a++) {
            float s[4][4];
#pragma unroll
            for (int n = 0; n < 4; n++) {
                const int colt = warp_n * 32 + n * 8 + (lane & 3) * 2;
                const float mk0 = maskS[kt * 128 + colt];
                const float mk1 = maskS[kt * 128 + colt + 1];
                s[n][0] = C[a][n][0] * 0.125f + mk0;
                s[n][1] = C[a][n][1] * 0.125f + mk1;
                s[n][2] = C[a][n][2] * 0.125f + mk0;
                s[n][3] = C[a][n][3] * 0.125f + mk1;
            }
#pragma unroll
            for (int hh = 0; hh < 2; hh++) {
                float cm = s[0][hh * 2];
#pragma unroll
                for (int n = 0; n < 4; n++) {
                    cm = fmaxf(cm, s[n][hh * 2]);
                    cm = fmaxf(cm, s[n][hh * 2 + 1]);
                }
                const int si = a * 2 + hh;
                const float mn = fmaxf(sm_[si], cm);
                float ps = 0.0f;
#pragma unroll
                for (int n = 0; n < 4; n++)
                    ps += __expf(s[n][hh * 2] - mn) + __expf(s[n][hh * 2 + 1] - mn);
                sl_[si] = sl_[si] * __expf(sm_[si] - mn) + ps;
                sm_[si] = mn;
            }
        }

        __syncthreads();
        if (kt + 2 < 16) load_k(kt + 2, kt & 1);
    }

#pragma unroll
    for (int i = 0; i < 8; i++) {
        float m = sm_[i], l = sl_[i];
#pragma unroll
        for (int off = 1; off <= 2; off <<= 1) {
            const float om = __shfl_xor_sync(0xffffffffu, m, off);
            const float ol = __shfl_xor_sync(0xffffffffu, l, off);
            const float mn = fmaxf(m, om);
            l = l * __expf(m - mn) + ol * __expf(om - mn);
            m = mn;
        }
        if ((lane & 3) == 0) {
            const int row = warp_m * 64 + (i >> 1) * 16 + (i & 1) * 8 + (lane >> 2);
            redM[warp_n * 128 + row] = m;
            redL[warp_n * 128 + row] = l;
        }
    }
    __syncthreads();
    if (tid < 128) {
        float m = redM[tid], l = redL[tid];
#pragma unroll
        for (int w = 1; w < 4; w++) {
            const float om = redM[w * 128 + tid];
            const float ol = redL[w * 128 + tid];
            const float mn = fmaxf(m, om);
            l = l * __expf(m - mn) + ol * __expf(om - mn);
            m = mn;
        }
        g_m[(size_t)bh * Sn + grow + tid] = m;
        g_l[(size_t)bh * Sn + grow + tid] = l;
    }
}

// ---------------------------------------------------------------------------
// K2b: fused.  QK^T fp16 3-term; p = exp(s-m)*invl; write final probs;
// P@V fp16 2-term (p-split x V-hi).
// smem: Qh|Ql | Kh0 Kl0 Kh1 Kl1 | Vh0 Vh1 | mask | m | invl = 156672 B
// ---------------------------------------------------------------------------
#define F_KOFF  (2 * T1)
#define F_VOFF  (6 * T1)
#define F_MASK  (8 * T1)                  // 147456
#define F_MROW  (F_MASK + Sn * 4)         // 155648
#define F_LROW  (F_MROW + 512)            // 156160
#define F_SMEM  (F_LROW + 512)            // 156672

__global__ __launch_bounds__(256) void fused_pv(
    const float* __restrict__ mask, float* __restrict__ probs, float* __restrict__ ctx)
{
    extern __shared__ char smem[];
    const uint32_t sb = smem_u32(smem);
    float* maskS = (float*)(smem + F_MASK);
    float* mrow  = (float*)(smem + F_MROW);
    float* lrow  = (float*)(smem + F_LROW);
    const int tid = threadIdx.x;
    const int lane = tid & 31;
    const int wid = tid >> 5;
    const int qt = blockIdx.x;
    const int bh = blockIdx.y;
    const int bidx = bh >> 4;
    const int h    = bh & 15;
    const int q0 = qt * 128;

    const size_t qgb = ((size_t)bh * Sn + q0) * Dn;
#pragma unroll
    for (int i = 0; i < 4; i++) {
        const int idx = tid + 256 * i;
        const int row = idx >> 3, c = idx & 7;
        CP_ASYNC(sb + row * ROWB + c * 16,      g_qfh + qgb + row * Dn + c * 8);
        CP_ASYNC(sb + T1 + row * ROWB + c * 16, g_qfl + qgb + row * Dn + c * 8);
    }

    auto load_kv = [&](int kt, int buf) {
        const size_t gb = ((size_t)bh * Sn + kt * 128) * Dn;
        const uint32_t kb = sb + F_KOFF + buf * 2 * T1;
        const uint32_t vb = sb + F_VOFF + buf * T1;
#pragma unroll
        for (int i = 0; i < 4; i++) {
            const int idx = tid + 256 * i;
            const int row = idx >> 3, c = idx & 7;
            const size_t g = gb + (size_t)row * Dn + c * 8;
            CP_ASYNC(kb + row * ROWB + c * 16,      g_kfh + g);
            CP_ASYNC(kb + T1 + row * ROWB + c * 16, g_kfl + g);
            CP_ASYNC(vb + row * ROWB + c * 16,      g_vf + g);
        }
        CP_COMMIT();
    };

    load_kv(0, 0);
    load_kv(1, 1);

#pragma unroll
    for (int i = 0; i < 2; i++)
        ((float4*)maskS)[tid + 256 * i] = ((const float4*)(mask + (size_t)bidx * Sn))[tid + 256 * i];
    if (tid < 128) {
        const size_t ro = (size_t)bh * Sn + q0 + tid;
        mrow[tid] = g_m[ro];
        lrow[tid] = 1.0f / g_l[ro];
    }

    float O[8][4];
#pragma unroll
    for (int n = 0; n < 8; n++)
#pragma unroll
        for (int j = 0; j < 4; j++) O[n][j] = 0.0f;

    const int rloc0 = wid * 16 + (lane >> 2);
    float mm0, ll0, mm1, ll1;

    for (int kt = 0; kt < 16; kt++) {
        if (kt == 15) { CP_WAIT0(); } else { CP_WAIT1(); }
        __syncthreads();
        if (kt == 0) { mm0 = mrow[rloc0]; ll0 = lrow[rloc0];
                       mm1 = mrow[rloc0 + 8]; ll1 = lrow[rloc0 + 8]; }

        const uint32_t kbase = sb + F_KOFF + (kt & 1) * 2 * T1;
        const uint32_t vbase = sb + F_VOFF + (kt & 1) * T1;

        float C[16][4];
#pragma unroll
        for (int n = 0; n < 16; n++)
#pragma unroll
            for (int j = 0; j < 4; j++) C[n][j] = 0.0f;

#pragma unroll
        for (int ks = 0; ks < 4; ks++) {
            uint32_t qh4[4], ql4[4];
            {
                const int row = wid * 16 + ((lane >> 3) & 1) * 8 + (lane & 7);
                const int colb = ks * 32 + (lane >> 4) * 16;
                ldsm4(qh4, sb + row * ROWB + colb);
                ldsm4(ql4, sb + T1 + row * ROWB + colb);
            }
#pragma unroll
            for (int g = 0; g < 8; g++) {
                uint32_t kh4[4], kl4[4];
                const int row = g * 16 + ((lane >> 4) & 1) * 8 + (lane & 7);
                const int colb = ks * 32 + ((lane >> 3) & 1) * 16;
                ldsm4(kh4, kbase + row * ROWB + colb);
                ldsm4(kl4, kbase + T1 + row * ROWB + colb);
                mma16816h(C[2*g],   qh4, kh4[0], kh4[1]);
                mma16816h(C[2*g],   qh4, kl4[0], kl4[1]);
                mma16816h(C[2*g],   ql4, kh4[0], kh4[1]);
                mma16816h(C[2*g+1], qh4, kh4[2], kh4[3]);
                mma16816h(C[2*g+1], qh4, kl4[2], kl4[3]);
                mma16816h(C[2*g+1], ql4, kh4[2], kh4[3]);
            }
        }

        const size_t prow0 = ((size_t)bh * Sn + q0 + rloc0) * Sn + kt * 128;
        const size_t prow1 = prow0 + (size_t)8 * Sn;
#pragma unroll
        for (int n = 0; n < 16; n++) {
            const int colt = n * 8 + (lane & 3) * 2;
            const float mk0 = maskS[kt * 128 + colt];
            const float mk1 = maskS[kt * 128 + colt + 1];
            const float p00 = __expf(C[n][0] * 0.125f + mk0 - mm0) * ll0;
            const float p01 = __expf(C[n][1] * 0.125f + mk1 - mm0) * ll0;
            const float p10 = __expf(C[n][2] * 0.125f + mk0 - mm1) * ll1;
            const float p11 = __expf(C[n][3] * 0.125f + mk1 - mm1) * ll1;
            C[n][0] = p00; C[n][1] = p01; C[n][2] = p10; C[n][3] = p11;
            *(float2*)&probs[prow0 + colt] = make_float2(p00, p01);
            *(float2*)&probs[prow1 + colt] = make_float2(p10, p11);
        }

        // P@V: fp16 2-term (p-split x V-hi)
#pragma unroll
        for (int kg = 0; kg < 8; kg++) {
            uint32_t aph[4], apl[4];
            split_packh(C[2*kg][0],   C[2*kg][1],   aph[0], apl[0]);
            split_packh(C[2*kg][2],   C[2*kg][3],   aph[1], apl[1]);
            split_packh(C[2*kg+1][0], C[2*kg+1][1], aph[2], apl[2]);
            split_packh(C[2*kg+1][2], C[2*kg+1][3], aph[3], apl[3]);
            const uint32_t brow = kg * 16 + (lane & 7) + ((lane >> 3) & 1) * 8;
#pragma unroll
            for (int nb = 0; nb < 4; nb++) {
                uint32_t vh4[4];
                ldsm4_t(vh4, vbase + brow * ROWB + nb * 32 + (lane >> 4) * 16);
                mma16816h(O[nb*2],   aph, vh4[0], vh4[1]);
                mma16816h(O[nb*2],   apl, vh4[0], vh4[1]);
                mma16816h(O[nb*2+1], aph, vh4[2], vh4[3]);
                mma16816h(O[nb*2+1], apl, vh4[2], vh4[3]);
            }
        }

        __syncthreads();
        if (kt + 2 < 16) load_kv(kt + 2, kt & 1);
    }

#pragma unroll
    for (int nb = 0; nb < 8; nb++) {
        const int col = nb * 8 + (lane & 3) * 2;
        const int row = q0 + wid * 16 + (lane >> 2);
        *(float2*)&ctx[((size_t)(bidx * Sn + row)) * HIDn + h * 64 + col] =
            make_float2(O[nb][0], O[nb][1]);
        *(float2*)&ctx[((size_t)(bidx * Sn + row + 8)) * HIDn + h * 64 + col] =
            make_float2(O[nb][2], O[nb][3]);
    }
}

// ---------------------------------------------------------------------------
extern "C" void kernel_launch(void* const* d_in, const int* in_sizes, int n_in,
                              void* d_out, int out_size)
{
    const float* x    = (const float*)d_in[0];
    const float* mask = (const float*)d_in[1];
    const float* Wq   = (const float*)d_in[2];
    const float* bq   = (const float*)d_in[3];
    const float* Wk   = (const float*)d_in[4];
    const float* bk   = (const float*)d_in[5];
    const float* Wv   = (const float*)d_in[6];
    const float* bv   = (const float*)d_in[7];

    float* ctx = (float*)d_out;
    const size_t PROBS_ELEMS = (size_t)BHn * Sn * Sn;
    size_t probs_off = 0;
    if ((size_t)out_size > PROBS_ELEMS) probs_off = (size_t)out_size - PROBS_ELEMS;
    float* probs = (float*)d_out + probs_off;

    cudaFuncSetAttribute(qkv_mma,   cudaFuncAttributeMaxDynamicSharedMemorySize, K1_SMEM);
    cudaFuncSetAttribute(stats_mma, cudaFuncAttributeMaxDynamicSharedMemorySize, K2_SMEM);
    cudaFuncSetAttribute(fused_pv,  cudaFuncAttributeMaxDynamicSharedMemorySize, F_SMEM);

    split_x_kernel<<<Mn * HIDn / 4 / 256, 256>>>((const float4*)x);
    split_w_kernel<<<dim3(HIDn * HIDn / 4 / 256, 3), 256>>>(
        (const float4*)Wq, (const float4*)Wk, (const float4*)Wv);
    qkv_mma<<<dim3(Mn/128, HIDn/128, 3), 256, K1_SMEM>>>(bq, bk, bv);
    stats_mma<<<dim3(Sn/128, BHn), 256, K2_SMEM>>>(mask);
    fused_pv<<<dim3(Sn/128, BHn), 256, F_SMEM>>>(mask, probs, ctx);
}

// round 10
// speedup vs baseline: 1.7851x; 1.0591x over previous
#include <cuda_runtime.h>
#include <cuda_bf16.h>
#include <cuda_fp16.h>
#include <math.h>
#include <stdint.h>

#define Bn   4
#define Sn   2048
#define HIDn 1024
#define NHn  16
#define Dn   64
#define BHn  64
#define Mn   8192

// ---------------- scratch (static device globals; no runtime alloc) --------
__device__ __nv_bfloat16 g_xh[(size_t)Mn * HIDn];
__device__ __nv_bfloat16 g_xl[(size_t)Mn * HIDn];
__device__ __nv_bfloat16 g_wh[(size_t)3 * HIDn * HIDn];
__device__ __nv_bfloat16 g_wl[(size_t)3 * HIDn * HIDn];
__device__ __half g_qfh[(size_t)BHn * Sn * Dn];
__device__ __half g_qfl[(size_t)BHn * Sn * Dn];
__device__ __half g_kfh[(size_t)BHn * Sn * Dn];
__device__ __half g_kfl[(size_t)BHn * Sn * Dn];
__device__ __half g_vf [(size_t)BHn * Sn * Dn];
__device__ float g_m[(size_t)BHn * Sn];
__device__ float g_l[(size_t)BHn * Sn];

// ---------------- PTX helpers (baseline-feature PTX only) -------------------
__device__ __forceinline__ uint32_t smem_u32(const void* p) {
    uint32_t a;
    asm("{ .reg .u64 t; cvta.to.shared.u64 t, %1; cvt.u32.u64 %0, t; }" : "=r"(a) : "l"(p));
    return a;
}
#define CP_ASYNC(dst, src) \
    asm volatile("cp.async.cg.shared.global [%0], [%1], 16;" :: "r"(dst), "l"(src))
#define CP_COMMIT() asm volatile("cp.async.commit_group;")
#define CP_WAIT0()  asm volatile("cp.async.wait_group 0;")
#define CP_WAIT1()  asm volatile("cp.async.wait_group 1;")

__device__ __forceinline__ void ldsm4(uint32_t r[4], uint32_t addr) {
    asm volatile("ldmatrix.sync.aligned.m8n8.x4.shared.b16 {%0,%1,%2,%3}, [%4];"
        : "=r"(r[0]), "=r"(r[1]), "=r"(r[2]), "=r"(r[3]) : "r"(addr));
}
__device__ __forceinline__ void ldsm4_t(uint32_t r[4], uint32_t addr) {
    asm volatile("ldmatrix.sync.aligned.m8n8.x4.trans.shared.b16 {%0,%1,%2,%3}, [%4];"
        : "=r"(r[0]), "=r"(r[1]), "=r"(r[2]), "=r"(r[3]) : "r"(addr));
}
// bf16 mma (qkv projection)
__device__ __forceinline__ void mma16816(float c[4], const uint32_t a[4],
                                         uint32_t b0, uint32_t b1) {
    asm volatile("mma.sync.aligned.m16n8k16.row.col.f32.bf16.bf16.f32 "
        "{%0,%1,%2,%3}, {%4,%5,%6,%7}, {%8,%9}, {%0,%1,%2,%3};"
        : "+f"(c[0]), "+f"(c[1]), "+f"(c[2]), "+f"(c[3])
        : "r"(a[0]), "r"(a[1]), "r"(a[2]), "r"(a[3]), "r"(b0), "r"(b1));
}
// fp16 mma (stats + fused)
__device__ __forceinline__ void mma16816h(float c[4], const uint32_t a[4],
                                          uint32_t b0, uint32_t b1) {
    asm volatile("mma.sync.aligned.m16n8k16.row.col.f32.f16.f16.f32 "
        "{%0,%1,%2,%3}, {%4,%5,%6,%7}, {%8,%9}, {%0,%1,%2,%3};"
        : "+f"(c[0]), "+f"(c[1]), "+f"(c[2]), "+f"(c[3])
        : "r"(a[0]), "r"(a[1]), "r"(a[2]), "r"(a[3]), "r"(b0), "r"(b1));
}

// ---------------- splits ----------------------------------------------------
__device__ __forceinline__ void split1(float v, uint16_t& h, uint16_t& l) {     // bf16
    __nv_bfloat16 hb = __float2bfloat16(v);
    float r = v - __bfloat162float(hb);
    h = __bfloat16_as_ushort(hb);
    l = __bfloat16_as_ushort(__float2bfloat16(r));
}
__device__ __forceinline__ void split_pack(float v0, float v1, uint32_t& ph, uint32_t& pl) {
    uint16_t h0, h1, l0, l1;
    split1(v0, h0, l0); split1(v1, h1, l1);
    ph = ((uint32_t)h1 << 16) | h0;
    pl = ((uint32_t)l1 << 16) | l0;
}
__device__ __forceinline__ void split1h(float v, uint16_t& h, uint16_t& l) {    // fp16
    __half hb = __float2half_rn(v);
    float r = v - __half2float(hb);
    h = __half_as_ushort(hb);
    l = __half_as_ushort(__float2half_rn(r));
}
__device__ __forceinline__ void split_packh(float v0, float v1, uint32_t& ph, uint32_t& pl) {
    uint16_t h0, h1, l0, l1;
    split1h(v0, h0, l0); split1h(v1, h1, l1);
    ph = ((uint32_t)h1 << 16) | h0;
    pl = ((uint32_t)l1 << 16) | l0;
}
__device__ __forceinline__ uint32_t packh1(float v0, float v1) {
    return ((uint32_t)__half_as_ushort(__float2half_rn(v1)) << 16) |
           (uint32_t)__half_as_ushort(__float2half_rn(v0));
}

__global__ __launch_bounds__(256) void split_x_kernel(const float4* __restrict__ src) {
    size_t i = (size_t)blockIdx.x * 256 + threadIdx.x;
    float4 v = src[i];
    uint32_t h01, l01, h23, l23;
    split_pack(v.x, v.y, h01, l01);
    split_pack(v.z, v.w, h23, l23);
    ((uint2*)g_xh)[i] = make_uint2(h01, h23);
    ((uint2*)g_xl)[i] = make_uint2(l01, l23);
}

__global__ __launch_bounds__(256) void split_w_kernel(const float4* __restrict__ Wq,
                                                      const float4* __restrict__ Wk,
                                                      const float4* __restrict__ Wv) {
    const int which = blockIdx.y;
    const float4* W = (which == 0) ? Wq : ((which == 1) ? Wk : Wv);
    size_t i = (size_t)blockIdx.x * 256 + threadIdx.x;
    float4 v = W[i];
    uint32_t h01, l01, h23, l23;
    split_pack(v.x, v.y, h01, l01);
    split_pack(v.z, v.w, h23, l23);
    size_t o = (size_t)which * (HIDn * HIDn / 4) + i;
    ((uint2*)g_wh)[o] = make_uint2(h01, h23);
    ((uint2*)g_wl)[o] = make_uint2(l01, l23);
}

// Tile: 128 rows x 64 elems x 2B (128B data + 16B pad = 144B row stride).
#define ROWB 144
#define T1   (128 * ROWB)     // 18432 B per tile

// ---------------------------------------------------------------------------
// K1: QKV projection (bf16 3-term).  Epilogue writes fp16:
// Q -> g_qfh/g_qfl, K -> g_kfh/g_kfl, V -> g_vf.
// ---------------------------------------------------------------------------
#define K1_SMEM (8 * T1)      // 147456 B

__global__ __launch_bounds__(256) void qkv_mma(
    const float* __restrict__ bq, const float* __restrict__ bk, const float* __restrict__ bv)
{
    extern __shared__ char smem[];
    const uint32_t sb = smem_u32(smem);
    const int tid = threadIdx.x;
    const int lane = tid & 31;
    const int wid = tid >> 5;
    const int warp_m = wid & 1;
    const int warp_n = wid >> 1;
    const int which = blockIdx.z;
    const int m0 = blockIdx.x * 128;
    const int n0 = blockIdx.y * 128;
    const float* bias = (which == 0) ? bq : ((which == 1) ? bk : bv);
    const __nv_bfloat16* wh = g_wh + (size_t)which * HIDn * HIDn;
    const __nv_bfloat16* wl = g_wl + (size_t)which * HIDn * HIDn;

    float C[4][4][4];
#pragma unroll
    for (int a = 0; a < 4; a++)
#pragma unroll
        for (int n = 0; n < 4; n++)
#pragma unroll
            for (int j = 0; j < 4; j++) C[a][n][j] = 0.0f;

    auto load_chunk = [&](int chunk, int buf) {
        const int kc = chunk * 64;
        const uint32_t bufb = sb + buf * 4 * T1;
#pragma unroll
        for (int t = 0; t < 4; t++) {
            const __nv_bfloat16* src = (t == 0) ? g_xh : (t == 1) ? g_xl : (t == 2) ? wh : wl;
            const int rbase = (t < 2) ? m0 : n0;
#pragma unroll
            for (int i = 0; i < 4; i++) {
                const int idx = tid + 256 * i;
                const int row = idx >> 3, c = idx & 7;
                CP_ASYNC(bufb + t * T1 + row * ROWB + c * 16,
                         src + (size_t)(rbase + row) * HIDn + kc + c * 8);
            }
        }
        CP_COMMIT();
    };

    auto compute = [&](int buf) {
        const uint32_t base = sb + buf * 4 * T1;
#pragma unroll
        for (int ks = 0; ks < 4; ks++) {
            uint32_t ah[4][4], al[4][4];
#pragma unroll
            for (int a = 0; a < 4; a++) {
                const int row = warp_m * 64 + a * 16 + ((lane >> 3) & 1) * 8 + (lane & 7);
                const int colb = ks * 32 + (lane >> 4) * 16;
                ldsm4(ah[a], base + row * ROWB + colb);
                ldsm4(al[a], base + T1 + row * ROWB + colb);
            }
            uint32_t bh[2][4], bl[2][4];
#pragma unroll
            for (int p = 0; p < 2; p++) {
                const int row = warp_n * 32 + p * 16 + ((lane >> 4) & 1) * 8 + (lane & 7);
                const int colb = ks * 32 + ((lane >> 3) & 1) * 16;
                ldsm4(bh[p], base + 2 * T1 + row * ROWB + colb);
                ldsm4(bl[p], base + 3 * T1 + row * ROWB + colb);
            }
#pragma unroll
            for (int a = 0; a < 4; a++)
#pragma unroll
                for (int n = 0; n < 4; n++) {
                    const int p = n >> 1, q = (n & 1) * 2;
                    mma16816(C[a][n], ah[a], bh[p][q], bh[p][q + 1]);
                    mma16816(C[a][n], ah[a], bl[p][q], bl[p][q + 1]);
                    mma16816(C[a][n], al[a], bh[p][q], bh[p][q + 1]);
                }
        }
    };

    load_chunk(0, 0);
    load_chunk(1, 1);
    for (int kt = 0; kt < 16; kt++) {
        if (kt == 15) { CP_WAIT0(); } else { CP_WAIT1(); }
        __syncthreads();
        compute(kt & 1);
        __syncthreads();
        if (kt + 2 < 16) load_chunk(kt + 2, kt & 1);
    }

    // epilogue: bias + fp16 split + scatter to [bh][s][d]
#pragma unroll
    for (int a = 0; a < 4; a++)
#pragma unroll
        for (int n = 0; n < 4; n++) {
            const int row0 = m0 + warp_m * 64 + a * 16 + (lane >> 2);
            const int col  = n0 + warp_n * 32 + n * 8 + (lane & 3) * 2;
            const float bb0 = bias[col], bb1 = bias[col + 1];
            const int hd = col >> 6, d = col & 63;
#pragma unroll
            for (int h = 0; h < 2; h++) {
                const int row = row0 + h * 8;
                const float v0 = C[a][n][h * 2 + 0] + bb0;
                const float v1 = C[a][n][h * 2 + 1] + bb1;
                const int bidx = row >> 11, s = row & (Sn - 1);
                const size_t oi = ((size_t)(bidx * NHn + hd) * Sn + s) * Dn + d;
                if (which == 2) {
                    *(uint32_t*)&g_vf[oi] = packh1(v0, v1);
                } else {
                    uint32_t ph, pl;
                    split_packh(v0, v1, ph, pl);
                    __half* oh = (which == 0) ? g_qfh : g_kfh;
                    __half* ol = (which == 0) ? g_qfl : g_kfl;
                    *(uint32_t*)&oh[oi] = ph;
                    *(uint32_t*)&ol[oi] = pl;
                }
            }
        }
}

// ---------------------------------------------------------------------------
// K2a: softmax stats only.  fp16 1-term: Qh x Kh.  (m cancels exactly in the
// fused normalize; l error averages out over the row.)
// smem: Qh | Khbuf0 | Khbuf1 | mask | red = 67584 B  -> 2 CTAs/SM (forced).
// ---------------------------------------------------------------------------
#define K2_MASKOFF (3 * T1)                    // 55296
#define K2_REDM    (K2_MASKOFF + Sn * 4)       // 63488
#define K2_REDL    (K2_REDM + 4 * 128 * 4)     // 65536
#define K2_SMEM    (K2_REDL + 4 * 128 * 4)     // 67584

__global__ __launch_bounds__(256, 2) void stats_mma(const float* __restrict__ mask)
{
    extern __shared__ char smem[];
    const uint32_t sb = smem_u32(smem);
    float* maskS = (float*)(smem + K2_MASKOFF);
    float* redM  = (float*)(smem + K2_REDM);
    float* redL  = (float*)(smem + K2_REDL);
    const int tid = threadIdx.x;
    const int lane = tid & 31;
    const int wid = tid >> 5;
    const int warp_m = wid & 1;
    const int warp_n = wid >> 1;
    const int qt = blockIdx.x;
    const int bh = blockIdx.y;
    const int bidx = bh >> 4;
    const int grow = qt * 128;

    const size_t qgb = ((size_t)bh * Sn + grow) * Dn;
#pragma unroll
    for (int i = 0; i < 4; i++) {
        const int idx = tid + 256 * i;
        const int row = idx >> 3, c = idx & 7;
        CP_ASYNC(sb + row * ROWB + c * 16, g_qfh + qgb + row * Dn + c * 8);
    }
#pragma unroll
    for (int i = 0; i < 2; i++)
        ((float4*)maskS)[tid + 256 * i] = ((const float4*)(mask + (size_t)bidx * Sn))[tid + 256 * i];

    auto load_k = [&](int kt, int buf) {
        const size_t kgb = ((size_t)bh * Sn + kt * 128) * Dn;
        const uint32_t bufb = sb + T1 + buf * T1;
#pragma unroll
        for (int i = 0; i < 4; i++) {
            const int idx = tid + 256 * i;
            const int row = idx >> 3, c = idx & 7;
            CP_ASYNC(bufb + row * ROWB + c * 16, g_kfh + kgb + row * Dn + c * 8);
        }
        CP_COMMIT();
    };

    load_k(0, 0);
    load_k(1, 1);

    float sm_[8], sl_[8];
#pragma unroll
    for (int i = 0; i < 8; i++) { sm_[i] = -1e30f; sl_[i] = 0.0f; }

    for (int kt = 0; kt < 16; kt++) {
        if (kt == 15) { CP_WAIT0(); } else { CP_WAIT1(); }
        __syncthreads();

        const uint32_t kbase = sb + T1 + (kt & 1) * T1;
        float C[4][4][4];
#pragma unroll
        for (int a = 0; a < 4; a++)
#pragma unroll
            for (int n = 0; n < 4; n++)
#pragma unroll
                for (int j = 0; j < 4; j++) C[a][n][j] = 0.0f;

#pragma unroll
        for (int ks = 0; ks < 4; ks++) {
            uint32_t ah[4][4];
#pragma unroll
            for (int a = 0; a < 4; a++) {
                const int row = warp_m * 64 + a * 16 + ((lane >> 3) & 1) * 8 + (lane & 7);
                const int colb = ks * 32 + (lane >> 4) * 16;
                ldsm4(ah[a], sb + row * ROWB + colb);
            }
            uint32_t bhf[2][4];
#pragma unroll
            for (int p = 0; p < 2; p++) {
                const int row = warp_n * 32 + p * 16 + ((lane >> 4) & 1) * 8 + (lane & 7);
                const int colb = ks * 32 + ((lane >> 3) & 1) * 16;
                ldsm4(bhf[p], kbase + row * ROWB + colb);
            }
#pragma unroll
            for (int a = 0; a < 4; a++)
#pragma unroll
                for (int n = 0; n < 4; n++) {
                    const int p = n >> 1, q = (n & 1) * 2;
                    mma16816h(C[a][n], ah[a], bhf[p][q], bhf[p][q + 1]);
                }
        }

#pragma unroll
        for (int a = 0; a < 4; a++) {
            float s[4][4];
#pragma unroll
            for (int n = 0; n < 4; n++) {
                const int colt = warp_n * 32 + n * 8 + (lane & 3) * 2;
                const float mk0 = maskS[kt * 128 + colt];
                const float mk1 = maskS[kt * 128 + colt + 1];
                s[n][0] = C[a][n][0] * 0.125f + mk0;
                s[n][1] = C[a][n][1] * 0.125f + mk1;
                s[n][2] = C[a][n][2] * 0.125f + mk0;
                s[n][3] = C[a][n][3] * 0.125f + mk1;
            }
#pragma unroll
            for (int hh = 0; hh < 2; hh++) {
                float cm = s[0][hh * 2];
#pragma unroll
                for (int n = 0; n < 4; n++) {
                    cm = fmaxf(cm, s[n][hh * 2]);
                    cm = fmaxf(cm, s[n][hh * 2 + 1]);
                }
                const int si = a * 2 + hh;
                const float mn = fmaxf(sm_[si], cm);
                float ps = 0.0f;
#pragma unroll
                for (int n = 0; n < 4; n++)
                    ps += __expf(s[n][hh * 2] - mn) + __expf(s[n][hh * 2 + 1] - mn);
                sl_[si] = sl_[si] * __expf(sm_[si] - mn) + ps;
                sm_[si] = mn;
            }
        }

        __syncthreads();
        if (kt + 2 < 16) load_k(kt + 2, kt & 1);
    }

#pragma unroll
    for (int i = 0; i < 8; i++) {
        float m = sm_[i], l = sl_[i];
#pragma unroll
        for (int off = 1; off <= 2; off <<= 1) {
            const float om = __shfl_xor_sync(0xffffffffu, m, off);
            const float ol = __shfl_xor_sync(0xffffffffu, l, off);
            const float mn = fmaxf(m, om);
            l = l * __expf(m - mn) + ol * __expf(om - mn);
            m = mn;
        }
        if ((lane & 3) == 0) {
            const int row = warp_m * 64 + (i >> 1) * 16 + (i & 1) * 8 + (lane >> 2);
            redM[warp_n * 128 + row] = m;
            redL[warp_n * 128 + row] = l;
        }
    }
    __syncthreads();
    if (tid < 128) {
        float m = redM[tid], l = redL[tid];
#pragma unroll
        for (int w = 1; w < 4; w++) {
            const float om = redM[w * 128 + tid];
            const float ol = redL[w * 128 + tid];
            const float mn = fmaxf(m, om);
            l = l * __expf(m - mn) + ol * __expf(om - mn);
            m = mn;
        }
        g_m[(size_t)bh * Sn + grow + tid] = m;
        g_l[(size_t)bh * Sn + grow + tid] = l;
    }
}

// ---------------------------------------------------------------------------
// K2b: fused.  QK^T fp16 3-term; p = exp(s-m)*invl; write final probs;
// P@V fp16 1-term (p-hi x V-hi).
// ---------------------------------------------------------------------------
#define F_KOFF  (2 * T1)
#define F_VOFF  (6 * T1)
#define F_MASK  (8 * T1)                  // 147456
#define F_MROW  (F_MASK + Sn * 4)         // 155648
#define F_LROW  (F_MROW + 512)            // 156160
#define F_SMEM  (F_LROW + 512)            // 156672

__global__ __launch_bounds__(256) void fused_pv(
    const float* __restrict__ mask, float* __restrict__ probs, float* __restrict__ ctx)
{
    extern __shared__ char smem[];
    const uint32_t sb = smem_u32(smem);
    float* maskS = (float*)(smem + F_MASK);
    float* mrow  = (float*)(smem + F_MROW);
    float* lrow  = (float*)(smem + F_LROW);
    const int tid = threadIdx.x;
    const int lane = tid & 31;
    const int wid = tid >> 5;
    const int qt = blockIdx.x;
    const int bh = blockIdx.y;
    const int bidx = bh >> 4;
    const int h    = bh & 15;
    const int q0 = qt * 128;

    const size_t qgb = ((size_t)bh * Sn + q0) * Dn;
#pragma unroll
    for (int i = 0; i < 4; i++) {
        const int idx = tid + 256 * i;
        const int row = idx >> 3, c = idx & 7;
        CP_ASYNC(sb + row * ROWB + c * 16,      g_qfh + qgb + row * Dn + c * 8);
        CP_ASYNC(sb + T1 + row * ROWB + c * 16, g_qfl + qgb + row * Dn + c * 8);
    }

    auto load_kv = [&](int kt, int buf) {
        const size_t gb = ((size_t)bh * Sn + kt * 128) * Dn;
        const uint32_t kb = sb + F_KOFF + buf * 2 * T1;
        const uint32_t vb = sb + F_VOFF + buf * T1;
#pragma unroll
        for (int i = 0; i < 4; i++) {
            const int idx = tid + 256 * i;
            const int row = idx >> 3, c = idx & 7;
            const size_t g = gb + (size_t)row * Dn + c * 8;
            CP_ASYNC(kb + row * ROWB + c * 16,      g_kfh + g);
            CP_ASYNC(kb + T1 + row * ROWB + c * 16, g_kfl + g);
            CP_ASYNC(vb + row * ROWB + c * 16,      g_vf + g);
        }
        CP_COMMIT();
    };

    load_kv(0, 0);
    load_kv(1, 1);

#pragma unroll
    for (int i = 0; i < 2; i++)
        ((float4*)maskS)[tid + 256 * i] = ((const float4*)(mask + (size_t)bidx * Sn))[tid + 256 * i];
    if (tid < 128) {
        const size_t ro = (size_t)bh * Sn + q0 + tid;
        mrow[tid] = g_m[ro];
        lrow[tid] = 1.0f / g_l[ro];
    }

    float O[8][4];
#pragma unroll
    for (int n = 0; n < 8; n++)
#pragma unroll
        for (int j = 0; j < 4; j++) O[n][j] = 0.0f;

    const int rloc0 = wid * 16 + (lane >> 2);
    float mm0, ll0, mm1, ll1;

    for (int kt = 0; kt < 16; kt++) {
        if (kt == 15) { CP_WAIT0(); } else { CP_WAIT1(); }
        __syncthreads();
        if (kt == 0) { mm0 = mrow[rloc0]; ll0 = lrow[rloc0];
                       mm1 = mrow[rloc0 + 8]; ll1 = lrow[rloc0 + 8]; }

        const uint32_t kbase = sb + F_KOFF + (kt & 1) * 2 * T1;
        const uint32_t vbase = sb + F_VOFF + (kt & 1) * T1;

        float C[16][4];
#pragma unroll
        for (int n = 0; n < 16; n++)
#pragma unroll
            for (int j = 0; j < 4; j++) C[n][j] = 0.0f;

#pragma unroll
        for (int ks = 0; ks < 4; ks++) {
            uint32_t qh4[4], ql4[4];
            {
                const int row = wid * 16 + ((lane >> 3) & 1) * 8 + (lane & 7);
                const int colb = ks * 32 + (lane >> 4) * 16;
                ldsm4(qh4, sb + row * ROWB + colb);
                ldsm4(ql4, sb + T1 + row * ROWB + colb);
            }
#pragma unroll
            for (int g = 0; g < 8; g++) {
                uint32_t kh4[4], kl4[4];
                const int row = g * 16 + ((lane >> 4) & 1) * 8 + (lane & 7);
                const int colb = ks * 32 + ((lane >> 3) & 1) * 16;
                ldsm4(kh4, kbase + row * ROWB + colb);
                ldsm4(kl4, kbase + T1 + row * ROWB + colb);
                mma16816h(C[2*g],   qh4, kh4[0], kh4[1]);
                mma16816h(C[2*g],   qh4, kl4[0], kl4[1]);
                mma16816h(C[2*g],   ql4, kh4[0], kh4[1]);
                mma16816h(C[2*g+1], qh4, kh4[2], kh4[3]);
                mma16816h(C[2*g+1], qh4, kl4[2], kl4[3]);
                mma16816h(C[2*g+1], ql4, kh4[2], kh4[3]);
            }
        }

        const size_t prow0 = ((size_t)bh * Sn + q0 + rloc0) * Sn + kt * 128;
        const size_t prow1 = prow0 + (size_t)8 * Sn;
#pragma unroll
        for (int n = 0; n < 16; n++) {
            const int colt = n * 8 + (lane & 3) * 2;
            const float mk0 = maskS[kt * 128 + colt];
            const float mk1 = maskS[kt * 128 + colt + 1];
            const float p00 = __expf(C[n][0] * 0.125f + mk0 - mm0) * ll0;
            const float p01 = __expf(C[n][1] * 0.125f + mk1 - mm0) * ll0;
            const float p10 = __expf(C[n][2] * 0.125f + mk0 - mm1) * ll1;
            const float p11 = __expf(C[n][3] * 0.125f + mk1 - mm1) * ll1;
            C[n][0] = p00; C[n][1] = p01; C[n][2] = p10; C[n][3] = p11;
            *(float2*)&probs[prow0 + colt] = make_float2(p00, p01);
            *(float2*)&probs[prow1 + colt] = make_float2(p10, p11);
        }

        // P@V: fp16 1-term (p-hi x V-hi)
#pragma unroll
        for (int kg = 0; kg < 8; kg++) {
            uint32_t aph[4];
            aph[0] = packh1(C[2*kg][0],   C[2*kg][1]);
            aph[1] = packh1(C[2*kg][2],   C[2*kg][3]);
            aph[2] = packh1(C[2*kg+1][0], C[2*kg+1][1]);
            aph[3] = packh1(C[2*kg+1][2], C[2*kg+1][3]);
            const uint32_t brow = kg * 16 + (lane & 7) + ((lane >> 3) & 1) * 8;
#pragma unroll
            for (int nb = 0; nb < 4; nb++) {
                uint32_t vh4[4];
                ldsm4_t(vh4, vbase + brow * ROWB + nb * 32 + (lane >> 4) * 16);
                mma16816h(O[nb*2],   aph, vh4[0], vh4[1]);
                mma16816h(O[nb*2+1], aph, vh4[2], vh4[3]);
            }
        }

        __syncthreads();
        if (kt + 2 < 16) load_kv(kt + 2, kt & 1);
    }

#pragma unroll
    for (int nb = 0; nb < 8; nb++) {
        const int col = nb * 8 + (lane & 3) * 2;
        const int row = q0 + wid * 16 + (lane >> 2);
        *(float2*)&ctx[((size_t)(bidx * Sn + row)) * HIDn + h * 64 + col] =
            make_float2(O[nb][0], O[nb][1]);
        *(float2*)&ctx[((size_t)(bidx * Sn + row + 8)) * HIDn + h * 64 + col] =
            make_float2(O[nb][2], O[nb][3]);
    }
}

// ---------------------------------------------------------------------------
extern "C" void kernel_launch(void* const* d_in, const int* in_sizes, int n_in,
                              void* d_out, int out_size)
{
    const float* x    = (const float*)d_in[0];
    const float* mask = (const float*)d_in[1];
    const float* Wq   = (const float*)d_in[2];
    const float* bq   = (const float*)d_in[3];
    const float* Wk   = (const float*)d_in[4];
    const float* bk   = (const float*)d_in[5];
    const float* Wv   = (const float*)d_in[6];
    const float* bv   = (const float*)d_in[7];

    float* ctx = (float*)d_out;
    const size_t PROBS_ELEMS = (size_t)BHn * Sn * Sn;
    size_t probs_off = 0;
    if ((size_t)out_size > PROBS_ELEMS) probs_off = (size_t)out_size - PROBS_ELEMS;
    float* probs = (float*)d_out + probs_off;

    cudaFuncSetAttribute(qkv_mma,   cudaFuncAttributeMaxDynamicSharedMemorySize, K1_SMEM);
    cudaFuncSetAttribute(stats_mma, cudaFuncAttributeMaxDynamicSharedMemorySize, K2_SMEM);
    cudaFuncSetAttribute(fused_pv,  cudaFuncAttributeMaxDynamicSharedMemorySize, F_SMEM);

    split_x_kernel<<<Mn * HIDn / 4 / 256, 256>>>((const float4*)x);
    split_w_kernel<<<dim3(HIDn * HIDn / 4 / 256, 3), 256>>>(
        (const float4*)Wq, (const float4*)Wk, (const float4*)Wv);
    qkv_mma<<<dim3(Mn/128, HIDn/128, 3), 256, K1_SMEM>>>(bq, bk, bv);
    stats_mma<<<dim3(Sn/128, BHn), 256, K2_SMEM>>>(mask);
    fused_pv<<<dim3(Sn/128, BHn), 256, F_SMEM>>>(mask, probs, ctx);
}

// round 11
// speedup vs baseline: 2.0243x; 1.1340x over previous
#include <cuda_runtime.h>
#include <cuda_bf16.h>
#include <cuda_fp16.h>
#include <math.h>
#include <stdint.h>

#define Bn   4
#define Sn   2048
#define HIDn 1024
#define NHn  16
#define Dn   64
#define BHn  64
#define Mn   8192

// ---------------- scratch (static device globals; no runtime alloc) --------
__device__ __nv_bfloat16 g_xh[(size_t)Mn * HIDn];
__device__ __nv_bfloat16 g_xl[(size_t)Mn * HIDn];
__device__ __nv_bfloat16 g_wh[(size_t)3 * HIDn * HIDn];
__device__ __nv_bfloat16 g_wl[(size_t)3 * HIDn * HIDn];
__device__ __half g_qfh[(size_t)BHn * Sn * Dn];
__device__ __half g_qfl[(size_t)BHn * Sn * Dn];
__device__ __half g_kfh[(size_t)BHn * Sn * Dn];
__device__ __half g_vf [(size_t)BHn * Sn * Dn];
__device__ float g_m[(size_t)BHn * Sn];
__device__ float g_l[(size_t)BHn * Sn];

// ---------------- PTX helpers (baseline-feature PTX only) -------------------
__device__ __forceinline__ uint32_t smem_u32(const void* p) {
    uint32_t a;
    asm("{ .reg .u64 t; cvta.to.shared.u64 t, %1; cvt.u32.u64 %0, t; }" : "=r"(a) : "l"(p));
    return a;
}
#define CP_ASYNC(dst, src) \
    asm volatile("cp.async.cg.shared.global [%0], [%1], 16;" :: "r"(dst), "l"(src))
#define CP_COMMIT() asm volatile("cp.async.commit_group;")
#define CP_WAIT0()  asm volatile("cp.async.wait_group 0;")
#define CP_WAIT1()  asm volatile("cp.async.wait_group 1;")

__device__ __forceinline__ void ldsm4(uint32_t r[4], uint32_t addr) {
    asm volatile("ldmatrix.sync.aligned.m8n8.x4.shared.b16 {%0,%1,%2,%3}, [%4];"
        : "=r"(r[0]), "=r"(r[1]), "=r"(r[2]), "=r"(r[3]) : "r"(addr));
}
__device__ __forceinline__ void ldsm4_t(uint32_t r[4], uint32_t addr) {
    asm volatile("ldmatrix.sync.aligned.m8n8.x4.trans.shared.b16 {%0,%1,%2,%3}, [%4];"
        : "=r"(r[0]), "=r"(r[1]), "=r"(r[2]), "=r"(r[3]) : "r"(addr));
}
// bf16 mma (qkv projection)
__device__ __forceinline__ void mma16816(float c[4], const uint32_t a[4],
                                         uint32_t b0, uint32_t b1) {
    asm volatile("mma.sync.aligned.m16n8k16.row.col.f32.bf16.bf16.f32 "
        "{%0,%1,%2,%3}, {%4,%5,%6,%7}, {%8,%9}, {%0,%1,%2,%3};"
        : "+f"(c[0]), "+f"(c[1]), "+f"(c[2]), "+f"(c[3])
        : "r"(a[0]), "r"(a[1]), "r"(a[2]), "r"(a[3]), "r"(b0), "r"(b1));
}
// fp16 mma (stats + fused)
__device__ __forceinline__ void mma16816h(float c[4], const uint32_t a[4],
                                          uint32_t b0, uint32_t b1) {
    asm volatile("mma.sync.aligned.m16n8k16.row.col.f32.f16.f16.f32 "
        "{%0,%1,%2,%3}, {%4,%5,%6,%7}, {%8,%9}, {%0,%1,%2,%3};"
        : "+f"(c[0]), "+f"(c[1]), "+f"(c[2]), "+f"(c[3])
        : "r"(a[0]), "r"(a[1]), "r"(a[2]), "r"(a[3]), "r"(b0), "r"(b1));
}

// ---------------- splits ----------------------------------------------------
__device__ __forceinline__ void split1(float v, uint16_t& h, uint16_t& l) {     // bf16
    __nv_bfloat16 hb = __float2bfloat16(v);
    float r = v - __bfloat162float(hb);
    h = __bfloat16_as_ushort(hb);
    l = __bfloat16_as_ushort(__float2bfloat16(r));
}
__device__ __forceinline__ void split_pack(float v0, float v1, uint32_t& ph, uint32_t& pl) {
    uint16_t h0, h1, l0, l1;
    split1(v0, h0, l0); split1(v1, h1, l1);
    ph = ((uint32_t)h1 << 16) | h0;
    pl = ((uint32_t)l1 << 16) | l0;
}
__device__ __forceinline__ void split1h(float v, uint16_t& h, uint16_t& l) {    // fp16
    __half hb = __float2half_rn(v);
    float r = v - __half2float(hb);
    h = __half_as_ushort(hb);
    l = __half_as_ushort(__float2half_rn(r));
}
__device__ __forceinline__ void split_packh(float v0, float v1, uint32_t& ph, uint32_t& pl) {
    uint16_t h0, h1, l0, l1;
    split1h(v0, h0, l0); split1h(v1, h1, l1);
    ph = ((uint32_t)h1 << 16) | h0;
    pl = ((uint32_t)l1 << 16) | l0;
}
__device__ __forceinline__ uint32_t packh1(float v0, float v1) {
    return ((uint32_t)__half_as_ushort(__float2half_rn(v1)) << 16) |
           (uint32_t)__half_as_ushort(__float2half_rn(v0));
}

__global__ __launch_bounds__(256) void split_x_kernel(const float4* __restrict__ src) {
    size_t i = (size_t)blockIdx.x * 256 + threadIdx.x;
    float4 v = src[i];
    uint32_t h01, l01, h23, l23;
    split_pack(v.x, v.y, h01, l01);
    split_pack(v.z, v.w, h23, l23);
    ((uint2*)g_xh)[i] = make_uint2(h01, h23);
    ((uint2*)g_xl)[i] = make_uint2(l01, l23);
}

__global__ __launch_bounds__(256) void split_w_kernel(const float4* __restrict__ Wq,
                                                      const float4* __restrict__ Wk,
                                                      const float4* __restrict__ Wv) {
    const int which = blockIdx.y;
    const float4* W = (which == 0) ? Wq : ((which == 1) ? Wk : Wv);
    size_t i = (size_t)blockIdx.x * 256 + threadIdx.x;
    float4 v = W[i];
    uint32_t h01, l01, h23, l23;
    split_pack(v.x, v.y, h01, l01);
    split_pack(v.z, v.w, h23, l23);
    size_t o = (size_t)which * (HIDn * HIDn / 4) + i;
    ((uint2*)g_wh)[o] = make_uint2(h01, h23);
    ((uint2*)g_wl)[o] = make_uint2(l01, l23);
}

// Tile: 128 rows x 64 elems x 2B (128B data + 16B pad = 144B row stride).
#define ROWB 144
#define T1   (128 * ROWB)     // 18432 B per tile

// ---------------------------------------------------------------------------
// K1: QKV projection (bf16 3-term).  Epilogue writes fp16:
// Q -> g_qfh/g_qfl, K -> g_kfh only (K-lo is dead: consumers use kh alone),
// V -> g_vf.
// ---------------------------------------------------------------------------
#define K1_SMEM (8 * T1)      // 147456 B

__global__ __launch_bounds__(256) void qkv_mma(
    const float* __restrict__ bq, const float* __restrict__ bk, const float* __restrict__ bv)
{
    extern __shared__ char smem[];
    const uint32_t sb = smem_u32(smem);
    const int tid = threadIdx.x;
    const int lane = tid & 31;
    const int wid = tid >> 5;
    const int warp_m = wid & 1;
    const int warp_n = wid >> 1;
    const int which = blockIdx.z;
    const int m0 = blockIdx.x * 128;
    const int n0 = blockIdx.y * 128;
    const float* bias = (which == 0) ? bq : ((which == 1) ? bk : bv);
    const __nv_bfloat16* wh = g_wh + (size_t)which * HIDn * HIDn;
    const __nv_bfloat16* wl = g_wl + (size_t)which * HIDn * HIDn;

    float C[4][4][4];
#pragma unroll
    for (int a = 0; a < 4; a++)
#pragma unroll
        for (int n = 0; n < 4; n++)
#pragma unroll
            for (int j = 0; j < 4; j++) C[a][n][j] = 0.0f;

    auto load_chunk = [&](int chunk, int buf) {
        const int kc = chunk * 64;
        const uint32_t bufb = sb + buf * 4 * T1;
#pragma unroll
        for (int t = 0; t < 4; t++) {
            const __nv_bfloat16* src = (t == 0) ? g_xh : (t == 1) ? g_xl : (t == 2) ? wh : wl;
            const int rbase = (t < 2) ? m0 : n0;
#pragma unroll
            for (int i = 0; i < 4; i++) {
                const int idx = tid + 256 * i;
                const int row = idx >> 3, c = idx & 7;
                CP_ASYNC(bufb + t * T1 + row * ROWB + c * 16,
                         src + (size_t)(rbase + row) * HIDn + kc + c * 8);
            }
        }
        CP_COMMIT();
    };

    auto compute = [&](int buf) {
        const uint32_t base = sb + buf * 4 * T1;
#pragma unroll
        for (int ks = 0; ks < 4; ks++) {
            uint32_t ah[4][4], al[4][4];
#pragma unroll
            for (int a = 0; a < 4; a++) {
                const int row = warp_m * 64 + a * 16 + ((lane >> 3) & 1) * 8 + (lane & 7);
                const int colb = ks * 32 + (lane >> 4) * 16;
                ldsm4(ah[a], base + row * ROWB + colb);
                ldsm4(al[a], base + T1 + row * ROWB + colb);
            }
            uint32_t bh[2][4], bl[2][4];
#pragma unroll
            for (int p = 0; p < 2; p++) {
                const int row = warp_n * 32 + p * 16 + ((lane >> 4) & 1) * 8 + (lane & 7);
                const int colb = ks * 32 + ((lane >> 3) & 1) * 16;
                ldsm4(bh[p], base + 2 * T1 + row * ROWB + colb);
                ldsm4(bl[p], base + 3 * T1 + row * ROWB + colb);
            }
#pragma unroll
            for (int a = 0; a < 4; a++)
#pragma unroll
                for (int n = 0; n < 4; n++) {
                    const int p = n >> 1, q = (n & 1) * 2;
                    mma16816(C[a][n], ah[a], bh[p][q], bh[p][q + 1]);
                    mma16816(C[a][n], ah[a], bl[p][q], bl[p][q + 1]);
                    mma16816(C[a][n], al[a], bh[p][q], bh[p][q + 1]);
                }
        }
    };

    load_chunk(0, 0);
    load_chunk(1, 1);
    for (int kt = 0; kt < 16; kt++) {
        if (kt == 15) { CP_WAIT0(); } else { CP_WAIT1(); }
        __syncthreads();
        compute(kt & 1);
        __syncthreads();
        if (kt + 2 < 16) load_chunk(kt + 2, kt & 1);
    }

    // epilogue: bias + fp16 split + scatter to [bh][s][d]
#pragma unroll
    for (int a = 0; a < 4; a++)
#pragma unroll
        for (int n = 0; n < 4; n++) {
            const int row0 = m0 + warp_m * 64 + a * 16 + (lane >> 2);
            const int col  = n0 + warp_n * 32 + n * 8 + (lane & 3) * 2;
            const float bb0 = bias[col], bb1 = bias[col + 1];
            const int hd = col >> 6, d = col & 63;
#pragma unroll
            for (int h = 0; h < 2; h++) {
                const int row = row0 + h * 8;
                const float v0 = C[a][n][h * 2 + 0] + bb0;
                const float v1 = C[a][n][h * 2 + 1] + bb1;
                const int bidx = row >> 11, s = row & (Sn - 1);
                const size_t oi = ((size_t)(bidx * NHn + hd) * Sn + s) * Dn + d;
                if (which == 2) {
                    *(uint32_t*)&g_vf[oi] = packh1(v0, v1);
                } else if (which == 1) {
                    *(uint32_t*)&g_kfh[oi] = packh1(v0, v1);   // k: hi only
                } else {
                    uint32_t ph, pl;
                    split_packh(v0, v1, ph, pl);
                    *(uint32_t*)&g_qfh[oi] = ph;
                    *(uint32_t*)&g_qfl[oi] = pl;
                }
            }
        }
}

// ---------------------------------------------------------------------------
// K2a: softmax stats only.  fp16 1-term: Qh x Kh.
// smem: Qh | Khbuf0 | Khbuf1 | mask | red = 67584 B  -> 2 CTAs/SM (forced).
// ---------------------------------------------------------------------------
#define K2_MASKOFF (3 * T1)                    // 55296
#define K2_REDM    (K2_MASKOFF + Sn * 4)       // 63488
#define K2_REDL    (K2_REDM + 4 * 128 * 4)     // 65536
#define K2_SMEM    (K2_REDL + 4 * 128 * 4)     // 67584

__global__ __launch_bounds__(256, 2) void stats_mma(const float* __restrict__ mask)
{
    extern __shared__ char smem[];
    const uint32_t sb = smem_u32(smem);
    float* maskS = (float*)(smem + K2_MASKOFF);
    float* redM  = (float*)(smem + K2_REDM);
    float* redL  = (float*)(smem + K2_REDL);
    const int tid = threadIdx.x;
    const int lane = tid & 31;
    const int wid = tid >> 5;
    const int warp_m = wid & 1;
    const int warp_n = wid >> 1;
    const int qt = blockIdx.x;
    const int bh = blockIdx.y;
    const int bidx = bh >> 4;
    const int grow = qt * 128;

    const size_t qgb = ((size_t)bh * Sn + grow) * Dn;
#pragma unroll
    for (int i = 0; i < 4; i++) {
        const int idx = tid + 256 * i;
        const int row = idx >> 3, c = idx & 7;
        CP_ASYNC(sb + row * ROWB + c * 16, g_qfh + qgb + row * Dn + c * 8);
    }
#pragma unroll
    for (int i = 0; i < 2; i++)
        ((float4*)maskS)[tid + 256 * i] = ((const float4*)(mask + (size_t)bidx * Sn))[tid + 256 * i];

    auto load_k = [&](int kt, int buf) {
        const size_t kgb = ((size_t)bh * Sn + kt * 128) * Dn;
        const uint32_t bufb = sb + T1 + buf * T1;
#pragma unroll
        for (int i = 0; i < 4; i++) {
            const int idx = tid + 256 * i;
            const int row = idx >> 3, c = idx & 7;
            CP_ASYNC(bufb + row * ROWB + c * 16, g_kfh + kgb + row * Dn + c * 8);
        }
        CP_COMMIT();
    };

    load_k(0, 0);
    load_k(1, 1);

    float sm_[8], sl_[8];
#pragma unroll
    for (int i = 0; i < 8; i++) { sm_[i] = -1e30f; sl_[i] = 0.0f; }

    for (int kt = 0; kt < 16; kt++) {
        if (kt == 15) { CP_WAIT0(); } else { CP_WAIT1(); }
        __syncthreads();

        const uint32_t kbase = sb + T1 + (kt & 1) * T1;
        float C[4][4][4];
#pragma unroll
        for (int a = 0; a < 4; a++)
#pragma unroll
            for (int n = 0; n < 4; n++)
#pragma unroll
                for (int j = 0; j < 4; j++) C[a][n][j] = 0.0f;

#pragma unroll
        for (int ks = 0; ks < 4; ks++) {
            uint32_t ah[4][4];
#pragma unroll
            for (int a = 0; a < 4; a++) {
                const int row = warp_m * 64 + a * 16 + ((lane >> 3) & 1) * 8 + (lane & 7);
                const int colb = ks * 32 + (lane >> 4) * 16;
                ldsm4(ah[a], sb + row * ROWB + colb);
            }
            uint32_t bhf[2][4];
#pragma unroll
            for (int p = 0; p < 2; p++) {
                const int row = warp_n * 32 + p * 16 + ((lane >> 4) & 1) * 8 + (lane & 7);
                const int colb = ks * 32 + ((lane >> 3) & 1) * 16;
                ldsm4(bhf[p], kbase + row * ROWB + colb);
            }
#pragma unroll
            for (int a = 0; a < 4; a++)
#pragma unroll
                for (int n = 0; n < 4; n++) {
                    const int p = n >> 1, q = (n & 1) * 2;
                    mma16816h(C[a][n], ah[a], bhf[p][q], bhf[p][q + 1]);
                }
        }

#pragma unroll
        for (int a = 0; a < 4; a++) {
            float s[4][4];
#pragma unroll
            for (int n = 0; n < 4; n++) {
                const int colt = warp_n * 32 + n * 8 + (lane & 3) * 2;
                const float mk0 = maskS[kt * 128 + colt];
                const float mk1 = maskS[kt * 128 + colt + 1];
                s[n][0] = C[a][n][0] * 0.125f + mk0;
                s[n][1] = C[a][n][1] * 0.125f + mk1;
                s[n][2] = C[a][n][2] * 0.125f + mk0;
                s[n][3] = C[a][n][3] * 0.125f + mk1;
            }
#pragma unroll
            for (int hh = 0; hh < 2; hh++) {
                float cm = s[0][hh * 2];
#pragma unroll
                for (int n = 0; n < 4; n++) {
                    cm = fmaxf(cm, s[n][hh * 2]);
                    cm = fmaxf(cm, s[n][hh * 2 + 1]);
                }
                const int si = a * 2 + hh;
                const float mn = fmaxf(sm_[si], cm);
                float ps = 0.0f;
#pragma unroll
                for (int n = 0; n < 4; n++)
                    ps += __expf(s[n][hh * 2] - mn) + __expf(s[n][hh * 2 + 1] - mn);
                sl_[si] = sl_[si] * __expf(sm_[si] - mn) + ps;
                sm_[si] = mn;
            }
        }

        __syncthreads();
        if (kt + 2 < 16) load_k(kt + 2, kt & 1);
    }

#pragma unroll
    for (int i = 0; i < 8; i++) {
        float m = sm_[i], l = sl_[i];
#pragma unroll
        for (int off = 1; off <= 2; off <<= 1) {
            const float om = __shfl_xor_sync(0xffffffffu, m, off);
            const float ol = __shfl_xor_sync(0xffffffffu, l, off);
            const float mn = fmaxf(m, om);
            l = l * __expf(m - mn) + ol * __expf(om - mn);
            m = mn;
        }
        if ((lane & 3) == 0) {
            const int row = warp_m * 64 + (i >> 1) * 16 + (i & 1) * 8 + (lane >> 2);
            redM[warp_n * 128 + row] = m;
            redL[warp_n * 128 + row] = l;
        }
    }
    __syncthreads();
    if (tid < 128) {
        float m = redM[tid], l = redL[tid];
#pragma unroll
        for (int w = 1; w < 4; w++) {
            const float om = redM[w * 128 + tid];
            const float ol = redL[w * 128 + tid];
            const float mn = fmaxf(m, om);
            l = l * __expf(m - mn) + ol * __expf(om - mn);
            m = mn;
        }
        g_m[(size_t)bh * Sn + grow + tid] = m;
        g_l[(size_t)bh * Sn + grow + tid] = l;
    }
}

// ---------------------------------------------------------------------------
// K2b: fused.  QK^T fp16 2-term (qh·kh + ql·kh); p = exp(s-m)*invl; write
// final probs; P@V fp16 1-term (p-hi x V-hi).
// smem: Qh | Ql | Kh0 | Kh1 | V0 | V1 | mask | m | invl = 119808 B
// ---------------------------------------------------------------------------
#define F_KOFF  (2 * T1)
#define F_VOFF  (4 * T1)
#define F_MASK  (6 * T1)                  // 110592
#define F_MROW  (F_MASK + Sn * 4)         // 118784
#define F_LROW  (F_MROW + 512)            // 119296
#define F_SMEM  (F_LROW + 512)            // 119808

__global__ __launch_bounds__(256) void fused_pv(
    const float* __restrict__ mask, float* __restrict__ probs, float* __restrict__ ctx)
{
    extern __shared__ char smem[];
    const uint32_t sb = smem_u32(smem);
    float* maskS = (float*)(smem + F_MASK);
    float* mrow  = (float*)(smem + F_MROW);
    float* lrow  = (float*)(smem + F_LROW);
    const int tid = threadIdx.x;
    const int lane = tid & 31;
    const int wid = tid >> 5;
    const int qt = blockIdx.x;
    const int bh = blockIdx.y;
    const int bidx = bh >> 4;
    const int h    = bh & 15;
    const int q0 = qt * 128;

    const size_t qgb = ((size_t)bh * Sn + q0) * Dn;
#pragma unroll
    for (int i = 0; i < 4; i++) {
        const int idx = tid + 256 * i;
        const int row = idx >> 3, c = idx & 7;
        CP_ASYNC(sb + row * ROWB + c * 16,      g_qfh + qgb + row * Dn + c * 8);
        CP_ASYNC(sb + T1 + row * ROWB + c * 16, g_qfl + qgb + row * Dn + c * 8);
    }

    auto load_kv = [&](int kt, int buf) {
        const size_t gb = ((size_t)bh * Sn + kt * 128) * Dn;
        const uint32_t kb = sb + F_KOFF + buf * T1;
        const uint32_t vb = sb + F_VOFF + buf * T1;
#pragma unroll
        for (int i = 0; i < 4; i++) {
            const int idx = tid + 256 * i;
            const int row = idx >> 3, c = idx & 7;
            const size_t g = gb + (size_t)row * Dn + c * 8;
            CP_ASYNC(kb + row * ROWB + c * 16, g_kfh + g);
            CP_ASYNC(vb + row * ROWB + c * 16, g_vf + g);
        }
        CP_COMMIT();
    };

    load_kv(0, 0);
    load_kv(1, 1);

#pragma unroll
    for (int i = 0; i < 2; i++)
        ((float4*)maskS)[tid + 256 * i] = ((const float4*)(mask + (size_t)bidx * Sn))[tid + 256 * i];
    if (tid < 128) {
        const size_t ro = (size_t)bh * Sn + q0 + tid;
        mrow[tid] = g_m[ro];
        lrow[tid] = 1.0f / g_l[ro];
    }

    float O[8][4];
#pragma unroll
    for (int n = 0; n < 8; n++)
#pragma unroll
        for (int j = 0; j < 4; j++) O[n][j] = 0.0f;

    const int rloc0 = wid * 16 + (lane >> 2);
    float mm0, ll0, mm1, ll1;

    for (int kt = 0; kt < 16; kt++) {
        if (kt == 15) { CP_WAIT0(); } else { CP_WAIT1(); }
        __syncthreads();
        if (kt == 0) { mm0 = mrow[rloc0]; ll0 = lrow[rloc0];
                       mm1 = mrow[rloc0 + 8]; ll1 = lrow[rloc0 + 8]; }

        const uint32_t kbase = sb + F_KOFF + (kt & 1) * T1;
        const uint32_t vbase = sb + F_VOFF + (kt & 1) * T1;

        float C[16][4];
#pragma unroll
        for (int n = 0; n < 16; n++)
#pragma unroll
            for (int j = 0; j < 4; j++) C[n][j] = 0.0f;

#pragma unroll
        for (int ks = 0; ks < 4; ks++) {
            uint32_t qh4[4], ql4[4];
            {
                const int row = wid * 16 + ((lane >> 3) & 1) * 8 + (lane & 7);
                const int colb = ks * 32 + (lane >> 4) * 16;
                ldsm4(qh4, sb + row * ROWB + colb);
                ldsm4(ql4, sb + T1 + row * ROWB + colb);
            }
#pragma unroll
            for (int g = 0; g < 8; g++) {
                uint32_t kh4[4];
                const int row = g * 16 + ((lane >> 4) & 1) * 8 + (lane & 7);
                const int colb = ks * 32 + ((lane >> 3) & 1) * 16;
                ldsm4(kh4, kbase + row * ROWB + colb);
                mma16816h(C[2*g],   qh4, kh4[0], kh4[1]);
                mma16816h(C[2*g],   ql4, kh4[0], kh4[1]);
                mma16816h(C[2*g+1], qh4, kh4[2], kh4[3]);
                mma16816h(C[2*g+1], ql4, kh4[2], kh4[3]);
            }
        }

        const size_t prow0 = ((size_t)bh * Sn + q0 + rloc0) * Sn + kt * 128;
        const size_t prow1 = prow0 + (size_t)8 * Sn;
#pragma unroll
        for (int n = 0; n < 16; n++) {
            const int colt = n * 8 + (lane & 3) * 2;
            const float mk0 = maskS[kt * 128 + colt];
            const float mk1 = maskS[kt * 128 + colt + 1];
            const float p00 = __expf(C[n][0] * 0.125f + mk0 - mm0) * ll0;
            const float p01 = __expf(C[n][1] * 0.125f + mk1 - mm0) * ll0;
            const float p10 = __expf(C[n][2] * 0.125f + mk0 - mm1) * ll1;
            const float p11 = __expf(C[n][3] * 0.125f + mk1 - mm1) * ll1;
            C[n][0] = p00; C[n][1] = p01; C[n][2] = p10; C[n][3] = p11;
            *(float2*)&probs[prow0 + colt] = make_float2(p00, p01);
            *(float2*)&probs[prow1 + colt] = make_float2(p10, p11);
        }

        // P@V: fp16 1-term (p-hi x V-hi)
#pragma unroll
        for (int kg = 0; kg < 8; kg++) {
            uint32_t aph[4];
            aph[0] = packh1(C[2*kg][0],   C[2*kg][1]);
            aph[1] = packh1(C[2*kg][2],   C[2*kg][3]);
            aph[2] = packh1(C[2*kg+1][0], C[2*kg+1][1]);
            aph[3] = packh1(C[2*kg+1][2], C[2*kg+1][3]);
            const uint32_t brow = kg * 16 + (lane & 7) + ((lane >> 3) & 1) * 8;
#pragma unroll
            for (int nb = 0; nb < 4; nb++) {
                uint32_t vh4[4];
                ldsm4_t(vh4, vbase + brow * ROWB + nb * 32 + (lane >> 4) * 16);
                mma16816h(O[nb*2],   aph, vh4[0], vh4[1]);
                mma16816h(O[nb*2+1], aph, vh4[2], vh4[3]);
            }
        }

        __syncthreads();
        if (kt + 2 < 16) load_kv(kt + 2, kt & 1);
    }

#pragma unroll
    for (int nb = 0; nb < 8; nb++) {
        const int col = nb * 8 + (lane & 3) * 2;
        const int row = q0 + wid * 16 + (lane >> 2);
        *(float2*)&ctx[((size_t)(bidx * Sn + row)) * HIDn + h * 64 + col] =
            make_float2(O[nb][0], O[nb][1]);
        *(float2*)&ctx[((size_t)(bidx * Sn + row + 8)) * HIDn + h * 64 + col] =
            make_float2(O[nb][2], O[nb][3]);
    }
}

// ---------------------------------------------------------------------------
extern "C" void kernel_launch(void* const* d_in, const int* in_sizes, int n_in,
                              void* d_out, int out_size)
{
    const float* x    = (const float*)d_in[0];
    const float* mask = (const float*)d_in[1];
    const float* Wq   = (const float*)d_in[2];
    const float* bq   = (const float*)d_in[3];
    const float* Wk   = (const float*)d_in[4];
    const float* bk   = (const float*)d_in[5];
    const float* Wv   = (const float*)d_in[6];
    const float* bv   = (const float*)d_in[7];

    float* ctx = (float*)d_out;
    const size_t PROBS_ELEMS = (size_t)BHn * Sn * Sn;
    size_t probs_off = 0;
    if ((size_t)out_size > PROBS_ELEMS) probs_off = (size_t)out_size - PROBS_ELEMS;
    float* probs = (float*)d_out + probs_off;

    cudaFuncSetAttribute(qkv_mma,   cudaFuncAttributeMaxDynamicSharedMemorySize, K1_SMEM);
    cudaFuncSetAttribute(stats_mma, cudaFuncAttributeMaxDynamicSharedMemorySize, K2_SMEM);
    cudaFuncSetAttribute(fused_pv,  cudaFuncAttributeMaxDynamicSharedMemorySize, F_SMEM);

    split_x_kernel<<<Mn * HIDn / 4 / 256, 256>>>((const float4*)x);
    split_w_kernel<<<dim3(HIDn * HIDn / 4 / 256, 3), 256>>>(
        (const float4*)Wq, (const float4*)Wk, (const float4*)Wv);
    qkv_mma<<<dim3(Mn/128, HIDn/128, 3), 256, K1_SMEM>>>(bq, bk, bv);
    stats_mma<<<dim3(Sn/128, BHn), 256, K2_SMEM>>>(mask);
    fused_pv<<<dim3(Sn/128, BHn), 256, F_SMEM>>>(mask, probs, ctx);
}

// round 12
// speedup vs baseline: 2.2545x; 1.1137x over previous
#include <cuda_runtime.h>
#include <cuda_bf16.h>
#include <cuda_fp16.h>
#include <math.h>
#include <stdint.h>

#define Bn   4
#define Sn   2048
#define HIDn 1024
#define NHn  16
#define Dn   64
#define BHn  64
#define Mn   8192

// ---------------- scratch (static device globals; no runtime alloc) --------
__device__ __nv_bfloat16 g_xh[(size_t)Mn * HIDn];     // bf16 splits (Q path)
__device__ __nv_bfloat16 g_xl[(size_t)Mn * HIDn];
__device__ __half        g_xfh[(size_t)Mn * HIDn];    // fp16 splits (K/V path)
__device__ __half        g_xfl[(size_t)Mn * HIDn];
__device__ __nv_bfloat16 g_wh[(size_t)HIDn * HIDn];   // Wq bf16 hi/lo
__device__ __nv_bfloat16 g_wl[(size_t)HIDn * HIDn];
__device__ __half        g_wfh[(size_t)2 * HIDn * HIDn]; // Wk, Wv fp16 hi
__device__ __half g_qfh[(size_t)BHn * Sn * Dn];
__device__ __half g_qfl[(size_t)BHn * Sn * Dn];
__device__ __half g_kfh[(size_t)BHn * Sn * Dn];
__device__ __half g_vf [(size_t)BHn * Sn * Dn];
__device__ float g_m[(size_t)BHn * Sn];
__device__ float g_l[(size_t)BHn * Sn];

// ---------------- PTX helpers (baseline-feature PTX only) -------------------
__device__ __forceinline__ uint32_t smem_u32(const void* p) {
    uint32_t a;
    asm("{ .reg .u64 t; cvta.to.shared.u64 t, %1; cvt.u32.u64 %0, t; }" : "=r"(a) : "l"(p));
    return a;
}
#define CP_ASYNC(dst, src) \
    asm volatile("cp.async.cg.shared.global [%0], [%1], 16;" :: "r"(dst), "l"(src))
#define CP_COMMIT() asm volatile("cp.async.commit_group;")
#define CP_WAIT0()  asm volatile("cp.async.wait_group 0;")
#define CP_WAIT1()  asm volatile("cp.async.wait_group 1;")

__device__ __forceinline__ void ldsm4(uint32_t r[4], uint32_t addr) {
    asm volatile("ldmatrix.sync.aligned.m8n8.x4.shared.b16 {%0,%1,%2,%3}, [%4];"
        : "=r"(r[0]), "=r"(r[1]), "=r"(r[2]), "=r"(r[3]) : "r"(addr));
}
__device__ __forceinline__ void ldsm4_t(uint32_t r[4], uint32_t addr) {
    asm volatile("ldmatrix.sync.aligned.m8n8.x4.trans.shared.b16 {%0,%1,%2,%3}, [%4];"
        : "=r"(r[0]), "=r"(r[1]), "=r"(r[2]), "=r"(r[3]) : "r"(addr));
}
// bf16 mma (Q projection)
__device__ __forceinline__ void mma16816(float c[4], const uint32_t a[4],
                                         uint32_t b0, uint32_t b1) {
    asm volatile("mma.sync.aligned.m16n8k16.row.col.f32.bf16.bf16.f32 "
        "{%0,%1,%2,%3}, {%4,%5,%6,%7}, {%8,%9}, {%0,%1,%2,%3};"
        : "+f"(c[0]), "+f"(c[1]), "+f"(c[2]), "+f"(c[3])
        : "r"(a[0]), "r"(a[1]), "r"(a[2]), "r"(a[3]), "r"(b0), "r"(b1));
}
// fp16 mma (K/V projection, stats, fused)
__device__ __forceinline__ void mma16816h(float c[4], const uint32_t a[4],
                                          uint32_t b0, uint32_t b1) {
    asm volatile("mma.sync.aligned.m16n8k16.row.col.f32.f16.f16.f32 "
        "{%0,%1,%2,%3}, {%4,%5,%6,%7}, {%8,%9}, {%0,%1,%2,%3};"
        : "+f"(c[0]), "+f"(c[1]), "+f"(c[2]), "+f"(c[3])
        : "r"(a[0]), "r"(a[1]), "r"(a[2]), "r"(a[3]), "r"(b0), "r"(b1));
}

// ---------------- splits ----------------------------------------------------
__device__ __forceinline__ void split1(float v, uint16_t& h, uint16_t& l) {     // bf16
    __nv_bfloat16 hb = __float2bfloat16(v);
    float r = v - __bfloat162float(hb);
    h = __bfloat16_as_ushort(hb);
    l = __bfloat16_as_ushort(__float2bfloat16(r));
}
__device__ __forceinline__ void split_pack(float v0, float v1, uint32_t& ph, uint32_t& pl) {
    uint16_t h0, h1, l0, l1;
    split1(v0, h0, l0); split1(v1, h1, l1);
    ph = ((uint32_t)h1 << 16) | h0;
    pl = ((uint32_t)l1 << 16) | l0;
}
__device__ __forceinline__ void split1h(float v, uint16_t& h, uint16_t& l) {    // fp16
    __half hb = __float2half_rn(v);
    float r = v - __half2float(hb);
    h = __half_as_ushort(hb);
    l = __half_as_ushort(__float2half_rn(r));
}
__device__ __forceinline__ void split_packh(float v0, float v1, uint32_t& ph, uint32_t& pl) {
    uint16_t h0, h1, l0, l1;
    split1h(v0, h0, l0); split1h(v1, h1, l1);
    ph = ((uint32_t)h1 << 16) | h0;
    pl = ((uint32_t)l1 << 16) | l0;
}
__device__ __forceinline__ uint32_t packh1(float v0, float v1) {
    return ((uint32_t)__half_as_ushort(__float2half_rn(v1)) << 16) |
           (uint32_t)__half_as_ushort(__float2half_rn(v0));
}

__global__ __launch_bounds__(256) void split_x_kernel(const float4* __restrict__ src) {
    size_t i = (size_t)blockIdx.x * 256 + threadIdx.x;
    float4 v = src[i];
    uint32_t h01, l01, h23, l23;
    split_pack(v.x, v.y, h01, l01);
    split_pack(v.z, v.w, h23, l23);
    ((uint2*)g_xh)[i] = make_uint2(h01, h23);
    ((uint2*)g_xl)[i] = make_uint2(l01, l23);
    uint32_t fh01, fl01, fh23, fl23;
    split_packh(v.x, v.y, fh01, fl01);
    split_packh(v.z, v.w, fh23, fl23);
    ((uint2*)g_xfh)[i] = make_uint2(fh01, fh23);
    ((uint2*)g_xfl)[i] = make_uint2(fl01, fl23);
}

__global__ __launch_bounds__(256) void split_w_kernel(const float4* __restrict__ Wq,
                                                      const float4* __restrict__ Wk,
                                                      const float4* __restrict__ Wv) {
    const int which = blockIdx.y;
    size_t i = (size_t)blockIdx.x * 256 + threadIdx.x;
    if (which == 0) {
        float4 v = Wq[i];
        uint32_t h01, l01, h23, l23;
        split_pack(v.x, v.y, h01, l01);
        split_pack(v.z, v.w, h23, l23);
        ((uint2*)g_wh)[i] = make_uint2(h01, h23);
        ((uint2*)g_wl)[i] = make_uint2(l01, l23);
    } else {
        float4 v = (which == 1) ? Wk[i] : Wv[i];
        size_t o = (size_t)(which - 1) * (HIDn * HIDn / 4) + i;
        ((uint2*)g_wfh)[o] = make_uint2(packh1(v.x, v.y), packh1(v.z, v.w));
    }
}

// Tile: 128 rows x 64 elems x 2B (128B data + 16B pad = 144B row stride).
#define ROWB 144
#define T1   (128 * ROWB)     // 18432 B per tile

// ---------------------------------------------------------------------------
// K1a: Q projection (bf16 3-term).  Writes fp16 hi/lo to g_qfh/g_qfl.
// ---------------------------------------------------------------------------
#define K1_SMEM (8 * T1)      // 147456 B

__global__ __launch_bounds__(256) void qkv_q(const float* __restrict__ bq)
{
    extern __shared__ char smem[];
    const uint32_t sb = smem_u32(smem);
    const int tid = threadIdx.x;
    const int lane = tid & 31;
    const int wid = tid >> 5;
    const int warp_m = wid & 1;
    const int warp_n = wid >> 1;
    const int m0 = blockIdx.x * 128;
    const int n0 = blockIdx.y * 128;

    float C[4][4][4];
#pragma unroll
    for (int a = 0; a < 4; a++)
#pragma unroll
        for (int n = 0; n < 4; n++)
#pragma unroll
            for (int j = 0; j < 4; j++) C[a][n][j] = 0.0f;

    auto load_chunk = [&](int chunk, int buf) {
        const int kc = chunk * 64;
        const uint32_t bufb = sb + buf * 4 * T1;
#pragma unroll
        for (int t = 0; t < 4; t++) {
            const __nv_bfloat16* src = (t == 0) ? g_xh : (t == 1) ? g_xl : (t == 2) ? g_wh : g_wl;
            const int rbase = (t < 2) ? m0 : n0;
#pragma unroll
            for (int i = 0; i < 4; i++) {
                const int idx = tid + 256 * i;
                const int row = idx >> 3, c = idx & 7;
                CP_ASYNC(bufb + t * T1 + row * ROWB + c * 16,
                         src + (size_t)(rbase + row) * HIDn + kc + c * 8);
            }
        }
        CP_COMMIT();
    };

    auto compute = [&](int buf) {
        const uint32_t base = sb + buf * 4 * T1;
#pragma unroll
        for (int ks = 0; ks < 4; ks++) {
            uint32_t ah[4][4], al[4][4];
#pragma unroll
            for (int a = 0; a < 4; a++) {
                const int row = warp_m * 64 + a * 16 + ((lane >> 3) & 1) * 8 + (lane & 7);
                const int colb = ks * 32 + (lane >> 4) * 16;
                ldsm4(ah[a], base + row * ROWB + colb);
                ldsm4(al[a], base + T1 + row * ROWB + colb);
            }
            uint32_t bh[2][4], bl[2][4];
#pragma unroll
            for (int p = 0; p < 2; p++) {
                const int row = warp_n * 32 + p * 16 + ((lane >> 4) & 1) * 8 + (lane & 7);
                const int colb = ks * 32 + ((lane >> 3) & 1) * 16;
                ldsm4(bh[p], base + 2 * T1 + row * ROWB + colb);
                ldsm4(bl[p], base + 3 * T1 + row * ROWB + colb);
            }
#pragma unroll
            for (int a = 0; a < 4; a++)
#pragma unroll
                for (int n = 0; n < 4; n++) {
                    const int p = n >> 1, q = (n & 1) * 2;
                    mma16816(C[a][n], ah[a], bh[p][q], bh[p][q + 1]);
                    mma16816(C[a][n], ah[a], bl[p][q], bl[p][q + 1]);
                    mma16816(C[a][n], al[a], bh[p][q], bh[p][q + 1]);
                }
        }
    };

    load_chunk(0, 0);
    load_chunk(1, 1);
    for (int kt = 0; kt < 16; kt++) {
        if (kt == 15) { CP_WAIT0(); } else { CP_WAIT1(); }
        __syncthreads();
        compute(kt & 1);
        __syncthreads();
        if (kt + 2 < 16) load_chunk(kt + 2, kt & 1);
    }

#pragma unroll
    for (int a = 0; a < 4; a++)
#pragma unroll
        for (int n = 0; n < 4; n++) {
            const int row0 = m0 + warp_m * 64 + a * 16 + (lane >> 2);
            const int col  = n0 + warp_n * 32 + n * 8 + (lane & 3) * 2;
            const float bb0 = bq[col], bb1 = bq[col + 1];
            const int hd = col >> 6, d = col & 63;
#pragma unroll
            for (int h = 0; h < 2; h++) {
                const int row = row0 + h * 8;
                const float v0 = C[a][n][h * 2 + 0] + bb0;
                const float v1 = C[a][n][h * 2 + 1] + bb1;
                const int bidx = row >> 11, s = row & (Sn - 1);
                const size_t oi = ((size_t)(bidx * NHn + hd) * Sn + s) * Dn + d;
                uint32_t ph, pl;
                split_packh(v0, v1, ph, pl);
                *(uint32_t*)&g_qfh[oi] = ph;
                *(uint32_t*)&g_qfl[oi] = pl;
            }
        }
}

// ---------------------------------------------------------------------------
// K1b: K/V projection (fp16 2-term: (xfh + xfl) x wfh).  grid.z: 0=K, 1=V.
// smem: 2 buffers x 3 tiles = 110592 B.
// ---------------------------------------------------------------------------
#define KV_SMEM (6 * T1)      // 110592 B

__global__ __launch_bounds__(256) void qkv_kv(
    const float* __restrict__ bk, const float* __restrict__ bv)
{
    extern __shared__ char smem[];
    const uint32_t sb = smem_u32(smem);
    const int tid = threadIdx.x;
    const int lane = tid & 31;
    const int wid = tid >> 5;
    const int warp_m = wid & 1;
    const int warp_n = wid >> 1;
    const int which = blockIdx.z;                 // 0=K, 1=V
    const int m0 = blockIdx.x * 128;
    const int n0 = blockIdx.y * 128;
    const float* bias = (which == 0) ? bk : bv;
    const __half* wf = g_wfh + (size_t)which * HIDn * HIDn;

    float C[4][4][4];
#pragma unroll
    for (int a = 0; a < 4; a++)
#pragma unroll
        for (int n = 0; n < 4; n++)
#pragma unroll
            for (int j = 0; j < 4; j++) C[a][n][j] = 0.0f;

    auto load_chunk = [&](int chunk, int buf) {
        const int kc = chunk * 64;
        const uint32_t bufb = sb + buf * 3 * T1;
#pragma unroll
        for (int t = 0; t < 3; t++) {
            const __half* src = (t == 0) ? g_xfh : (t == 1) ? g_xfl : wf;
            const int rbase = (t < 2) ? m0 : n0;
#pragma unroll
            for (int i = 0; i < 4; i++) {
                const int idx = tid + 256 * i;
                const int row = idx >> 3, c = idx & 7;
                CP_ASYNC(bufb + t * T1 + row * ROWB + c * 16,
                         src + (size_t)(rbase + row) * HIDn + kc + c * 8);
            }
        }
        CP_COMMIT();
    };

    auto compute = [&](int buf) {
        const uint32_t base = sb + buf * 3 * T1;
#pragma unroll
        for (int ks = 0; ks < 4; ks++) {
            uint32_t ah[4][4], al[4][4];
#pragma unroll
            for (int a = 0; a < 4; a++) {
                const int row = warp_m * 64 + a * 16 + ((lane >> 3) & 1) * 8 + (lane & 7);
                const int colb = ks * 32 + (lane >> 4) * 16;
                ldsm4(ah[a], base + row * ROWB + colb);
                ldsm4(al[a], base + T1 + row * ROWB + colb);
            }
            uint32_t bh[2][4];
#pragma unroll
            for (int p = 0; p < 2; p++) {
                const int row = warp_n * 32 + p * 16 + ((lane >> 4) & 1) * 8 + (lane & 7);
                const int colb = ks * 32 + ((lane >> 3) & 1) * 16;
                ldsm4(bh[p], base + 2 * T1 + row * ROWB + colb);
            }
#pragma unroll
            for (int a = 0; a < 4; a++)
#pragma unroll
                for (int n = 0; n < 4; n++) {
                    const int p = n >> 1, q = (n & 1) * 2;
                    mma16816h(C[a][n], ah[a], bh[p][q], bh[p][q + 1]);
                    mma16816h(C[a][n], al[a], bh[p][q], bh[p][q + 1]);
                }
        }
    };

    load_chunk(0, 0);
    load_chunk(1, 1);
    for (int kt = 0; kt < 16; kt++) {
        if (kt == 15) { CP_WAIT0(); } else { CP_WAIT1(); }
        __syncthreads();
        compute(kt & 1);
        __syncthreads();
        if (kt + 2 < 16) load_chunk(kt + 2, kt & 1);
    }

    __half* out = (which == 0) ? g_kfh : g_vf;
#pragma unroll
    for (int a = 0; a < 4; a++)
#pragma unroll
        for (int n = 0; n < 4; n++) {
            const int row0 = m0 + warp_m * 64 + a * 16 + (lane >> 2);
            const int col  = n0 + warp_n * 32 + n * 8 + (lane & 3) * 2;
            const float bb0 = bias[col], bb1 = bias[col + 1];
            const int hd = col >> 6, d = col & 63;
#pragma unroll
            for (int h = 0; h < 2; h++) {
                const int row = row0 + h * 8;
                const float v0 = C[a][n][h * 2 + 0] + bb0;
                const float v1 = C[a][n][h * 2 + 1] + bb1;
                const int bidx = row >> 11, s = row & (Sn - 1);
                const size_t oi = ((size_t)(bidx * NHn + hd) * Sn + s) * Dn + d;
                *(uint32_t*)&out[oi] = packh1(v0, v1);
            }
        }
}

// ---------------------------------------------------------------------------
// K2a: softmax stats only.  fp16 1-term: Qh x Kh.
// smem: Qh | Khbuf0 | Khbuf1 | mask | red = 67584 B  -> 2 CTAs/SM (forced).
// ---------------------------------------------------------------------------
#define K2_MASKOFF (3 * T1)                    // 55296
#define K2_REDM    (K2_MASKOFF + Sn * 4)       // 63488
#define K2_REDL    (K2_REDM + 4 * 128 * 4)     // 65536
#define K2_SMEM    (K2_REDL + 4 * 128 * 4)     // 67584

__global__ __launch_bounds__(256, 2) void stats_mma(const float* __restrict__ mask)
{
    extern __shared__ char smem[];
    const uint32_t sb = smem_u32(smem);
    float* maskS = (float*)(smem + K2_MASKOFF);
    float* redM  = (float*)(smem + K2_REDM);
    float* redL  = (float*)(smem + K2_REDL);
    const int tid = threadIdx.x;
    const int lane = tid & 31;
    const int wid = tid >> 5;
    const int warp_m = wid & 1;
    const int warp_n = wid >> 1;
    const int qt = blockIdx.x;
    const int bh = blockIdx.y;
    const int bidx = bh >> 4;
    const int grow = qt * 128;

    const size_t qgb = ((size_t)bh * Sn + grow) * Dn;
#pragma unroll
    for (int i = 0; i < 4; i++) {
        const int idx = tid + 256 * i;
        const int row = idx >> 3, c = idx & 7;
        CP_ASYNC(sb + row * ROWB + c * 16, g_qfh + qgb + row * Dn + c * 8);
    }
#pragma unroll
    for (int i = 0; i < 2; i++)
        ((float4*)maskS)[tid + 256 * i] = ((const float4*)(mask + (size_t)bidx * Sn))[tid + 256 * i];

    auto load_k = [&](int kt, int buf) {
        const size_t kgb = ((size_t)bh * Sn + kt * 128) * Dn;
        const uint32_t bufb = sb + T1 + buf * T1;
#pragma unroll
        for (int i = 0; i < 4; i++) {
            const int idx = tid + 256 * i;
            const int row = idx >> 3, c = idx & 7;
            CP_ASYNC(bufb + row * ROWB + c * 16, g_kfh + kgb + row * Dn + c * 8);
        }
        CP_COMMIT();
    };

    load_k(0, 0);
    load_k(1, 1);

    float sm_[8], sl_[8];
#pragma unroll
    for (int i = 0; i < 8; i++) { sm_[i] = -1e30f; sl_[i] = 0.0f; }

    for (int kt = 0; kt < 16; kt++) {
        if (kt == 15) { CP_WAIT0(); } else { CP_WAIT1(); }
        __syncthreads();

        const uint32_t kbase = sb + T1 + (kt & 1) * T1;
        float C[4][4][4];
#pragma unroll
        for (int a = 0; a < 4; a++)
#pragma unroll
            for (int n = 0; n < 4; n++)
#pragma unroll
                for (int j = 0; j < 4; j++) C[a][n][j] = 0.0f;

#pragma unroll
        for (int ks = 0; ks < 4; ks++) {
            uint32_t ah[4][4];
#pragma unroll
            for (int a = 0; a < 4; a++) {
                const int row = warp_m * 64 + a * 16 + ((lane >> 3) & 1) * 8 + (lane & 7);
                const int colb = ks * 32 + (lane >> 4) * 16;
                ldsm4(ah[a], sb + row * ROWB + colb);
            }
            uint32_t bhf[2][4];
#pragma unroll
            for (int p = 0; p < 2; p++) {
                const int row = warp_n * 32 + p * 16 + ((lane >> 4) & 1) * 8 + (lane & 7);
                const int colb = ks * 32 + ((lane >> 3) & 1) * 16;
                ldsm4(bhf[p], kbase + row * ROWB + colb);
            }
#pragma unroll
            for (int a = 0; a < 4; a++)
#pragma unroll
                for (int n = 0; n < 4; n++) {
                    const int p = n >> 1, q = (n & 1) * 2;
                    mma16816h(C[a][n], ah[a], bhf[p][q], bhf[p][q + 1]);
                }
        }

#pragma unroll
        for (int a = 0; a < 4; a++) {
            float s[4][4];
#pragma unroll
            for (int n = 0; n < 4; n++) {
                const int colt = warp_n * 32 + n * 8 + (lane & 3) * 2;
                const float mk0 = maskS[kt * 128 + colt];
                const float mk1 = maskS[kt * 128 + colt + 1];
                s[n][0] = C[a][n][0] * 0.125f + mk0;
                s[n][1] = C[a][n][1] * 0.125f + mk1;
                s[n][2] = C[a][n][2] * 0.125f + mk0;
                s[n][3] = C[a][n][3] * 0.125f + mk1;
            }
#pragma unroll
            for (int hh = 0; hh < 2; hh++) {
                float cm = s[0][hh * 2];
#pragma unroll
                for (int n = 0; n < 4; n++) {
                    cm = fmaxf(cm, s[n][hh * 2]);
                    cm = fmaxf(cm, s[n][hh * 2 + 1]);
                }
                const int si = a * 2 + hh;
                const float mn = fmaxf(sm_[si], cm);
                float ps = 0.0f;
#pragma unroll
                for (int n = 0; n < 4; n++)
                    ps += __expf(s[n][hh * 2] - mn) + __expf(s[n][hh * 2 + 1] - mn);
                sl_[si] = sl_[si] * __expf(sm_[si] - mn) + ps;
                sm_[si] = mn;
            }
        }

        __syncthreads();
        if (kt + 2 < 16) load_k(kt + 2, kt & 1);
    }

#pragma unroll
    for (int i = 0; i < 8; i++) {
        float m = sm_[i], l = sl_[i];
#pragma unroll
        for (int off = 1; off <= 2; off <<= 1) {
            const float om = __shfl_xor_sync(0xffffffffu, m, off);
            const float ol = __shfl_xor_sync(0xffffffffu, l, off);
            const float mn = fmaxf(m, om);
            l = l * __expf(m - mn) + ol * __expf(om - mn);
            m = mn;
        }
        if ((lane & 3) == 0) {
            const int row = warp_m * 64 + (i >> 1) * 16 + (i & 1) * 8 + (lane >> 2);
            redM[warp_n * 128 + row] = m;
            redL[warp_n * 128 + row] = l;
        }
    }
    __syncthreads();
    if (tid < 128) {
        float m = redM[tid], l = redL[tid];
#pragma unroll
        for (int w = 1; w < 4; w++) {
            const float om = redM[w * 128 + tid];
            const float ol = redL[w * 128 + tid];
            const float mn = fmaxf(m, om);
            l = l * __expf(m - mn) + ol * __expf(om - mn);
            m = mn;
        }
        g_m[(size_t)bh * Sn + grow + tid] = m;
        g_l[(size_t)bh * Sn + grow + tid] = l;
    }
}

// ---------------------------------------------------------------------------
// K2b: fused.  QK^T fp16 2-term (qh·kh + ql·kh); p = exp(s-m)*invl; write
// final probs; P@V fp16 1-term (p-hi x V-hi).
// ---------------------------------------------------------------------------
#define F_KOFF  (2 * T1)
#define F_VOFF  (4 * T1)
#define F_MASK  (6 * T1)                  // 110592
#define F_MROW  (F_MASK + Sn * 4)         // 118784
#define F_LROW  (F_MROW + 512)            // 119296
#define F_SMEM  (F_LROW + 512)            // 119808

__global__ __launch_bounds__(256) void fused_pv(
    const float* __restrict__ mask, float* __restrict__ probs, float* __restrict__ ctx)
{
    extern __shared__ char smem[];
    const uint32_t sb = smem_u32(smem);
    float* maskS = (float*)(smem + F_MASK);
    float* mrow  = (float*)(smem + F_MROW);
    float* lrow  = (float*)(smem + F_LROW);
    const int tid = threadIdx.x;
    const int lane = tid & 31;
    const int wid = tid >> 5;
    const int qt = blockIdx.x;
    const int bh = blockIdx.y;
    const int bidx = bh >> 4;
    const int h    = bh & 15;
    const int q0 = qt * 128;

    const size_t qgb = ((size_t)bh * Sn + q0) * Dn;
#pragma unroll
    for (int i = 0; i < 4; i++) {
        const int idx = tid + 256 * i;
        const int row = idx >> 3, c = idx & 7;
        CP_ASYNC(sb + row * ROWB + c * 16,      g_qfh + qgb + row * Dn + c * 8);
        CP_ASYNC(sb + T1 + row * ROWB + c * 16, g_qfl + qgb + row * Dn + c * 8);
    }

    auto load_kv = [&](int kt, int buf) {
        const size_t gb = ((size_t)bh * Sn + kt * 128) * Dn;
        const uint32_t kb = sb + F_KOFF + buf * T1;
        const uint32_t vb = sb + F_VOFF + buf * T1;
#pragma unroll
        for (int i = 0; i < 4; i++) {
            const int idx = tid + 256 * i;
            const int row = idx >> 3, c = idx & 7;
            const size_t g = gb + (size_t)row * Dn + c * 8;
            CP_ASYNC(kb + row * ROWB + c * 16, g_kfh + g);
            CP_ASYNC(vb + row * ROWB + c * 16, g_vf + g);
        }
        CP_COMMIT();
    };

    load_kv(0, 0);
    load_kv(1, 1);

#pragma unroll
    for (int i = 0; i < 2; i++)
        ((float4*)maskS)[tid + 256 * i] = ((const float4*)(mask + (size_t)bidx * Sn))[tid + 256 * i];
    if (tid < 128) {
        const size_t ro = (size_t)bh * Sn + q0 + tid;
        mrow[tid] = g_m[ro];
        lrow[tid] = 1.0f / g_l[ro];
    }

    float O[8][4];
#pragma unroll
    for (int n = 0; n < 8; n++)
#pragma unroll
        for (int j = 0; j < 4; j++) O[n][j] = 0.0f;

    const int rloc0 = wid * 16 + (lane >> 2);
    float mm0, ll0, mm1, ll1;

    for (int kt = 0; kt < 16; kt++) {
        if (kt == 15) { CP_WAIT0(); } else { CP_WAIT1(); }
        __syncthreads();
        if (kt == 0) { mm0 = mrow[rloc0]; ll0 = lrow[rloc0];
                       mm1 = mrow[rloc0 + 8]; ll1 = lrow[rloc0 + 8]; }

        const uint32_t kbase = sb + F_KOFF + (kt & 1) * T1;
        const uint32_t vbase = sb + F_VOFF + (kt & 1) * T1;

        float C[16][4];
#pragma unroll
        for (int n = 0; n < 16; n++)
#pragma unroll
            for (int j = 0; j < 4; j++) C[n][j] = 0.0f;

#pragma unroll
        for (int ks = 0; ks < 4; ks++) {
            uint32_t qh4[4], ql4[4];
            {
                const int row = wid * 16 + ((lane >> 3) & 1) * 8 + (lane & 7);
                const int colb = ks * 32 + (lane >> 4) * 16;
                ldsm4(qh4, sb + row * ROWB + colb);
                ldsm4(ql4, sb + T1 + row * ROWB + colb);
            }
#pragma unroll
            for (int g = 0; g < 8; g++) {
                uint32_t kh4[4];
                const int row = g * 16 + ((lane >> 4) & 1) * 8 + (lane & 7);
                const int colb = ks * 32 + ((lane >> 3) & 1) * 16;
                ldsm4(kh4, kbase + row * ROWB + colb);
                mma16816h(C[2*g],   qh4, kh4[0], kh4[1]);
                mma16816h(C[2*g],   ql4, kh4[0], kh4[1]);
                mma16816h(C[2*g+1], qh4, kh4[2], kh4[3]);
                mma16816h(C[2*g+1], ql4, kh4[2], kh4[3]);
            }
        }

        const size_t prow0 = ((size_t)bh * Sn + q0 + rloc0) * Sn + kt * 128;
        const size_t prow1 = prow0 + (size_t)8 * Sn;
#pragma unroll
        for (int n = 0; n < 16; n++) {
            const int colt = n * 8 + (lane & 3) * 2;
            const float mk0 = maskS[kt * 128 + colt];
            const float mk1 = maskS[kt * 128 + colt + 1];
            const float p00 = __expf(C[n][0] * 0.125f + mk0 - mm0) * ll0;
            const float p01 = __expf(C[n][1] * 0.125f + mk1 - mm0) * ll0;
            const float p10 = __expf(C[n][2] * 0.125f + mk0 - mm1) * ll1;
            const float p11 = __expf(C[n][3] * 0.125f + mk1 - mm1) * ll1;
            C[n][0] = p00; C[n][1] = p01; C[n][2] = p10; C[n][3] = p11;
            *(float2*)&probs[prow0 + colt] = make_float2(p00, p01);
            *(float2*)&probs[prow1 + colt] = make_float2(p10, p11);
        }

        // P@V: fp16 1-term (p-hi x V-hi)
#pragma unroll
        for (int kg = 0; kg < 8; kg++) {
            uint32_t aph[4];
            aph[0] = packh1(C[2*kg][0],   C[2*kg][1]);
            aph[1] = packh1(C[2*kg][2],   C[2*kg][3]);
            aph[2] = packh1(C[2*kg+1][0], C[2*kg+1][1]);
            aph[3] = packh1(C[2*kg+1][2], C[2*kg+1][3]);
            const uint32_t brow = kg * 16 + (lane & 7) + ((lane >> 3) & 1) * 8;
#pragma unroll
            for (int nb = 0; nb < 4; nb++) {
                uint32_t vh4[4];
                ldsm4_t(vh4, vbase + brow * ROWB + nb * 32 + (lane >> 4) * 16);
                mma16816h(O[nb*2],   aph, vh4[0], vh4[1]);
                mma16816h(O[nb*2+1], aph, vh4[2], vh4[3]);
            }
        }

        __syncthreads();
        if (kt + 2 < 16) load_kv(kt + 2, kt & 1);
    }

#pragma unroll
    for (int nb = 0; nb < 8; nb++) {
        const int col = nb * 8 + (lane & 3) * 2;
        const int row = q0 + wid * 16 + (lane >> 2);
        *(float2*)&ctx[((size_t)(bidx * Sn + row)) * HIDn + h * 64 + col] =
            make_float2(O[nb][0], O[nb][1]);
        *(float2*)&ctx[((size_t)(bidx * Sn + row + 8)) * HIDn + h * 64 + col] =
            make_float2(O[nb][2], O[nb][3]);
    }
}

// ---------------------------------------------------------------------------
extern "C" void kernel_launch(void* const* d_in, const int* in_sizes, int n_in,
                              void* d_out, int out_size)
{
    const float* x    = (const float*)d_in[0];
    const float* mask = (const float*)d_in[1];
    const float* Wq   = (const float*)d_in[2];
    const float* bq   = (const float*)d_in[3];
    const float* Wk   = (const float*)d_in[4];
    const float* bk   = (const float*)d_in[5];
    const float* Wv   = (const float*)d_in[6];
    const float* bv   = (const float*)d_in[7];

    float* ctx = (float*)d_out;
    const size_t PROBS_ELEMS = (size_t)BHn * Sn * Sn;
    size_t probs_off = 0;
    if ((size_t)out_size > PROBS_ELEMS) probs_off = (size_t)out_size - PROBS_ELEMS;
    float* probs = (float*)d_out + probs_off;

    cudaFuncSetAttribute(qkv_q,     cudaFuncAttributeMaxDynamicSharedMemorySize, K1_SMEM);
    cudaFuncSetAttribute(qkv_kv,    cudaFuncAttributeMaxDynamicSharedMemorySize, KV_SMEM);
    cudaFuncSetAttribute(stats_mma, cudaFuncAttributeMaxDynamicSharedMemorySize, K2_SMEM);
    cudaFuncSetAttribute(fused_pv,  cudaFuncAttributeMaxDynamicSharedMemorySize, F_SMEM);

    split_x_kernel<<<Mn * HIDn / 4 / 256, 256>>>((const float4*)x);
    split_w_kernel<<<dim3(HIDn * HIDn / 4 / 256, 3), 256>>>(
        (const float4*)Wq, (const float4*)Wk, (const float4*)Wv);
    qkv_q<<<dim3(Mn/128, HIDn/128), 256, K1_SMEM>>>(bq);
    qkv_kv<<<dim3(Mn/128, HIDn/128, 2), 256, KV_SMEM>>>(bk, bv);
    stats_mma<<<dim3(Sn/128, BHn), 256, K2_SMEM>>>(mask);
    fused_pv<<<dim3(Sn/128, BHn), 256, F_SMEM>>>(mask, probs, ctx);
}

// round 13
// speedup vs baseline: 2.4613x; 1.0917x over previous
#include <cuda_runtime.h>
#include <cuda_fp16.h>
#include <math.h>
#include <stdint.h>

#define Bn   4
#define Sn   2048
#define HIDn 1024
#define NHn  16
#define Dn   64
#define BHn  64
#define Mn   8192

// ---------------- scratch (static device globals; no runtime alloc) --------
__device__ __half g_xfh[(size_t)Mn * HIDn];          // x fp16 hi/lo split
__device__ __half g_xfl[(size_t)Mn * HIDn];
__device__ __half g_wfh[(size_t)3 * HIDn * HIDn];    // Wq,Wk,Wv fp16 hi
__device__ __half g_qfh[(size_t)BHn * Sn * Dn];
__device__ __half g_kfh[(size_t)BHn * Sn * Dn];
__device__ __half g_vf [(size_t)BHn * Sn * Dn];
__device__ float g_m[(size_t)BHn * Sn];
__device__ float g_l[(size_t)BHn * Sn];

// ---------------- PTX helpers (baseline-feature PTX only) -------------------
__device__ __forceinline__ uint32_t smem_u32(const void* p) {
    uint32_t a;
    asm("{ .reg .u64 t; cvta.to.shared.u64 t, %1; cvt.u32.u64 %0, t; }" : "=r"(a) : "l"(p));
    return a;
}
#define CP_ASYNC(dst, src) \
    asm volatile("cp.async.cg.shared.global [%0], [%1], 16;" :: "r"(dst), "l"(src))
#define CP_COMMIT() asm volatile("cp.async.commit_group;")
#define CP_WAIT0()  asm volatile("cp.async.wait_group 0;")
#define CP_WAIT1()  asm volatile("cp.async.wait_group 1;")

__device__ __forceinline__ void ldsm4(uint32_t r[4], uint32_t addr) {
    asm volatile("ldmatrix.sync.aligned.m8n8.x4.shared.b16 {%0,%1,%2,%3}, [%4];"
        : "=r"(r[0]), "=r"(r[1]), "=r"(r[2]), "=r"(r[3]) : "r"(addr));
}
__device__ __forceinline__ void ldsm4_t(uint32_t r[4], uint32_t addr) {
    asm volatile("ldmatrix.sync.aligned.m8n8.x4.trans.shared.b16 {%0,%1,%2,%3}, [%4];"
        : "=r"(r[0]), "=r"(r[1]), "=r"(r[2]), "=r"(r[3]) : "r"(addr));
}
__device__ __forceinline__ void mma16816h(float c[4], const uint32_t a[4],
                                          uint32_t b0, uint32_t b1) {
    asm volatile("mma.sync.aligned.m16n8k16.row.col.f32.f16.f16.f32 "
        "{%0,%1,%2,%3}, {%4,%5,%6,%7}, {%8,%9}, {%0,%1,%2,%3};"
        : "+f"(c[0]), "+f"(c[1]), "+f"(c[2]), "+f"(c[3])
        : "r"(a[0]), "r"(a[1]), "r"(a[2]), "r"(a[3]), "r"(b0), "r"(b1));
}

// ---------------- fp16 split ------------------------------------------------
__device__ __forceinline__ void split1h(float v, uint16_t& h, uint16_t& l) {
    __half hb = __float2half_rn(v);
    float r = v - __half2float(hb);
    h = __half_as_ushort(hb);
    l = __half_as_ushort(__float2half_rn(r));
}
__device__ __forceinline__ void split_packh(float v0, float v1, uint32_t& ph, uint32_t& pl) {
    uint16_t h0, h1, l0, l1;
    split1h(v0, h0, l0); split1h(v1, h1, l1);
    ph = ((uint32_t)h1 << 16) | h0;
    pl = ((uint32_t)l1 << 16) | l0;
}
__device__ __forceinline__ uint32_t packh1(float v0, float v1) {
    return ((uint32_t)__half_as_ushort(__float2half_rn(v1)) << 16) |
           (uint32_t)__half_as_ushort(__float2half_rn(v0));
}

__global__ __launch_bounds__(256) void split_x_kernel(const float4* __restrict__ src) {
    size_t i = (size_t)blockIdx.x * 256 + threadIdx.x;
    float4 v = src[i];
    uint32_t fh01, fl01, fh23, fl23;
    split_packh(v.x, v.y, fh01, fl01);
    split_packh(v.z, v.w, fh23, fl23);
    ((uint2*)g_xfh)[i] = make_uint2(fh01, fh23);
    ((uint2*)g_xfl)[i] = make_uint2(fl01, fl23);
}

__global__ __launch_bounds__(256) void split_w_kernel(const float4* __restrict__ Wq,
                                                      const float4* __restrict__ Wk,
                                                      const float4* __restrict__ Wv) {
    const int which = blockIdx.y;
    const float4* W = (which == 0) ? Wq : ((which == 1) ? Wk : Wv);
    size_t i = (size_t)blockIdx.x * 256 + threadIdx.x;
    float4 v = W[i];
    size_t o = (size_t)which * (HIDn * HIDn / 4) + i;
    ((uint2*)g_wfh)[o] = make_uint2(packh1(v.x, v.y), packh1(v.z, v.w));
}

// Tile: 128 rows x 64 elems x 2B (128B data + 16B pad = 144B row stride).
#define ROWB 144
#define T1   (128 * ROWB)     // 18432 B per tile

// ---------------------------------------------------------------------------
// K1: Q/K/V projection (fp16 2-term: (xfh + xfl) x wfh).  grid.z: 0=Q,1=K,2=V.
// Output fp16 hi only, [bh][s][d] layout.
// smem: 2 buffers x 3 tiles = 110592 B -> 2 CTAs/SM.
// ---------------------------------------------------------------------------
#define KV_SMEM (6 * T1)      // 110592 B

__global__ __launch_bounds__(256) void qkv_all(
    const float* __restrict__ bq, const float* __restrict__ bk, const float* __restrict__ bv)
{
    extern __shared__ char smem[];
    const uint32_t sb = smem_u32(smem);
    const int tid = threadIdx.x;
    const int lane = tid & 31;
    const int wid = tid >> 5;
    const int warp_m = wid & 1;
    const int warp_n = wid >> 1;
    const int which = blockIdx.z;
    const int m0 = blockIdx.x * 128;
    const int n0 = blockIdx.y * 128;
    const float* bias = (which == 0) ? bq : ((which == 1) ? bk : bv);
    const __half* wf = g_wfh + (size_t)which * HIDn * HIDn;

    float C[4][4][4];
#pragma unroll
    for (int a = 0; a < 4; a++)
#pragma unroll
        for (int n = 0; n < 4; n++)
#pragma unroll
            for (int j = 0; j < 4; j++) C[a][n][j] = 0.0f;

    auto load_chunk = [&](int chunk, int buf) {
        const int kc = chunk * 64;
        const uint32_t bufb = sb + buf * 3 * T1;
#pragma unroll
        for (int t = 0; t < 3; t++) {
            const __half* src = (t == 0) ? g_xfh : (t == 1) ? g_xfl : wf;
            const int rbase = (t < 2) ? m0 : n0;
#pragma unroll
            for (int i = 0; i < 4; i++) {
                const int idx = tid + 256 * i;
                const int row = idx >> 3, c = idx & 7;
                CP_ASYNC(bufb + t * T1 + row * ROWB + c * 16,
                         src + (size_t)(rbase + row) * HIDn + kc + c * 8);
            }
        }
        CP_COMMIT();
    };

    auto compute = [&](int buf) {
        const uint32_t base = sb + buf * 3 * T1;
#pragma unroll
        for (int ks = 0; ks < 4; ks++) {
            uint32_t ah[4][4], al[4][4];
#pragma unroll
            for (int a = 0; a < 4; a++) {
                const int row = warp_m * 64 + a * 16 + ((lane >> 3) & 1) * 8 + (lane & 7);
                const int colb = ks * 32 + (lane >> 4) * 16;
                ldsm4(ah[a], base + row * ROWB + colb);
                ldsm4(al[a], base + T1 + row * ROWB + colb);
            }
            uint32_t bh[2][4];
#pragma unroll
            for (int p = 0; p < 2; p++) {
                const int row = warp_n * 32 + p * 16 + ((lane >> 4) & 1) * 8 + (lane & 7);
                const int colb = ks * 32 + ((lane >> 3) & 1) * 16;
                ldsm4(bh[p], base + 2 * T1 + row * ROWB + colb);
            }
#pragma unroll
            for (int a = 0; a < 4; a++)
#pragma unroll
                for (int n = 0; n < 4; n++) {
                    const int p = n >> 1, q = (n & 1) * 2;
                    mma16816h(C[a][n], ah[a], bh[p][q], bh[p][q + 1]);
                    mma16816h(C[a][n], al[a], bh[p][q], bh[p][q + 1]);
                }
        }
    };

    load_chunk(0, 0);
    load_chunk(1, 1);
    for (int kt = 0; kt < 16; kt++) {
        if (kt == 15) { CP_WAIT0(); } else { CP_WAIT1(); }
        __syncthreads();
        compute(kt & 1);
        __syncthreads();
        if (kt + 2 < 16) load_chunk(kt + 2, kt & 1);
    }

    __half* out = (which == 0) ? g_qfh : ((which == 1) ? g_kfh : g_vf);
#pragma unroll
    for (int a = 0; a < 4; a++)
#pragma unroll
        for (int n = 0; n < 4; n++) {
            const int row0 = m0 + warp_m * 64 + a * 16 + (lane >> 2);
            const int col  = n0 + warp_n * 32 + n * 8 + (lane & 3) * 2;
            const float bb0 = bias[col], bb1 = bias[col + 1];
            const int hd = col >> 6, d = col & 63;
#pragma unroll
            for (int h = 0; h < 2; h++) {
                const int row = row0 + h * 8;
                const float v0 = C[a][n][h * 2 + 0] + bb0;
                const float v1 = C[a][n][h * 2 + 1] + bb1;
                const int bidx = row >> 11, s = row & (Sn - 1);
                const size_t oi = ((size_t)(bidx * NHn + hd) * Sn + s) * Dn + d;
                *(uint32_t*)&out[oi] = packh1(v0, v1);
            }
        }
}

// ---------------------------------------------------------------------------
// K2a: softmax stats only.  fp16 1-term: Qh x Kh.
// smem: Qh | Khbuf0 | Khbuf1 | mask | red = 67584 B  -> 2 CTAs/SM (forced).
// ---------------------------------------------------------------------------
#define K2_MASKOFF (3 * T1)                    // 55296
#define K2_REDM    (K2_MASKOFF + Sn * 4)       // 63488
#define K2_REDL    (K2_REDM + 4 * 128 * 4)     // 65536
#define K2_SMEM    (K2_REDL + 4 * 128 * 4)     // 67584

__global__ __launch_bounds__(256, 2) void stats_mma(const float* __restrict__ mask)
{
    extern __shared__ char smem[];
    const uint32_t sb = smem_u32(smem);
    float* maskS = (float*)(smem + K2_MASKOFF);
    float* redM  = (float*)(smem + K2_REDM);
    float* redL  = (float*)(smem + K2_REDL);
    const int tid = threadIdx.x;
    const int lane = tid & 31;
    const int wid = tid >> 5;
    const int warp_m = wid & 1;
    const int warp_n = wid >> 1;
    const int qt = blockIdx.x;
    const int bh = blockIdx.y;
    const int bidx = bh >> 4;
    const int grow = qt * 128;

    const size_t qgb = ((size_t)bh * Sn + grow) * Dn;
#pragma unroll
    for (int i = 0; i < 4; i++) {
        const int idx = tid + 256 * i;
        const int row = idx >> 3, c = idx & 7;
        CP_ASYNC(sb + row * ROWB + c * 16, g_qfh + qgb + row * Dn + c * 8);
    }
#pragma unroll
    for (int i = 0; i < 2; i++)
        ((float4*)maskS)[tid + 256 * i] = ((const float4*)(mask + (size_t)bidx * Sn))[tid + 256 * i];

    auto load_k = [&](int kt, int buf) {
        const size_t kgb = ((size_t)bh * Sn + kt * 128) * Dn;
        const uint32_t bufb = sb + T1 + buf * T1;
#pragma unroll
        for (int i = 0; i < 4; i++) {
            const int idx = tid + 256 * i;
            const int row = idx >> 3, c = idx & 7;
            CP_ASYNC(bufb + row * ROWB + c * 16, g_kfh + kgb + row * Dn + c * 8);
        }
        CP_COMMIT();
    };

    load_k(0, 0);
    load_k(1, 1);

    float sm_[8], sl_[8];
#pragma unroll
    for (int i = 0; i < 8; i++) { sm_[i] = -1e30f; sl_[i] = 0.0f; }

    for (int kt = 0; kt < 16; kt++) {
        if (kt == 15) { CP_WAIT0(); } else { CP_WAIT1(); }
        __syncthreads();

        const uint32_t kbase = sb + T1 + (kt & 1) * T1;
        float C[4][4][4];
#pragma unroll
        for (int a = 0; a < 4; a++)
#pragma unroll
            for (int n = 0; n < 4; n++)
#pragma unroll
                for (int j = 0; j < 4; j++) C[a][n][j] = 0.0f;

#pragma unroll
        for (int ks = 0; ks < 4; ks++) {
            uint32_t ah[4][4];
#pragma unroll
            for (int a = 0; a < 4; a++) {
                const int row = warp_m * 64 + a * 16 + ((lane >> 3) & 1) * 8 + (lane & 7);
                const int colb = ks * 32 + (lane >> 4) * 16;
                ldsm4(ah[a], sb + row * ROWB + colb);
            }
            uint32_t bhf[2][4];
#pragma unroll
            for (int p = 0; p < 2; p++) {
                const int row = warp_n * 32 + p * 16 + ((lane >> 4) & 1) * 8 + (lane & 7);
                const int colb = ks * 32 + ((lane >> 3) & 1) * 16;
                ldsm4(bhf[p], kbase + row * ROWB + colb);
            }
#pragma unroll
            for (int a = 0; a < 4; a++)
#pragma unroll
                for (int n = 0; n < 4; n++) {
                    const int p = n >> 1, q = (n & 1) * 2;
                    mma16816h(C[a][n], ah[a], bhf[p][q], bhf[p][q + 1]);
                }
        }

#pragma unroll
        for (int a = 0; a < 4; a++) {
            float s[4][4];
#pragma unroll
            for (int n = 0; n < 4; n++) {
                const int colt = warp_n * 32 + n * 8 + (lane & 3) * 2;
                const float mk0 = maskS[kt * 128 + colt];
                const float mk1 = maskS[kt * 128 + colt + 1];
                s[n][0] = C[a][n][0] * 0.125f + mk0;
                s[n][1] = C[a][n][1] * 0.125f + mk1;
                s[n][2] = C[a][n][2] * 0.125f + mk0;
                s[n][3] = C[a][n][3] * 0.125f + mk1;
            }
#pragma unroll
            for (int hh = 0; hh < 2; hh++) {
                float cm = s[0][hh * 2];
#pragma unroll
                for (int n = 0; n < 4; n++) {
                    cm = fmaxf(cm, s[n][hh * 2]);
                    cm = fmaxf(cm, s[n][hh * 2 + 1]);
                }
                const int si = a * 2 + hh;
                const float mn = fmaxf(sm_[si], cm);
                float ps = 0.0f;
#pragma unroll
                for (int n = 0; n < 4; n++)
                    ps += __expf(s[n][hh * 2] - mn) + __expf(s[n][hh * 2 + 1] - mn);
                sl_[si] = sl_[si] * __expf(sm_[si] - mn) + ps;
                sm_[si] = mn;
            }
        }

        __syncthreads();
        if (kt + 2 < 16) load_k(kt + 2, kt & 1);
    }

#pragma unroll
    for (int i = 0; i < 8; i++) {
        float m = sm_[i], l = sl_[i];
#pragma unroll
        for (int off = 1; off <= 2; off <<= 1) {
            const float om = __shfl_xor_sync(0xffffffffu, m, off);
            const float ol = __shfl_xor_sync(0xffffffffu, l, off);
            const float mn = fmaxf(m, om);
            l = l * __expf(m - mn) + ol * __expf(om - mn);
            m = mn;
        }
        if ((lane & 3) == 0) {
            const int row = warp_m * 64 + (i >> 1) * 16 + (i & 1) * 8 + (lane >> 2);
            redM[warp_n * 128 + row] = m;
            redL[warp_n * 128 + row] = l;
        }
    }
    __syncthreads();
    if (tid < 128) {
        float m = redM[tid], l = redL[tid];
#pragma unroll
        for (int w = 1; w < 4; w++) {
            const float om = redM[w * 128 + tid];
            const float ol = redL[w * 128 + tid];
            const float mn = fmaxf(m, om);
            l = l * __expf(m - mn) + ol * __expf(om - mn);
            m = mn;
        }
        g_m[(size_t)bh * Sn + grow + tid] = m;
        g_l[(size_t)bh * Sn + grow + tid] = l;
    }
}

// ---------------------------------------------------------------------------
// K2b: fused.  QK^T fp16 1-term (qh·kh — bit-identical to stats' scores);
// p = exp(s-m)*invl; write final probs; P@V fp16 1-term (p-hi x V-hi).
// smem: Qh | Kh0 | Kh1 | V0 | V1 | mask | m | invl = 101376 B
// ---------------------------------------------------------------------------
#define F_KOFF  (1 * T1)
#define F_VOFF  (3 * T1)
#define F_MASK  (5 * T1)                  // 92160
#define F_MROW  (F_MASK + Sn * 4)         // 100352
#define F_LROW  (F_MROW + 512)            // 100864
#define F_SMEM  (F_LROW + 512)            // 101376

__global__ __launch_bounds__(256) void fused_pv(
    const float* __restrict__ mask, float* __restrict__ probs, float* __restrict__ ctx)
{
    extern __shared__ char smem[];
    const uint32_t sb = smem_u32(smem);
    float* maskS = (float*)(smem + F_MASK);
    float* mrow  = (float*)(smem + F_MROW);
    float* lrow  = (float*)(smem + F_LROW);
    const int tid = threadIdx.x;
    const int lane = tid & 31;
    const int wid = tid >> 5;
    const int qt = blockIdx.x;
    const int bh = blockIdx.y;
    const int bidx = bh >> 4;
    const int h    = bh & 15;
    const int q0 = qt * 128;

    const size_t qgb = ((size_t)bh * Sn + q0) * Dn;
#pragma unroll
    for (int i = 0; i < 4; i++) {
        const int idx = tid + 256 * i;
        const int row = idx >> 3, c = idx & 7;
        CP_ASYNC(sb + row * ROWB + c * 16, g_qfh + qgb + row * Dn + c * 8);
    }

    auto load_kv = [&](int kt, int buf) {
        const size_t gb = ((size_t)bh * Sn + kt * 128) * Dn;
        const uint32_t kb = sb + F_KOFF + buf * T1;
        const uint32_t vb = sb + F_VOFF + buf * T1;
#pragma unroll
        for (int i = 0; i < 4; i++) {
            const int idx = tid + 256 * i;
            const int row = idx >> 3, c = idx & 7;
            const size_t g = gb + (size_t)row * Dn + c * 8;
            CP_ASYNC(kb + row * ROWB + c * 16, g_kfh + g);
            CP_ASYNC(vb + row * ROWB + c * 16, g_vf + g);
        }
        CP_COMMIT();
    };

    load_kv(0, 0);
    load_kv(1, 1);

#pragma unroll
    for (int i = 0; i < 2; i++)
        ((float4*)maskS)[tid + 256 * i] = ((const float4*)(mask + (size_t)bidx * Sn))[tid + 256 * i];
    if (tid < 128) {
        const size_t ro = (size_t)bh * Sn + q0 + tid;
        mrow[tid] = g_m[ro];
        lrow[tid] = 1.0f / g_l[ro];
    }

    float O[8][4];
#pragma unroll
    for (int n = 0; n < 8; n++)
#pragma unroll
        for (int j = 0; j < 4; j++) O[n][j] = 0.0f;

    const int rloc0 = wid * 16 + (lane >> 2);
    float mm0, ll0, mm1, ll1;

    for (int kt = 0; kt < 16; kt++) {
        if (kt == 15) { CP_WAIT0(); } else { CP_WAIT1(); }
        __syncthreads();
        if (kt == 0) { mm0 = mrow[rloc0]; ll0 = lrow[rloc0];
                       mm1 = mrow[rloc0 + 8]; ll1 = lrow[rloc0 + 8]; }

        const uint32_t kbase = sb + F_KOFF + (kt & 1) * T1;
        const uint32_t vbase = sb + F_VOFF + (kt & 1) * T1;

        float C[16][4];
#pragma unroll
        for (int n = 0; n < 16; n++)
#pragma unroll
            for (int j = 0; j < 4; j++) C[n][j] = 0.0f;

#pragma unroll
        for (int ks = 0; ks < 4; ks++) {
            uint32_t qh4[4];
            {
                const int row = wid * 16 + ((lane >> 3) & 1) * 8 + (lane & 7);
                const int colb = ks * 32 + (lane >> 4) * 16;
                ldsm4(qh4, sb + row * ROWB + colb);
            }
#pragma unroll
            for (int g = 0; g < 8; g++) {
                uint32_t kh4[4];
                const int row = g * 16 + ((lane >> 4) & 1) * 8 + (lane & 7);
                const int colb = ks * 32 + ((lane >> 3) & 1) * 16;
                ldsm4(kh4, kbase + row * ROWB + colb);
                mma16816h(C[2*g],   qh4, kh4[0], kh4[1]);
                mma16816h(C[2*g+1], qh4, kh4[2], kh4[3]);
            }
        }

        const size_t prow0 = ((size_t)bh * Sn + q0 + rloc0) * Sn + kt * 128;
        const size_t prow1 = prow0 + (size_t)8 * Sn;
#pragma unroll
        for (int n = 0; n < 16; n++) {
            const int colt = n * 8 + (lane & 3) * 2;
            const float mk0 = maskS[kt * 128 + colt];
            const float mk1 = maskS[kt * 128 + colt + 1];
            const float p00 = __expf(C[n][0] * 0.125f + mk0 - mm0) * ll0;
            const float p01 = __expf(C[n][1] * 0.125f + mk1 - mm0) * ll0;
            const float p10 = __expf(C[n][2] * 0.125f + mk0 - mm1) * ll1;
            const float p11 = __expf(C[n][3] * 0.125f + mk1 - mm1) * ll1;
            C[n][0] = p00; C[n][1] = p01; C[n][2] = p10; C[n][3] = p11;
            *(float2*)&probs[prow0 + colt] = make_float2(p00, p01);
            *(float2*)&probs[prow1 + colt] = make_float2(p10, p11);
        }

        // P@V: fp16 1-term (p-hi x V-hi)
#pragma unroll
        for (int kg = 0; kg < 8; kg++) {
            uint32_t aph[4];
            aph[0] = packh1(C[2*kg][0],   C[2*kg][1]);
            aph[1] = packh1(C[2*kg][2],   C[2*kg][3]);
            aph[2] = packh1(C[2*kg+1][0], C[2*kg+1][1]);
            aph[3] = packh1(C[2*kg+1][2], C[2*kg+1][3]);
            const uint32_t brow = kg * 16 + (lane & 7) + ((lane >> 3) & 1) * 8;
#pragma unroll
            for (int nb = 0; nb < 4; nb++) {
                uint32_t vh4[4];
                ldsm4_t(vh4, vbase + brow * ROWB + nb * 32 + (lane >> 4) * 16);
                mma16816h(O[nb*2],   aph, vh4[0], vh4[1]);
                mma16816h(O[nb*2+1], aph, vh4[2], vh4[3]);
            }
        }

        __syncthreads();
        if (kt + 2 < 16) load_kv(kt + 2, kt & 1);
    }

#pragma unroll
    for (int nb = 0; nb < 8; nb++) {
        const int col = nb * 8 + (lane & 3) * 2;
        const int row = q0 + wid * 16 + (lane >> 2);
        *(float2*)&ctx[((size_t)(bidx * Sn + row)) * HIDn + h * 64 + col] =
            make_float2(O[nb][0], O[nb][1]);
        *(float2*)&ctx[((size_t)(bidx * Sn + row + 8)) * HIDn + h * 64 + col] =
            make_float2(O[nb][2], O[nb][3]);
    }
}

// ---------------------------------------------------------------------------
extern "C" void kernel_launch(void* const* d_in, const int* in_sizes, int n_in,
                              void* d_out, int out_size)
{
    const float* x    = (const float*)d_in[0];
    const float* mask = (const float*)d_in[1];
    const float* Wq   = (const float*)d_in[2];
    const float* bq   = (const float*)d_in[3];
    const float* Wk   = (const float*)d_in[4];
    const float* bk   = (const float*)d_in[5];
    const float* Wv   = (const float*)d_in[6];
    const float* bv   = (const float*)d_in[7];

    float* ctx = (float*)d_out;
    const size_t PROBS_ELEMS = (size_t)BHn * Sn * Sn;
    size_t probs_off = 0;
    if ((size_t)out_size > PROBS_ELEMS) probs_off = (size_t)out_size - PROBS_ELEMS;
    float* probs = (float*)d_out + probs_off;

    cudaFuncSetAttribute(qkv_all,   cudaFuncAttributeMaxDynamicSharedMemorySize, KV_SMEM);
    cudaFuncSetAttribute(stats_mma, cudaFuncAttributeMaxDynamicSharedMemorySize, K2_SMEM);
    cudaFuncSetAttribute(fused_pv,  cudaFuncAttributeMaxDynamicSharedMemorySize, F_SMEM);

    split_x_kernel<<<Mn * HIDn / 4 / 256, 256>>>((const float4*)x);
    split_w_kernel<<<dim3(HIDn * HIDn / 4 / 256, 3), 256>>>(
        (const float4*)Wq, (const float4*)Wk, (const float4*)Wv);
    qkv_all<<<dim3(Mn/128, HIDn/128, 3), 256, KV_SMEM>>>(bq, bk, bv);
    stats_mma<<<dim3(Sn/128, BHn), 256, K2_SMEM>>>(mask);
    fused_pv<<<dim3(Sn/128, BHn), 256, F_SMEM>>>(mask, probs, ctx);
}

// round 14
// speedup vs baseline: 2.5778x; 1.0474x over previous
#include <cuda_runtime.h>
#include <cuda_fp16.h>
#include <math.h>
#include <stdint.h>

#define Bn   4
#define Sn   2048
#define HIDn 1024
#define NHn  16
#define Dn   64
#define BHn  64
#define Mn   8192

// ---------------- scratch (static device globals; no runtime alloc) --------
__device__ __half g_xfh[(size_t)Mn * HIDn];          // x fp16 hi/lo split
__device__ __half g_xfl[(size_t)Mn * HIDn];
__device__ __half g_wfh[(size_t)3 * HIDn * HIDn];    // Wq,Wk,Wv fp16 hi
__device__ __half g_qfh[(size_t)BHn * Sn * Dn];
__device__ __half g_kfh[(size_t)BHn * Sn * Dn];
__device__ __half g_vf [(size_t)BHn * Sn * Dn];
__device__ float g_m[(size_t)BHn * Sn];
__device__ float g_l[(size_t)BHn * Sn];

// ---------------- PTX helpers (baseline-feature PTX only) -------------------
__device__ __forceinline__ uint32_t smem_u32(const void* p) {
    uint32_t a;
    asm("{ .reg .u64 t; cvta.to.shared.u64 t, %1; cvt.u32.u64 %0, t; }" : "=r"(a) : "l"(p));
    return a;
}
#define CP_ASYNC(dst, src) \
    asm volatile("cp.async.cg.shared.global [%0], [%1], 16;" :: "r"(dst), "l"(src))
#define CP_COMMIT() asm volatile("cp.async.commit_group;")
#define CP_WAIT0()  asm volatile("cp.async.wait_group 0;")
#define CP_WAIT1()  asm volatile("cp.async.wait_group 1;")

__device__ __forceinline__ void ldsm4(uint32_t r[4], uint32_t addr) {
    asm volatile("ldmatrix.sync.aligned.m8n8.x4.shared.b16 {%0,%1,%2,%3}, [%4];"
        : "=r"(r[0]), "=r"(r[1]), "=r"(r[2]), "=r"(r[3]) : "r"(addr));
}
__device__ __forceinline__ void ldsm4_t(uint32_t r[4], uint32_t addr) {
    asm volatile("ldmatrix.sync.aligned.m8n8.x4.trans.shared.b16 {%0,%1,%2,%3}, [%4];"
        : "=r"(r[0]), "=r"(r[1]), "=r"(r[2]), "=r"(r[3]) : "r"(addr));
}
__device__ __forceinline__ void mma16816h(float c[4], const uint32_t a[4],
                                          uint32_t b0, uint32_t b1) {
    asm volatile("mma.sync.aligned.m16n8k16.row.col.f32.f16.f16.f32 "
        "{%0,%1,%2,%3}, {%4,%5,%6,%7}, {%8,%9}, {%0,%1,%2,%3};"
        : "+f"(c[0]), "+f"(c[1]), "+f"(c[2]), "+f"(c[3])
        : "r"(a[0]), "r"(a[1]), "r"(a[2]), "r"(a[3]), "r"(b0), "r"(b1));
}

// ---------------- fp16 split ------------------------------------------------
__device__ __forceinline__ void split1h(float v, uint16_t& h, uint16_t& l) {
    __half hb = __float2half_rn(v);
    float r = v - __half2float(hb);
    h = __half_as_ushort(hb);
    l = __half_as_ushort(__float2half_rn(r));
}
__device__ __forceinline__ void split_packh(float v0, float v1, uint32_t& ph, uint32_t& pl) {
    uint16_t h0, h1, l0, l1;
    split1h(v0, h0, l0); split1h(v1, h1, l1);
    ph = ((uint32_t)h1 << 16) | h0;
    pl = ((uint32_t)l1 << 16) | l0;
}
__device__ __forceinline__ uint32_t packh1(float v0, float v1) {
    return ((uint32_t)__half_as_ushort(__float2half_rn(v1)) << 16) |
           (uint32_t)__half_as_ushort(__float2half_rn(v0));
}

// Merged split kernel: blocks [0, XB) split x; blocks [XB, XB+3*WB) split W.
#define XB (Mn * HIDn / 4 / 256)          // 8192
#define WB (HIDn * HIDn / 4 / 256)        // 1024

__global__ __launch_bounds__(256) void split_all_kernel(
    const float4* __restrict__ x, const float4* __restrict__ Wq,
    const float4* __restrict__ Wk, const float4* __restrict__ Wv)
{
    const int b = blockIdx.x;
    if (b < XB) {
        size_t i = (size_t)b * 256 + threadIdx.x;
        float4 v = x[i];
        uint32_t fh01, fl01, fh23, fl23;
        split_packh(v.x, v.y, fh01, fl01);
        split_packh(v.z, v.w, fh23, fl23);
        ((uint2*)g_xfh)[i] = make_uint2(fh01, fh23);
        ((uint2*)g_xfl)[i] = make_uint2(fl01, fl23);
    } else {
        const int wb = b - XB;
        const int which = wb / WB;
        size_t i = (size_t)(wb - which * WB) * 256 + threadIdx.x;
        const float4* W = (which == 0) ? Wq : ((which == 1) ? Wk : Wv);
        float4 v = W[i];
        size_t o = (size_t)which * (HIDn * HIDn / 4) + i;
        ((uint2*)g_wfh)[o] = make_uint2(packh1(v.x, v.y), packh1(v.z, v.w));
    }
}

// Tile: 128 rows x 64 elems x 2B (128B data + 16B pad = 144B row stride).
#define ROWB 144
#define T1   (128 * ROWB)     // 18432 B per tile

// ---------------------------------------------------------------------------
// K1: Q/K/V projection (fp16 2-term: (xfh + xfl) x wfh).  grid.z: 0=Q,1=K,2=V.
// ---------------------------------------------------------------------------
#define KV_SMEM (6 * T1)      // 110592 B

__global__ __launch_bounds__(256) void qkv_all(
    const float* __restrict__ bq, const float* __restrict__ bk, const float* __restrict__ bv)
{
    extern __shared__ char smem[];
    const uint32_t sb = smem_u32(smem);
    const int tid = threadIdx.x;
    const int lane = tid & 31;
    const int wid = tid >> 5;
    const int warp_m = wid & 1;
    const int warp_n = wid >> 1;
    const int which = blockIdx.z;
    const int m0 = blockIdx.x * 128;
    const int n0 = blockIdx.y * 128;
    const float* bias = (which == 0) ? bq : ((which == 1) ? bk : bv);
    const __half* wf = g_wfh + (size_t)which * HIDn * HIDn;

    float C[4][4][4];
#pragma unroll
    for (int a = 0; a < 4; a++)
#pragma unroll
        for (int n = 0; n < 4; n++)
#pragma unroll
            for (int j = 0; j < 4; j++) C[a][n][j] = 0.0f;

    auto load_chunk = [&](int chunk, int buf) {
        const int kc = chunk * 64;
        const uint32_t bufb = sb + buf * 3 * T1;
#pragma unroll
        for (int t = 0; t < 3; t++) {
            const __half* src = (t == 0) ? g_xfh : (t == 1) ? g_xfl : wf;
            const int rbase = (t < 2) ? m0 : n0;
#pragma unroll
            for (int i = 0; i < 4; i++) {
                const int idx = tid + 256 * i;
                const int row = idx >> 3, c = idx & 7;
                CP_ASYNC(bufb + t * T1 + row * ROWB + c * 16,
                         src + (size_t)(rbase + row) * HIDn + kc + c * 8);
            }
        }
        CP_COMMIT();
    };

    auto compute = [&](int buf) {
        const uint32_t base = sb + buf * 3 * T1;
#pragma unroll
        for (int ks = 0; ks < 4; ks++) {
            uint32_t ah[4][4], al[4][4];
#pragma unroll
            for (int a = 0; a < 4; a++) {
                const int row = warp_m * 64 + a * 16 + ((lane >> 3) & 1) * 8 + (lane & 7);
                const int colb = ks * 32 + (lane >> 4) * 16;
                ldsm4(ah[a], base + row * ROWB + colb);
                ldsm4(al[a], base + T1 + row * ROWB + colb);
            }
            uint32_t bh[2][4];
#pragma unroll
            for (int p = 0; p < 2; p++) {
                const int row = warp_n * 32 + p * 16 + ((lane >> 4) & 1) * 8 + (lane & 7);
                const int colb = ks * 32 + ((lane >> 3) & 1) * 16;
                ldsm4(bh[p], base + 2 * T1 + row * ROWB + colb);
            }
#pragma unroll
            for (int a = 0; a < 4; a++)
#pragma unroll
                for (int n = 0; n < 4; n++) {
                    const int p = n >> 1, q = (n & 1) * 2;
                    mma16816h(C[a][n], ah[a], bh[p][q], bh[p][q + 1]);
                    mma16816h(C[a][n], al[a], bh[p][q], bh[p][q + 1]);
                }
        }
    };

    load_chunk(0, 0);
    load_chunk(1, 1);
    for (int kt = 0; kt < 16; kt++) {
        if (kt == 15) { CP_WAIT0(); } else { CP_WAIT1(); }
        __syncthreads();
        compute(kt & 1);
        __syncthreads();
        if (kt + 2 < 16) load_chunk(kt + 2, kt & 1);
    }

    __half* out = (which == 0) ? g_qfh : ((which == 1) ? g_kfh : g_vf);
#pragma unroll
    for (int a = 0; a < 4; a++)
#pragma unroll
        for (int n = 0; n < 4; n++) {
            const int row0 = m0 + warp_m * 64 + a * 16 + (lane >> 2);
            const int col  = n0 + warp_n * 32 + n * 8 + (lane & 3) * 2;
            const float bb0 = bias[col], bb1 = bias[col + 1];
            const int hd = col >> 6, d = col & 63;
#pragma unroll
            for (int h = 0; h < 2; h++) {
                const int row = row0 + h * 8;
                const float v0 = C[a][n][h * 2 + 0] + bb0;
                const float v1 = C[a][n][h * 2 + 1] + bb1;
                const int bidx = row >> 11, s = row & (Sn - 1);
                const size_t oi = ((size_t)(bidx * NHn + hd) * Sn + s) * Dn + d;
                *(uint32_t*)&out[oi] = packh1(v0, v1);
            }
        }
}

// ---------------------------------------------------------------------------
// K2a: softmax stats only.  fp16 1-term: Qh x Kh.
// ---------------------------------------------------------------------------
#define K2_MASKOFF (3 * T1)                    // 55296
#define K2_REDM    (K2_MASKOFF + Sn * 4)       // 63488
#define K2_REDL    (K2_REDM + 4 * 128 * 4)     // 65536
#define K2_SMEM    (K2_REDL + 4 * 128 * 4)     // 67584

__global__ __launch_bounds__(256, 2) void stats_mma(const float* __restrict__ mask)
{
    extern __shared__ char smem[];
    const uint32_t sb = smem_u32(smem);
    float* maskS = (float*)(smem + K2_MASKOFF);
    float* redM  = (float*)(smem + K2_REDM);
    float* redL  = (float*)(smem + K2_REDL);
    const int tid = threadIdx.x;
    const int lane = tid & 31;
    const int wid = tid >> 5;
    const int warp_m = wid & 1;
    const int warp_n = wid >> 1;
    const int qt = blockIdx.x;
    const int bh = blockIdx.y;
    const int bidx = bh >> 4;
    const int grow = qt * 128;

    const size_t qgb = ((size_t)bh * Sn + grow) * Dn;
#pragma unroll
    for (int i = 0; i < 4; i++) {
        const int idx = tid + 256 * i;
        const int row = idx >> 3, c = idx & 7;
        CP_ASYNC(sb + row * ROWB + c * 16, g_qfh + qgb + row * Dn + c * 8);
    }
#pragma unroll
    for (int i = 0; i < 2; i++)
        ((float4*)maskS)[tid + 256 * i] = ((const float4*)(mask + (size_t)bidx * Sn))[tid + 256 * i];

    auto load_k = [&](int kt, int buf) {
        const size_t kgb = ((size_t)bh * Sn + kt * 128) * Dn;
        const uint32_t bufb = sb + T1 + buf * T1;
#pragma unroll
        for (int i = 0; i < 4; i++) {
            const int idx = tid + 256 * i;
            const int row = idx >> 3, c = idx & 7;
            CP_ASYNC(bufb + row * ROWB + c * 16, g_kfh + kgb + row * Dn + c * 8);
        }
        CP_COMMIT();
    };

    load_k(0, 0);
    load_k(1, 1);

    float sm_[8], sl_[8];
#pragma unroll
    for (int i = 0; i < 8; i++) { sm_[i] = -1e30f; sl_[i] = 0.0f; }

    for (int kt = 0; kt < 16; kt++) {
        if (kt == 15) { CP_WAIT0(); } else { CP_WAIT1(); }
        __syncthreads();

        const uint32_t kbase = sb + T1 + (kt & 1) * T1;
        float C[4][4][4];
#pragma unroll
        for (int a = 0; a < 4; a++)
#pragma unroll
            for (int n = 0; n < 4; n++)
#pragma unroll
                for (int j = 0; j < 4; j++) C[a][n][j] = 0.0f;

#pragma unroll
        for (int ks = 0; ks < 4; ks++) {
            uint32_t ah[4][4];
#pragma unroll
            for (int a = 0; a < 4; a++) {
                const int row = warp_m * 64 + a * 16 + ((lane >> 3) & 1) * 8 + (lane & 7);
                const int colb = ks * 32 + (lane >> 4) * 16;
                ldsm4(ah[a], sb + row * ROWB + colb);
            }
            uint32_t bhf[2][4];
#pragma unroll
            for (int p = 0; p < 2; p++) {
                const int row = warp_n * 32 + p * 16 + ((lane >> 4) & 1) * 8 + (lane & 7);
                const int colb = ks * 32 + ((lane >> 3) & 1) * 16;
                ldsm4(bhf[p], kbase + row * ROWB + colb);
            }
#pragma unroll
            for (int a = 0; a < 4; a++)
#pragma unroll
                for (int n = 0; n < 4; n++) {
                    const int p = n >> 1, q = (n & 1) * 2;
                    mma16816h(C[a][n], ah[a], bhf[p][q], bhf[p][q + 1]);
                }
        }

#pragma unroll
        for (int a = 0; a < 4; a++) {
            float s[4][4];
#pragma unroll
            for (int n = 0; n < 4; n++) {
                const int colt = warp_n * 32 + n * 8 + (lane & 3) * 2;
                const float mk0 = maskS[kt * 128 + colt];
                const float mk1 = maskS[kt * 128 + colt + 1];
                s[n][0] = C[a][n][0] * 0.125f + mk0;
                s[n][1] = C[a][n][1] * 0.125f + mk1;
                s[n][2] = C[a][n][2] * 0.125f + mk0;
                s[n][3] = C[a][n][3] * 0.125f + mk1;
            }
#pragma unroll
            for (int hh = 0; hh < 2; hh++) {
                float cm = s[0][hh * 2];
#pragma unroll
                for (int n = 0; n < 4; n++) {
                    cm = fmaxf(cm, s[n][hh * 2]);
                    cm = fmaxf(cm, s[n][hh * 2 + 1]);
                }
                const int si = a * 2 + hh;
                const float mn = fmaxf(sm_[si], cm);
                float ps = 0.0f;
#pragma unroll
                for (int n = 0; n < 4; n++)
                    ps += __expf(s[n][hh * 2] - mn) + __expf(s[n][hh * 2 + 1] - mn);
                sl_[si] = sl_[si] * __expf(sm_[si] - mn) + ps;
                sm_[si] = mn;
            }
        }

        __syncthreads();
        if (kt + 2 < 16) load_k(kt + 2, kt & 1);
    }

#pragma unroll
    for (int i = 0; i < 8; i++) {
        float m = sm_[i], l = sl_[i];
#pragma unroll
        for (int off = 1; off <= 2; off <<= 1) {
            const float om = __shfl_xor_sync(0xffffffffu, m, off);
            const float ol = __shfl_xor_sync(0xffffffffu, l, off);
            const float mn = fmaxf(m, om);
            l = l * __expf(m - mn) + ol * __expf(om - mn);
            m = mn;
        }
        if ((lane & 3) == 0) {
            const int row = warp_m * 64 + (i >> 1) * 16 + (i & 1) * 8 + (lane >> 2);
            redM[warp_n * 128 + row] = m;
            redL[warp_n * 128 + row] = l;
        }
    }
    __syncthreads();
    if (tid < 128) {
        float m = redM[tid], l = redL[tid];
#pragma unroll
        for (int w = 1; w < 4; w++) {
            const float om = redM[w * 128 + tid];
            const float ol = redL[w * 128 + tid];
            const float mn = fmaxf(m, om);
            l = l * __expf(m - mn) + ol * __expf(om - mn);
            m = mn;
        }
        g_m[(size_t)bh * Sn + grow + tid] = m;
        g_l[(size_t)bh * Sn + grow + tid] = l;
    }
}

// ---------------------------------------------------------------------------
// K2b: fused.  QK^T fp16 1-term, processed in two key-halves of 64 cols each
// (C[8][4] instead of C[16][4] -> ~100 regs -> 2 CTAs/SM).  Arithmetic is
// bit-identical to R13 (per-n-block ks-order unchanged).
// smem: Qh | Kh0 | Kh1 | V0 | V1 | mask | m | invl = 101376 B
// ---------------------------------------------------------------------------
#define F_KOFF  (1 * T1)
#define F_VOFF  (3 * T1)
#define F_MASK  (5 * T1)                  // 92160
#define F_MROW  (F_MASK + Sn * 4)         // 100352
#define F_LROW  (F_MROW + 512)            // 100864
#define F_SMEM  (F_LROW + 512)            // 101376

__global__ __launch_bounds__(256, 2) void fused_pv(
    const float* __restrict__ mask, float* __restrict__ probs, float* __restrict__ ctx)
{
    extern __shared__ char smem[];
    const uint32_t sb = smem_u32(smem);
    float* maskS = (float*)(smem + F_MASK);
    float* mrow  = (float*)(smem + F_MROW);
    float* lrow  = (float*)(smem + F_LROW);
    const int tid = threadIdx.x;
    const int lane = tid & 31;
    const int wid = tid >> 5;
    const int qt = blockIdx.x;
    const int bh = blockIdx.y;
    const int bidx = bh >> 4;
    const int h    = bh & 15;
    const int q0 = qt * 128;

    const size_t qgb = ((size_t)bh * Sn + q0) * Dn;
#pragma unroll
    for (int i = 0; i < 4; i++) {
        const int idx = tid + 256 * i;
        const int row = idx >> 3, c = idx & 7;
        CP_ASYNC(sb + row * ROWB + c * 16, g_qfh + qgb + row * Dn + c * 8);
    }

    auto load_kv = [&](int kt, int buf) {
        const size_t gb = ((size_t)bh * Sn + kt * 128) * Dn;
        const uint32_t kb = sb + F_KOFF + buf * T1;
        const uint32_t vb = sb + F_VOFF + buf * T1;
#pragma unroll
        for (int i = 0; i < 4; i++) {
            const int idx = tid + 256 * i;
            const int row = idx >> 3, c = idx & 7;
            const size_t g = gb + (size_t)row * Dn + c * 8;
            CP_ASYNC(kb + row * ROWB + c * 16, g_kfh + g);
            CP_ASYNC(vb + row * ROWB + c * 16, g_vf + g);
        }
        CP_COMMIT();
    };

    load_kv(0, 0);
    load_kv(1, 1);

#pragma unroll
    for (int i = 0; i < 2; i++)
        ((float4*)maskS)[tid + 256 * i] = ((const float4*)(mask + (size_t)bidx * Sn))[tid + 256 * i];
    if (tid < 128) {
        const size_t ro = (size_t)bh * Sn + q0 + tid;
        mrow[tid] = g_m[ro];
        lrow[tid] = 1.0f / g_l[ro];
    }

    float O[8][4];
#pragma unroll
    for (int n = 0; n < 8; n++)
#pragma unroll
        for (int j = 0; j < 4; j++) O[n][j] = 0.0f;

    const int rloc0 = wid * 16 + (lane >> 2);
    float mm0, ll0, mm1, ll1;

    for (int kt = 0; kt < 16; kt++) {
        if (kt == 15) { CP_WAIT0(); } else { CP_WAIT1(); }
        __syncthreads();
        if (kt == 0) { mm0 = mrow[rloc0]; ll0 = lrow[rloc0];
                       mm1 = mrow[rloc0 + 8]; ll1 = lrow[rloc0 + 8]; }

        const uint32_t kbase = sb + F_KOFF + (kt & 1) * T1;
        const uint32_t vbase = sb + F_VOFF + (kt & 1) * T1;
        const size_t prow0 = ((size_t)bh * Sn + q0 + rloc0) * Sn + kt * 128;
        const size_t prow1 = prow0 + (size_t)8 * Sn;

#pragma unroll
        for (int half = 0; half < 2; half++) {
            // ---- QK^T for keys [half*64, half*64+64)
            float C[8][4];
#pragma unroll
            for (int n = 0; n < 8; n++)
#pragma unroll
                for (int j = 0; j < 4; j++) C[n][j] = 0.0f;

#pragma unroll
            for (int ks = 0; ks < 4; ks++) {
                uint32_t qh4[4];
                {
                    const int row = wid * 16 + ((lane >> 3) & 1) * 8 + (lane & 7);
                    const int colb = ks * 32 + (lane >> 4) * 16;
                    ldsm4(qh4, sb + row * ROWB + colb);
                }
#pragma unroll
                for (int g = 0; g < 4; g++) {
                    uint32_t kh4[4];
                    const int row = (half * 4 + g) * 16 + ((lane >> 4) & 1) * 8 + (lane & 7);
                    const int colb = ks * 32 + ((lane >> 3) & 1) * 16;
                    ldsm4(kh4, kbase + row * ROWB + colb);
                    mma16816h(C[2*g],   qh4, kh4[0], kh4[1]);
                    mma16816h(C[2*g+1], qh4, kh4[2], kh4[3]);
                }
            }

            // ---- normalize + write probs cols [half*64, half*64+64)
#pragma unroll
            for (int n = 0; n < 8; n++) {
                const int colt = half * 64 + n * 8 + (lane & 3) * 2;
                const float mk0 = maskS[kt * 128 + colt];
                const float mk1 = maskS[kt * 128 + colt + 1];
                const float p00 = __expf(C[n][0] * 0.125f + mk0 - mm0) * ll0;
                const float p01 = __expf(C[n][1] * 0.125f + mk1 - mm0) * ll0;
                const float p10 = __expf(C[n][2] * 0.125f + mk0 - mm1) * ll1;
                const float p11 = __expf(C[n][3] * 0.125f + mk1 - mm1) * ll1;
                C[n][0] = p00; C[n][1] = p01; C[n][2] = p10; C[n][3] = p11;
                *(float2*)&probs[prow0 + colt] = make_float2(p00, p01);
                *(float2*)&probs[prow1 + colt] = make_float2(p10, p11);
            }

            // ---- P@V over this half's 4 key-groups
#pragma unroll
            for (int kg = 0; kg < 4; kg++) {
                uint32_t aph[4];
                aph[0] = packh1(C[2*kg][0],   C[2*kg][1]);
                aph[1] = packh1(C[2*kg][2],   C[2*kg][3]);
                aph[2] = packh1(C[2*kg+1][0], C[2*kg+1][1]);
                aph[3] = packh1(C[2*kg+1][2], C[2*kg+1][3]);
                const uint32_t brow = (half * 4 + kg) * 16 + (lane & 7) + ((lane >> 3) & 1) * 8;
#pragma unroll
                for (int nb = 0; nb < 4; nb++) {
                    uint32_t vh4[4];
                    ldsm4_t(vh4, vbase + brow * ROWB + nb * 32 + (lane >> 4) * 16);
                    mma16816h(O[nb*2],   aph, vh4[0], vh4[1]);
                    mma16816h(O[nb*2+1], aph, vh4[2], vh4[3]);
                }
            }
        }

        __syncthreads();
        if (kt + 2 < 16) load_kv(kt + 2, kt & 1);
    }

#pragma unroll
    for (int nb = 0; nb < 8; nb++) {
        const int col = nb * 8 + (lane & 3) * 2;
        const int row = q0 + wid * 16 + (lane >> 2);
        *(float2*)&ctx[((size_t)(bidx * Sn + row)) * HIDn + h * 64 + col] =
            make_float2(O[nb][0], O[nb][1]);
        *(float2*)&ctx[((size_t)(bidx * Sn + row + 8)) * HIDn + h * 64 + col] =
            make_float2(O[nb][2], O[nb][3]);
    }
}

// ---------------------------------------------------------------------------
extern "C" void kernel_launch(void* const* d_in, const int* in_sizes, int n_in,
                              void* d_out, int out_size)
{
    const float* x    = (const float*)d_in[0];
    const float* mask = (const float*)d_in[1];
    const float* Wq   = (const float*)d_in[2];
    const float* bq   = (const float*)d_in[3];
    const float* Wk   = (const float*)d_in[4];
    const float* bk   = (const float*)d_in[5];
    const float* Wv   = (const float*)d_in[6];
    const float* bv   = (const float*)d_in[7];

    float* ctx = (float*)d_out;
    const size_t PROBS_ELEMS = (size_t)BHn * Sn * Sn;
    size_t probs_off = 0;
    if ((size_t)out_size > PROBS_ELEMS) probs_off = (size_t)out_size - PROBS_ELEMS;
    float* probs = (float*)d_out + probs_off;

    cudaFuncSetAttribute(qkv_all,   cudaFuncAttributeMaxDynamicSharedMemorySize, KV_SMEM);
    cudaFuncSetAttribute(stats_mma, cudaFuncAttributeMaxDynamicSharedMemorySize, K2_SMEM);
    cudaFuncSetAttribute(fused_pv,  cudaFuncAttributeMaxDynamicSharedMemorySize, F_SMEM);

    split_all_kernel<<<XB + 3 * WB, 256>>>(
        (const float4*)x, (const float4*)Wq, (const float4*)Wk, (const float4*)Wv);
    qkv_all<<<dim3(Mn/128, HIDn/128, 3), 256, KV_SMEM>>>(bq, bk, bv);
    stats_mma<<<dim3(Sn/128, BHn), 256, K2_SMEM>>>(mask);
    fused_pv<<<dim3(Sn/128, BHn), 256, F_SMEM>>>(mask, probs, ctx);
}

// round 15
// speedup vs baseline: 3.2171x; 1.2480x over previous
#include <cuda_runtime.h>
#include <cuda_fp16.h>
#include <math.h>
#include <stdint.h>

#define Bn   4
#define Sn   2048
#define HIDn 1024
#define NHn  16
#define Dn   64
#define BHn  64
#define Mn   8192

// ---------------- scratch (static device globals; no runtime alloc) --------
__device__ __half g_xfh[(size_t)Mn * HIDn];          // x fp16 hi
__device__ __half g_wfh[(size_t)3 * HIDn * HIDn];    // Wq,Wk,Wv fp16 hi
__device__ __half g_qfh[(size_t)BHn * Sn * Dn];
__device__ __half g_kfh[(size_t)BHn * Sn * Dn];
__device__ __half g_vf [(size_t)BHn * Sn * Dn];
__device__ float g_m[(size_t)BHn * Sn];
__device__ float g_l[(size_t)BHn * Sn];

// ---------------- PTX helpers (baseline-feature PTX only) -------------------
__device__ __forceinline__ uint32_t smem_u32(const void* p) {
    uint32_t a;
    asm("{ .reg .u64 t; cvta.to.shared.u64 t, %1; cvt.u32.u64 %0, t; }" : "=r"(a) : "l"(p));
    return a;
}
#define CP_ASYNC(dst, src) \
    asm volatile("cp.async.cg.shared.global [%0], [%1], 16;" :: "r"(dst), "l"(src))
#define CP_COMMIT() asm volatile("cp.async.commit_group;")
#define CP_WAIT0()  asm volatile("cp.async.wait_group 0;")
#define CP_WAIT1()  asm volatile("cp.async.wait_group 1;")

__device__ __forceinline__ void ldsm4(uint32_t r[4], uint32_t addr) {
    asm volatile("ldmatrix.sync.aligned.m8n8.x4.shared.b16 {%0,%1,%2,%3}, [%4];"
        : "=r"(r[0]), "=r"(r[1]), "=r"(r[2]), "=r"(r[3]) : "r"(addr));
}
__device__ __forceinline__ void ldsm4_t(uint32_t r[4], uint32_t addr) {
    asm volatile("ldmatrix.sync.aligned.m8n8.x4.trans.shared.b16 {%0,%1,%2,%3}, [%4];"
        : "=r"(r[0]), "=r"(r[1]), "=r"(r[2]), "=r"(r[3]) : "r"(addr));
}
__device__ __forceinline__ void mma16816h(float c[4], const uint32_t a[4],
                                          uint32_t b0, uint32_t b1) {
    asm volatile("mma.sync.aligned.m16n8k16.row.col.f32.f16.f16.f32 "
        "{%0,%1,%2,%3}, {%4,%5,%6,%7}, {%8,%9}, {%0,%1,%2,%3};"
        : "+f"(c[0]), "+f"(c[1]), "+f"(c[2]), "+f"(c[3])
        : "r"(a[0]), "r"(a[1]), "r"(a[2]), "r"(a[3]), "r"(b0), "r"(b1));
}

__device__ __forceinline__ uint32_t packh1(float v0, float v1) {
    return ((uint32_t)__half_as_ushort(__float2half_rn(v1)) << 16) |
           (uint32_t)__half_as_ushort(__float2half_rn(v0));
}

// Merged split kernel: blocks [0, XB) quantize x; blocks [XB, XB+3*WB) W.
#define XB (Mn * HIDn / 4 / 256)          // 8192
#define WB (HIDn * HIDn / 4 / 256)        // 1024

__global__ __launch_bounds__(256) void split_all_kernel(
    const float4* __restrict__ x, const float4* __restrict__ Wq,
    const float4* __restrict__ Wk, const float4* __restrict__ Wv)
{
    const int b = blockIdx.x;
    if (b < XB) {
        size_t i = (size_t)b * 256 + threadIdx.x;
        float4 v = x[i];
        ((uint2*)g_xfh)[i] = make_uint2(packh1(v.x, v.y), packh1(v.z, v.w));
    } else {
        const int wb = b - XB;
        const int which = wb / WB;
        size_t i = (size_t)(wb - which * WB) * 256 + threadIdx.x;
        const float4* W = (which == 0) ? Wq : ((which == 1) ? Wk : Wv);
        float4 v = W[i];
        size_t o = (size_t)which * (HIDn * HIDn / 4) + i;
        ((uint2*)g_wfh)[o] = make_uint2(packh1(v.x, v.y), packh1(v.z, v.w));
    }
}

// Tile: 128 rows x 64 elems x 2B (128B data + 16B pad = 144B row stride).
#define ROWB 144
#define T1   (128 * ROWB)     // 18432 B per tile

// ---------------------------------------------------------------------------
// K1: Q/K/V projection (fp16 1-term: xfh x wfh).  grid.z: 0=Q,1=K,2=V.
// smem: 2 buffers x 2 tiles = 73728 B -> 2+ CTAs/SM.
// ---------------------------------------------------------------------------
#define KV_SMEM (4 * T1)      // 73728 B

__global__ __launch_bounds__(256, 2) void qkv_all(
    const float* __restrict__ bq, const float* __restrict__ bk, const float* __restrict__ bv)
{
    extern __shared__ char smem[];
    const uint32_t sb = smem_u32(smem);
    const int tid = threadIdx.x;
    const int lane = tid & 31;
    const int wid = tid >> 5;
    const int warp_m = wid & 1;
    const int warp_n = wid >> 1;
    const int which = blockIdx.z;
    const int m0 = blockIdx.x * 128;
    const int n0 = blockIdx.y * 128;
    const float* bias = (which == 0) ? bq : ((which == 1) ? bk : bv);
    const __half* wf = g_wfh + (size_t)which * HIDn * HIDn;

    float C[4][4][4];
#pragma unroll
    for (int a = 0; a < 4; a++)
#pragma unroll
        for (int n = 0; n < 4; n++)
#pragma unroll
            for (int j = 0; j < 4; j++) C[a][n][j] = 0.0f;

    auto load_chunk = [&](int chunk, int buf) {
        const int kc = chunk * 64;
        const uint32_t bufb = sb + buf * 2 * T1;
#pragma unroll
        for (int t = 0; t < 2; t++) {
            const __half* src = (t == 0) ? g_xfh : wf;
            const int rbase = (t == 0) ? m0 : n0;
#pragma unroll
            for (int i = 0; i < 4; i++) {
                const int idx = tid + 256 * i;
                const int row = idx >> 3, c = idx & 7;
                CP_ASYNC(bufb + t * T1 + row * ROWB + c * 16,
                         src + (size_t)(rbase + row) * HIDn + kc + c * 8);
            }
        }
        CP_COMMIT();
    };

    auto compute = [&](int buf) {
        const uint32_t base = sb + buf * 2 * T1;
#pragma unroll
        for (int ks = 0; ks < 4; ks++) {
            uint32_t ah[4][4];
#pragma unroll
            for (int a = 0; a < 4; a++) {
                const int row = warp_m * 64 + a * 16 + ((lane >> 3) & 1) * 8 + (lane & 7);
                const int colb = ks * 32 + (lane >> 4) * 16;
                ldsm4(ah[a], base + row * ROWB + colb);
            }
            uint32_t bh[2][4];
#pragma unroll
            for (int p = 0; p < 2; p++) {
                const int row = warp_n * 32 + p * 16 + ((lane >> 4) & 1) * 8 + (lane & 7);
                const int colb = ks * 32 + ((lane >> 3) & 1) * 16;
                ldsm4(bh[p], base + T1 + row * ROWB + colb);
            }
#pragma unroll
            for (int a = 0; a < 4; a++)
#pragma unroll
                for (int n = 0; n < 4; n++) {
                    const int p = n >> 1, q = (n & 1) * 2;
                    mma16816h(C[a][n], ah[a], bh[p][q], bh[p][q + 1]);
                }
        }
    };

    load_chunk(0, 0);
    load_chunk(1, 1);
    for (int kt = 0; kt < 16; kt++) {
        if (kt == 15) { CP_WAIT0(); } else { CP_WAIT1(); }
        __syncthreads();
        compute(kt & 1);
        __syncthreads();
        if (kt + 2 < 16) load_chunk(kt + 2, kt & 1);
    }

    __half* out = (which == 0) ? g_qfh : ((which == 1) ? g_kfh : g_vf);
#pragma unroll
    for (int a = 0; a < 4; a++)
#pragma unroll
        for (int n = 0; n < 4; n++) {
            const int row0 = m0 + warp_m * 64 + a * 16 + (lane >> 2);
            const int col  = n0 + warp_n * 32 + n * 8 + (lane & 3) * 2;
            const float bb0 = bias[col], bb1 = bias[col + 1];
            const int hd = col >> 6, d = col & 63;
#pragma unroll
            for (int h = 0; h < 2; h++) {
                const int row = row0 + h * 8;
                const float v0 = C[a][n][h * 2 + 0] + bb0;
                const float v1 = C[a][n][h * 2 + 1] + bb1;
                const int bidx = row >> 11, s = row & (Sn - 1);
                const size_t oi = ((size_t)(bidx * NHn + hd) * Sn + s) * Dn + d;
                *(uint32_t*)&out[oi] = packh1(v0, v1);
            }
        }
}

// ---------------------------------------------------------------------------
// K2a: softmax stats only.  fp16 1-term: Qh x Kh.
// ---------------------------------------------------------------------------
#define K2_MASKOFF (3 * T1)                    // 55296
#define K2_REDM    (K2_MASKOFF + Sn * 4)       // 63488
#define K2_REDL    (K2_REDM + 4 * 128 * 4)     // 65536
#define K2_SMEM    (K2_REDL + 4 * 128 * 4)     // 67584

__global__ __launch_bounds__(256, 2) void stats_mma(const float* __restrict__ mask)
{
    extern __shared__ char smem[];
    const uint32_t sb = smem_u32(smem);
    float* maskS = (float*)(smem + K2_MASKOFF);
    float* redM  = (float*)(smem + K2_REDM);
    float* redL  = (float*)(smem + K2_REDL);
    const int tid = threadIdx.x;
    const int lane = tid & 31;
    const int wid = tid >> 5;
    const int warp_m = wid & 1;
    const int warp_n = wid >> 1;
    const int qt = blockIdx.x;
    const int bh = blockIdx.y;
    const int bidx = bh >> 4;
    const int grow = qt * 128;

    const size_t qgb = ((size_t)bh * Sn + grow) * Dn;
#pragma unroll
    for (int i = 0; i < 4; i++) {
        const int idx = tid + 256 * i;
        const int row = idx >> 3, c = idx & 7;
        CP_ASYNC(sb + row * ROWB + c * 16, g_qfh + qgb + row * Dn + c * 8);
    }
#pragma unroll
    for (int i = 0; i < 2; i++)
        ((float4*)maskS)[tid + 256 * i] = ((const float4*)(mask + (size_t)bidx * Sn))[tid + 256 * i];

    auto load_k = [&](int kt, int buf) {
        const size_t kgb = ((size_t)bh * Sn + kt * 128) * Dn;
        const uint32_t bufb = sb + T1 + buf * T1;
#pragma unroll
        for (int i = 0; i < 4; i++) {
            const int idx = tid + 256 * i;
            const int row = idx >> 3, c = idx & 7;
            CP_ASYNC(bufb + row * ROWB + c * 16, g_kfh + kgb + row * Dn + c * 8);
        }
        CP_COMMIT();
    };

    load_k(0, 0);
    load_k(1, 1);

    float sm_[8], sl_[8];
#pragma unroll
    for (int i = 0; i < 8; i++) { sm_[i] = -1e30f; sl_[i] = 0.0f; }

    for (int kt = 0; kt < 16; kt++) {
        if (kt == 15) { CP_WAIT0(); } else { CP_WAIT1(); }
        __syncthreads();

        const uint32_t kbase = sb + T1 + (kt & 1) * T1;
        float C[4][4][4];
#pragma unroll
        for (int a = 0; a < 4; a++)
#pragma unroll
            for (int n = 0; n < 4; n++)
#pragma unroll
                for (int j = 0; j < 4; j++) C[a][n][j] = 0.0f;

#pragma unroll
        for (int ks = 0; ks < 4; ks++) {
            uint32_t ah[4][4];
#pragma unroll
            for (int a = 0; a < 4; a++) {
                const int row = warp_m * 64 + a * 16 + ((lane >> 3) & 1) * 8 + (lane & 7);
                const int colb = ks * 32 + (lane >> 4) * 16;
                ldsm4(ah[a], sb + row * ROWB + colb);
            }
            uint32_t bhf[2][4];
#pragma unroll
            for (int p = 0; p < 2; p++) {
                const int row = warp_n * 32 + p * 16 + ((lane >> 4) & 1) * 8 + (lane & 7);
                const int colb = ks * 32 + ((lane >> 3) & 1) * 16;
                ldsm4(bhf[p], kbase + row * ROWB + colb);
            }
#pragma unroll
            for (int a = 0; a < 4; a++)
#pragma unroll
                for (int n = 0; n < 4; n++) {
                    const int p = n >> 1, q = (n & 1) * 2;
                    mma16816h(C[a][n], ah[a], bhf[p][q], bhf[p][q + 1]);
                }
        }

#pragma unroll
        for (int a = 0; a < 4; a++) {
            float s[4][4];
#pragma unroll
            for (int n = 0; n < 4; n++) {
                const int colt = warp_n * 32 + n * 8 + (lane & 3) * 2;
                const float mk0 = maskS[kt * 128 + colt];
                const float mk1 = maskS[kt * 128 + colt + 1];
                s[n][0] = C[a][n][0] * 0.125f + mk0;
                s[n][1] = C[a][n][1] * 0.125f + mk1;
                s[n][2] = C[a][n][2] * 0.125f + mk0;
                s[n][3] = C[a][n][3] * 0.125f + mk1;
            }
#pragma unroll
            for (int hh = 0; hh < 2; hh++) {
                float cm = s[0][hh * 2];
#pragma unroll
                for (int n = 0; n < 4; n++) {
                    cm = fmaxf(cm, s[n][hh * 2]);
                    cm = fmaxf(cm, s[n][hh * 2 + 1]);
                }
                const int si = a * 2 + hh;
                const float mn = fmaxf(sm_[si], cm);
                float ps = 0.0f;
#pragma unroll
                for (int n = 0; n < 4; n++)
                    ps += __expf(s[n][hh * 2] - mn) + __expf(s[n][hh * 2 + 1] - mn);
                sl_[si] = sl_[si] * __expf(sm_[si] - mn) + ps;
                sm_[si] = mn;
            }
        }

        __syncthreads();
        if (kt + 2 < 16) load_k(kt + 2, kt & 1);
    }

#pragma unroll
    for (int i = 0; i < 8; i++) {
        float m = sm_[i], l = sl_[i];
#pragma unroll
        for (int off = 1; off <= 2; off <<= 1) {
            const float om = __shfl_xor_sync(0xffffffffu, m, off);
            const float ol = __shfl_xor_sync(0xffffffffu, l, off);
            const float mn = fmaxf(m, om);
            l = l * __expf(m - mn) + ol * __expf(om - mn);
            m = mn;
        }
        if ((lane & 3) == 0) {
            const int row = warp_m * 64 + (i >> 1) * 16 + (i & 1) * 8 + (lane >> 2);
            redM[warp_n * 128 + row] = m;
            redL[warp_n * 128 + row] = l;
        }
    }
    __syncthreads();
    if (tid < 128) {
        float m = redM[tid], l = redL[tid];
#pragma unroll
        for (int w = 1; w < 4; w++) {
            const float om = redM[w * 128 + tid];
            const float ol = redL[w * 128 + tid];
            const float mn = fmaxf(m, om);
            l = l * __expf(m - mn) + ol * __expf(om - mn);
            m = mn;
        }
        g_m[(size_t)bh * Sn + grow + tid] = m;
        g_l[(size_t)bh * Sn + grow + tid] = l;
    }
}

// ---------------------------------------------------------------------------
// K2b: fused.  QK^T fp16 1-term in two key-halves (2 CTAs/SM);
// p = exp(s-m)*invl; write final probs; P@V fp16 1-term.
// ---------------------------------------------------------------------------
#define F_KOFF  (1 * T1)
#define F_VOFF  (3 * T1)
#define F_MASK  (5 * T1)                  // 92160
#define F_MROW  (F_MASK + Sn * 4)         // 100352
#define F_LROW  (F_MROW + 512)            // 100864
#define F_SMEM  (F_LROW + 512)            // 101376

__global__ __launch_bounds__(256, 2) void fused_pv(
    const float* __restrict__ mask, float* __restrict__ probs, float* __restrict__ ctx)
{
    extern __shared__ char smem[];
    const uint32_t sb = smem_u32(smem);
    float* maskS = (float*)(smem + F_MASK);
    float* mrow  = (float*)(smem + F_MROW);
    float* lrow  = (float*)(smem + F_LROW);
    const int tid = threadIdx.x;
    const int lane = tid & 31;
    const int wid = tid >> 5;
    const int qt = blockIdx.x;
    const int bh = blockIdx.y;
    const int bidx = bh >> 4;
    const int h    = bh & 15;
    const int q0 = qt * 128;

    const size_t qgb = ((size_t)bh * Sn + q0) * Dn;
#pragma unroll
    for (int i = 0; i < 4; i++) {
        const int idx = tid + 256 * i;
        const int row = idx >> 3, c = idx & 7;
        CP_ASYNC(sb + row * ROWB + c * 16, g_qfh + qgb + row * Dn + c * 8);
    }

    auto load_kv = [&](int kt, int buf) {
        const size_t gb = ((size_t)bh * Sn + kt * 128) * Dn;
        const uint32_t kb = sb + F_KOFF + buf * T1;
        const uint32_t vb = sb + F_VOFF + buf * T1;
#pragma unroll
        for (int i = 0; i < 4; i++) {
            const int idx = tid + 256 * i;
            const int row = idx >> 3, c = idx & 7;
            const size_t g = gb + (size_t)row * Dn + c * 8;
            CP_ASYNC(kb + row * ROWB + c * 16, g_kfh + g);
            CP_ASYNC(vb + row * ROWB + c * 16, g_vf + g);
        }
        CP_COMMIT();
    };

    load_kv(0, 0);
    load_kv(1, 1);

#pragma unroll
    for (int i = 0; i < 2; i++)
        ((float4*)maskS)[tid + 256 * i] = ((const float4*)(mask + (size_t)bidx * Sn))[tid + 256 * i];
    if (tid < 128) {
        const size_t ro = (size_t)bh * Sn + q0 + tid;
        mrow[tid] = g_m[ro];
        lrow[tid] = 1.0f / g_l[ro];
    }

    float O[8][4];
#pragma unroll
    for (int n = 0; n < 8; n++)
#pragma unroll
        for (int j = 0; j < 4; j++) O[n][j] = 0.0f;

    const int rloc0 = wid * 16 + (lane >> 2);
    float mm0, ll0, mm1, ll1;

    for (int kt = 0; kt < 16; kt++) {
        if (kt == 15) { CP_WAIT0(); } else { CP_WAIT1(); }
        __syncthreads();
        if (kt == 0) { mm0 = mrow[rloc0]; ll0 = lrow[rloc0];
                       mm1 = mrow[rloc0 + 8]; ll1 = lrow[rloc0 + 8]; }

        const uint32_t kbase = sb + F_KOFF + (kt & 1) * T1;
        const uint32_t vbase = sb + F_VOFF + (kt & 1) * T1;
        const size_t prow0 = ((size_t)bh * Sn + q0 + rloc0) * Sn + kt * 128;
        const size_t prow1 = prow0 + (size_t)8 * Sn;

#pragma unroll
        for (int half = 0; half < 2; half++) {
            float C[8][4];
#pragma unroll
            for (int n = 0; n < 8; n++)
#pragma unroll
                for (int j = 0; j < 4; j++) C[n][j] = 0.0f;

#pragma unroll
            for (int ks = 0; ks < 4; ks++) {
                uint32_t qh4[4];
                {
                    const int row = wid * 16 + ((lane >> 3) & 1) * 8 + (lane & 7);
                    const int colb = ks * 32 + (lane >> 4) * 16;
                    ldsm4(qh4, sb + row * ROWB + colb);
                }
#pragma unroll
                for (int g = 0; g < 4; g++) {
                    uint32_t kh4[4];
                    const int row = (half * 4 + g) * 16 + ((lane >> 4) & 1) * 8 + (lane & 7);
                    const int colb = ks * 32 + ((lane >> 3) & 1) * 16;
                    ldsm4(kh4, kbase + row * ROWB + colb);
                    mma16816h(C[2*g],   qh4, kh4[0], kh4[1]);
                    mma16816h(C[2*g+1], qh4, kh4[2], kh4[3]);
                }
            }

#pragma unroll
            for (int n = 0; n < 8; n++) {
                const int colt = half * 64 + n * 8 + (lane & 3) * 2;
                const float mk0 = maskS[kt * 128 + colt];
                const float mk1 = maskS[kt * 128 + colt + 1];
                const float p00 = __expf(C[n][0] * 0.125f + mk0 - mm0) * ll0;
                const float p01 = __expf(C[n][1] * 0.125f + mk1 - mm0) * ll0;
                const float p10 = __expf(C[n][2] * 0.125f + mk0 - mm1) * ll1;
                const float p11 = __expf(C[n][3] * 0.125f + mk1 - mm1) * ll1;
                C[n][0] = p00; C[n][1] = p01; C[n][2] = p10; C[n][3] = p11;
                *(float2*)&probs[prow0 + colt] = make_float2(p00, p01);
                *(float2*)&probs[prow1 + colt] = make_float2(p10, p11);
            }

#pragma unroll
            for (int kg = 0; kg < 4; kg++) {
                uint32_t aph[4];
                aph[0] = packh1(C[2*kg][0],   C[2*kg][1]);
                aph[1] = packh1(C[2*kg][2],   C[2*kg][3]);
                aph[2] = packh1(C[2*kg+1][0], C[2*kg+1][1]);
                aph[3] = packh1(C[2*kg+1][2], C[2*kg+1][3]);
                const uint32_t brow = (half * 4 + kg) * 16 + (lane & 7) + ((lane >> 3) & 1) * 8;
#pragma unroll
                for (int nb = 0; nb < 4; nb++) {
                    uint32_t vh4[4];
                    ldsm4_t(vh4, vbase + brow * ROWB + nb * 32 + (lane >> 4) * 16);
                    mma16816h(O[nb*2],   aph, vh4[0], vh4[1]);
                    mma16816h(O[nb*2+1], aph, vh4[2], vh4[3]);
                }
            }
        }

        __syncthreads();
        if (kt + 2 < 16) load_kv(kt + 2, kt & 1);
    }

#pragma unroll
    for (int nb = 0; nb < 8; nb++) {
        const int col = nb * 8 + (lane & 3) * 2;
        const int row = q0 + wid * 16 + (lane >> 2);
        *(float2*)&ctx[((size_t)(bidx * Sn + row)) * HIDn + h * 64 + col] =
            make_float2(O[nb][0], O[nb][1]);
        *(float2*)&ctx[((size_t)(bidx * Sn + row + 8)) * HIDn + h * 64 + col] =
            make_float2(O[nb][2], O[nb][3]);
    }
}

// ---------------------------------------------------------------------------
extern "C" void kernel_launch(void* const* d_in, const int* in_sizes, int n_in,
                              void* d_out, int out_size)
{
    const float* x    = (const float*)d_in[0];
    const float* mask = (const float*)d_in[1];
    const float* Wq   = (const float*)d_in[2];
    const float* bq   = (const float*)d_in[3];
    const float* Wk   = (const float*)d_in[4];
    const float* bk   = (const float*)d_in[5];
    const float* Wv   = (const float*)d_in[6];
    const float* bv   = (const float*)d_in[7];

    float* ctx = (float*)d_out;
    const size_t PROBS_ELEMS = (size_t)BHn * Sn * Sn;
    size_t probs_off = 0;
    if ((size_t)out_size > PROBS_ELEMS) probs_off = (size_t)out_size - PROBS_ELEMS;
    float* probs = (float*)d_out + probs_off;

    cudaFuncSetAttribute(qkv_all,   cudaFuncAttributeMaxDynamicSharedMemorySize, KV_SMEM);
    cudaFuncSetAttribute(stats_mma, cudaFuncAttributeMaxDynamicSharedMemorySize, K2_SMEM);
    cudaFuncSetAttribute(fused_pv,  cudaFuncAttributeMaxDynamicSharedMemorySize, F_SMEM);

    split_all_kernel<<<XB + 3 * WB, 256>>>(
        (const float4*)x, (const float4*)Wq, (const float4*)Wk, (const float4*)Wv);
    qkv_all<<<dim3(Mn/128, HIDn/128, 3), 256, KV_SMEM>>>(bq, bk, bv);
    stats_mma<<<dim3(Sn/128, BHn), 256, K2_SMEM>>>(mask);
    fused_pv<<<dim3(Sn/128, BHn), 256, F_SMEM>>>(mask, probs, ctx);
}